// round 9
// baseline (speedup 1.0000x reference)
#include <cuda_runtime.h>
#include <cuda_fp16.h>
#include <cstdint>

#define BATCH 8
#define TT    4096
#define DIM   512
#define NH    8
#define HD    64
#define QDIM  512
#define GG    3584
#define NCHUNK 56

// ---- global scratch (u32 = half2 of adjacent elements of ONE plane) ----
__device__ __align__(256) uint32_t g_Q  [(size_t)NH*BATCH*QDIM*HD];        // packed (hi|lo) per element
__device__ __align__(256) uint32_t g_Kh [(size_t)NH*BATCH*GG*(HD/2)];      // [pair][g][dpair]
__device__ __align__(256) uint32_t g_Kl [(size_t)NH*BATCH*GG*(HD/2)];
__device__ __align__(256) uint32_t g_V2h[(size_t)NH*BATCH*(GG/2)*HD];      // [pair][gpair][d]
__device__ __align__(256) uint32_t g_V2l[(size_t)NH*BATCH*(GG/2)*HD];
__device__ __align__(256) uint32_t g_Hdh[(size_t)BATCH*QDIM*(DIM/2)];      // [b][q][epair]
__device__ __align__(256) uint32_t g_Hdl[(size_t)BATCH*QDIM*(DIM/2)];
__device__ __align__(256) uint32_t g_Xh [(size_t)BATCH*TT*(DIM/2)];        // [b][t][kpair]
__device__ __align__(256) uint32_t g_Xl [(size_t)BATCH*TT*(DIM/2)];
__device__ __align__(256) uint32_t g_Wth[(size_t)3*NH*HD*(DIM/2)];         // [w][h][n][kpair]
__device__ __align__(256) uint32_t g_Wtl[(size_t)3*NH*HD*(DIM/2)];
__device__ __align__(256) uint32_t g_Woth[(size_t)DIM*(DIM/2)];            // [n][kpair]
__device__ __align__(256) uint32_t g_Wotl[(size_t)DIM*(DIM/2)];

__device__ __forceinline__ uint32_t packsplit(float v) {
    __half h = __float2half_rn(v);
    __half l = __float2half_rn(v - __half2float(h));
    return (uint32_t)__half_as_ushort(h) | ((uint32_t)__half_as_ushort(l) << 16);
}
__device__ __forceinline__ void psplit2(float p0, float p1, uint32_t& hi, uint32_t& lo) {
    __half2 h = __floats2half2_rn(p0, p1);
    float2 hf = __half22float2(h);
    __half2 l = __floats2half2_rn(p0 - hf.x, p1 - hf.y);
    hi = *reinterpret_cast<uint32_t*>(&h);
    lo = *reinterpret_cast<uint32_t*>(&l);
}
__device__ __forceinline__ uint32_t h2scale8(uint32_t a) {   // *=0.125 exact
    __half2 s = __float2half2_rn(0.125f);
    __half2 r = __hmul2(*reinterpret_cast<__half2*>(&a), s);
    return *reinterpret_cast<uint32_t*>(&r);
}
#define HI_PAIR(v0, v1) __byte_perm((v0), (v1), 0x5410)
#define LO_PAIR(v0, v1) __byte_perm((v0), (v1), 0x7632)

__device__ __forceinline__ void mma16(float* c, const uint32_t* a, const uint32_t* b) {
    asm volatile(
        "mma.sync.aligned.m16n8k16.row.col.f32.f16.f16.f32 "
        "{%0,%1,%2,%3},{%4,%5,%6,%7},{%8,%9},{%0,%1,%2,%3};"
        : "+f"(c[0]), "+f"(c[1]), "+f"(c[2]), "+f"(c[3])
        : "r"(a[0]), "r"(a[1]), "r"(a[2]), "r"(a[3]), "r"(b[0]), "r"(b[1]));
}
__device__ __forceinline__ void mma3(float* c, const uint32_t* ah, const uint32_t* al,
                                     const uint32_t* bh, const uint32_t* bl) {
    mma16(c, ah, bl);
    mma16(c, al, bh);
    mma16(c, ah, bh);
}
__device__ __forceinline__ void cpa16(uint32_t dst, const void* src) {
    asm volatile("cp.async.cg.shared.global [%0], [%1], 16;" :: "r"(dst), "l"(src));
}

// ===========================================================================
// Prep kernels: split inputs into hi/lo half planes (transposed weights)
// ===========================================================================
__global__ __launch_bounds__(256) void splitx_kernel(const float* __restrict__ X) {
    int i = blockIdx.x * 256 + threadIdx.x;              // per float4
    float4 v = reinterpret_cast<const float4*>(X)[i];
    uint32_t h0, l0, h1, l1;
    psplit2(v.x, v.y, h0, l0);
    psplit2(v.z, v.w, h1, l1);
    g_Xh[2 * i] = h0; g_Xh[2 * i + 1] = h1;
    g_Xl[2 * i] = l0; g_Xl[2 * i + 1] = l1;
}
__global__ __launch_bounds__(256) void splitw_qkv_kernel(const float* __restrict__ Wq,
                                                         const float* __restrict__ Wk,
                                                         const float* __restrict__ Wv) {
    int idx = blockIdx.x * 256 + threadIdx.x;   // [w][h][n][kpair] flattened
    int kp = idx & 255, n = (idx >> 8) & 63, h = (idx >> 14) & 7, w = idx >> 17;
    const float* W = (w == 0) ? Wq : (w == 1) ? Wk : Wv;
    const float* b = W + ((size_t)h * DIM + 2 * kp) * HD + n;
    uint32_t hi, lo;
    psplit2(b[0], b[HD], hi, lo);
    g_Wth[idx] = hi; g_Wtl[idx] = lo;
}
__global__ __launch_bounds__(256) void splitw_o_kernel(const float* __restrict__ Wo) {
    int idx = blockIdx.x * 256 + threadIdx.x;   // [n][kpair]
    int kp = idx & 255, n = idx >> 8;
    const float* b = Wo + (size_t)(2 * kp) * DIM + n;
    uint32_t hi, lo;
    psplit2(b[0], b[DIM], hi, lo);
    g_Woth[idx] = hi; g_Wotl[idx] = lo;
}

// ===========================================================================
// QKV projection, ONE weight per block (K / V / Q modes):
// 256 thr, 8 warps (4M x 2N), warp 32x32, block 128x64, K-chunk 16,
// 3-stage cp.async, 1 bar/iter, 55KB smem + ~90 regs -> 2 blocks/SM.
// grid (8 heads, 480): y<224 K, 224<=y<448 V, y>=448 Q.
// ===========================================================================
#define GLD 12                                     // row stride u32 (8 data + 4 pad)
#define PJ_A_U32 (128 * GLD)                       // 1536 per plane
#define PJ_B_U32 (64 * GLD)                        // 768 per plane
#define PJ_STAGE_U32 (2 * PJ_A_U32 + 2 * PJ_B_U32) // 4608
#define PJ_SMEM (3 * PJ_STAGE_U32 * 4)             // 55296

__global__ __launch_bounds__(256, 2)
void qkv_kernel()
{
    extern __shared__ uint32_t dsm[];
    const uint32_t sb = (uint32_t)__cvta_generic_to_shared(dsm);

    const int tid  = threadIdx.x;
    const int lane = tid & 31;
    const int warp = tid >> 5;
    const int wm   = warp >> 1;      // 0..3
    const int wn   = warp & 1;       // 0..1
    const int bn   = blockIdx.x;     // head
    const int bm   = blockIdx.y;     // 0..479
    const int r0 = lane >> 2;
    const int j2 = 2 * (lane & 3);

    // mode: 0=K, 1=V, 2=Q
    int mode, bidx, t0, rowoff, wsel;
    if (bm < 224)       { mode = 0; int m2 = bm;        bidx = m2 / 28; t0 = (m2 % 28) * 128; rowoff = QDIM; wsel = 1; }
    else if (bm < 448)  { mode = 1; int m2 = bm - 224;  bidx = m2 / 28; t0 = (m2 % 28) * 128; rowoff = QDIM; wsel = 2; }
    else                { mode = 2; int m2 = bm - 448;  bidx = m2 >> 2; t0 = (m2 & 3) * 128;  rowoff = 0;    wsel = 0; }

    const uint32_t* Xhp = g_Xh + ((size_t)bidx * TT + rowoff + t0) * (DIM / 2);
    const uint32_t* Xlp = g_Xl + ((size_t)bidx * TT + rowoff + t0) * (DIM / 2);
    const size_t wb = ((size_t)(wsel * NH + bn)) * HD * (DIM / 2);
    const uint32_t* Whp = g_Wth + wb;
    const uint32_t* Wlp = g_Wtl + wb;

    auto prefetch = [&](int st, int c) {
        uint32_t base = sb + st * (PJ_STAGE_U32 * 4);
        #pragma unroll
        for (int j = 0; j < 2; j++) {      // A: 2 planes x 128 rows x 2 segs = 512
            int idx = tid + j * 256;
            int p = idx >> 8, rem = idx & 255;
            int row = rem >> 1, seg = rem & 1;
            cpa16(base + p * (PJ_A_U32 * 4) + row * (GLD * 4) + seg * 16,
                  (p ? Xlp : Xhp) + (size_t)row * (DIM / 2) + c * 8 + seg * 4);
        }
        {                                   // B: 2 planes x 64 rows x 2 segs = 256
            int p = tid >> 7, rem = tid & 127;
            int row = rem >> 1, seg = rem & 1;
            cpa16(base + (2 * PJ_A_U32 + p * PJ_B_U32) * 4 + row * (GLD * 4) + seg * 16,
                  (p ? Wlp : Whp) + (size_t)row * (DIM / 2) + c * 8 + seg * 4);
        }
    };

    float acc[2][4][4];     // [mt][nt][i]
    #pragma unroll
    for (int a = 0; a < 2; a++)
        #pragma unroll
        for (int b = 0; b < 4; b++)
            #pragma unroll
            for (int c = 0; c < 4; c++) acc[a][b][c] = 0.f;

    prefetch(0, 0);
    asm volatile("cp.async.commit_group;");
    prefetch(1, 1);
    asm volatile("cp.async.commit_group;");

    for (int it = 0; it < 32; it++) {
        asm volatile("cp.async.wait_group 1;");
        __syncthreads();
        if (it + 2 < 32) prefetch((it + 2) % 3, it + 2);
        asm volatile("cp.async.commit_group;");

        const uint32_t* Ah = dsm + (it % 3) * PJ_STAGE_U32;
        const uint32_t* Al = Ah + PJ_A_U32;
        const uint32_t* Bh = Ah + 2 * PJ_A_U32;
        const uint32_t* Bl = Bh + PJ_B_U32;

        uint32_t ah[2][4], al[2][4];
        #pragma unroll
        for (int mt = 0; mt < 2; mt++) {
            int base = (wm * 32 + mt * 16 + r0) * GLD + (lane & 3);
            ah[mt][0] = Ah[base];           al[mt][0] = Al[base];
            ah[mt][1] = Ah[base + 8 * GLD]; al[mt][1] = Al[base + 8 * GLD];
            ah[mt][2] = Ah[base + 4];       al[mt][2] = Al[base + 4];
            ah[mt][3] = Ah[base + 8 * GLD + 4]; al[mt][3] = Al[base + 8 * GLD + 4];
        }
        #pragma unroll
        for (int nt = 0; nt < 4; nt++) {
            int cidx = (wn * 32 + nt * 8 + r0) * GLD + (lane & 3);
            uint32_t bh[2], bl[2];
            bh[0] = Bh[cidx]; bh[1] = Bh[cidx + 4];
            bl[0] = Bl[cidx]; bl[1] = Bl[cidx + 4];
            #pragma unroll
            for (int mt = 0; mt < 2; mt++)
                mma3(acc[mt][nt], ah[mt], al[mt], bh, bl);
        }
        __syncthreads();
    }

    // Epilogues
    const size_t pb = (size_t)(bn * BATCH + bidx);
    if (mode == 2) {
        #pragma unroll
        for (int mt = 0; mt < 2; mt++)
            #pragma unroll
            for (int nt = 0; nt < 4; nt++)
                #pragma unroll
                for (int i = 0; i < 4; i++) {
                    int mloc = wm * 32 + mt * 16 + r0 + ((i & 2) ? 8 : 0);
                    int nloc = wn * 32 + nt * 8 + j2 + (i & 1);
                    g_Q[(pb * QDIM + t0 + mloc) * HD + nloc] = packsplit(acc[mt][nt][i]);
                }
    } else if (mode == 0) {
        #pragma unroll
        for (int mt = 0; mt < 2; mt++)
            #pragma unroll
            for (int nt = 0; nt < 4; nt++) {
                int grow = t0 + wm * 32 + mt * 16 + r0;
                int dp = wn * 16 + nt * 4 + (lane & 3);
                uint32_t h0, l0, h1, l1;
                psplit2(acc[mt][nt][0], acc[mt][nt][1], h0, l0);
                psplit2(acc[mt][nt][2], acc[mt][nt][3], h1, l1);
                size_t kb = (pb * GG + grow) * (HD / 2) + dp;
                g_Kh[kb] = h0; g_Kl[kb] = l0;
                g_Kh[kb + 8 * (HD / 2)] = h1; g_Kl[kb + 8 * (HD / 2)] = l1;
            }
    } else {
        #pragma unroll
        for (int mt = 0; mt < 2; mt++)
            #pragma unroll
            for (int nt = 0; nt < 4; nt++) {
                int grow = t0 + wm * 32 + mt * 16 + r0;
                uint32_t p0 = packsplit(acc[mt][nt][0]);
                uint32_t p1 = packsplit(acc[mt][nt][1]);
                uint32_t p2 = packsplit(acc[mt][nt][2]);
                uint32_t p3 = packsplit(acc[mt][nt][3]);
                uint32_t q0 = __shfl_down_sync(0xffffffffu, p0, 4);
                uint32_t q1 = __shfl_down_sync(0xffffffffu, p1, 4);
                uint32_t q2 = __shfl_down_sync(0xffffffffu, p2, 4);
                uint32_t q3 = __shfl_down_sync(0xffffffffu, p3, 4);
                if ((r0 & 1) == 0) {
                    int d0 = wn * 32 + nt * 8 + j2;
                    size_t vb = (pb * (GG / 2) + (grow >> 1)) * HD + d0;
                    g_V2h[vb]     = HI_PAIR(p0, q0); g_V2l[vb]     = LO_PAIR(p0, q0);
                    g_V2h[vb + 1] = HI_PAIR(p1, q1); g_V2l[vb + 1] = LO_PAIR(p1, q1);
                    g_V2h[vb + 4 * HD]     = HI_PAIR(p2, q2); g_V2l[vb + 4 * HD]     = LO_PAIR(p2, q2);
                    g_V2h[vb + 4 * HD + 1] = HI_PAIR(p3, q3); g_V2l[vb + 4 * HD + 1] = LO_PAIR(p3, q3);
                }
            }
    }
}

// ===========================================================================
// Out projection: 256 thr, 8 warps (4M x 2N), warp 32x32, block 128x64,
// K-chunk 16, 3-stage cp.async, 2 blocks/SM (54KB smem).
// ===========================================================================
__global__ __launch_bounds__(256, 2)
void oproj_kernel(float* __restrict__ Outp)
{
    extern __shared__ uint32_t dsm[];
    const uint32_t sb = (uint32_t)__cvta_generic_to_shared(dsm);

    const int tid  = threadIdx.x;
    const int lane = tid & 31;
    const int warp = tid >> 5;
    const int wm   = warp >> 1;
    const int wn   = warp & 1;
    const int bm   = blockIdx.y;
    const int bn   = blockIdx.x;
    const int r0 = lane >> 2;
    const int j2 = 2 * (lane & 3);

    const size_t arow = (size_t)bm * 128;
    const size_t brow = (size_t)bn * 64;

    auto prefetch = [&](int st, int c) {
        uint32_t base = sb + st * (PJ_STAGE_U32 * 4);
        #pragma unroll
        for (int j = 0; j < 2; j++) {
            int idx = tid + j * 256;
            int p = idx >> 8, rem = idx & 255;
            int row = rem >> 1, seg = rem & 1;
            cpa16(base + p * (PJ_A_U32 * 4) + row * (GLD * 4) + seg * 16,
                  (p ? g_Hdl : g_Hdh) + (arow + row) * (DIM / 2) + c * 8 + seg * 4);
        }
        {
            int p = tid >> 7, rem = tid & 127;
            int row = rem >> 1, seg = rem & 1;
            cpa16(base + (2 * PJ_A_U32 + p * PJ_B_U32) * 4 + row * (GLD * 4) + seg * 16,
                  (p ? g_Wotl : g_Woth) + (brow + row) * (DIM / 2) + c * 8 + seg * 4);
        }
    };

    float acc[2][4][4];
    #pragma unroll
    for (int a = 0; a < 2; a++)
        #pragma unroll
        for (int b = 0; b < 4; b++)
            #pragma unroll
            for (int c = 0; c < 4; c++) acc[a][b][c] = 0.f;

    prefetch(0, 0);
    asm volatile("cp.async.commit_group;");
    prefetch(1, 1);
    asm volatile("cp.async.commit_group;");

    for (int it = 0; it < 32; it++) {
        asm volatile("cp.async.wait_group 1;");
        __syncthreads();
        if (it + 2 < 32) prefetch((it + 2) % 3, it + 2);
        asm volatile("cp.async.commit_group;");

        const uint32_t* Ah = dsm + (it % 3) * PJ_STAGE_U32;
        const uint32_t* Al = Ah + PJ_A_U32;
        const uint32_t* Bh = Ah + 2 * PJ_A_U32;
        const uint32_t* Bl = Bh + PJ_B_U32;

        uint32_t ah[2][4], al[2][4];
        #pragma unroll
        for (int mt = 0; mt < 2; mt++) {
            int base = (wm * 32 + mt * 16 + r0) * GLD + (lane & 3);
            ah[mt][0] = Ah[base];           al[mt][0] = Al[base];
            ah[mt][1] = Ah[base + 8 * GLD]; al[mt][1] = Al[base + 8 * GLD];
            ah[mt][2] = Ah[base + 4];       al[mt][2] = Al[base + 4];
            ah[mt][3] = Ah[base + 8 * GLD + 4]; al[mt][3] = Al[base + 8 * GLD + 4];
        }
        #pragma unroll
        for (int nt = 0; nt < 4; nt++) {
            int cidx = (wn * 32 + nt * 8 + r0) * GLD + (lane & 3);
            uint32_t bh[2], bl[2];
            bh[0] = Bh[cidx]; bh[1] = Bh[cidx + 4];
            bl[0] = Bl[cidx]; bl[1] = Bl[cidx + 4];
            #pragma unroll
            for (int mt = 0; mt < 2; mt++)
                mma3(acc[mt][nt], ah[mt], al[mt], bh, bl);
        }
        __syncthreads();
    }

    #pragma unroll
    for (int mt = 0; mt < 2; mt++)
        #pragma unroll
        for (int nt = 0; nt < 4; nt++)
            #pragma unroll
            for (int i = 0; i < 4; i++) {
                int mloc = wm * 32 + mt * 16 + r0 + ((i & 2) ? 8 : 0);
                int nloc = wn * 32 + nt * 8 + j2 + (i & 1);
                Outp[(size_t)(bm * 128 + mloc) * DIM + bn * 64 + nloc] = acc[mt][nt][i];
            }
}

// ===========================================================================
// Flash attention: plane smem, 3-buffer cp.async, 1 bar/iter.
// (unchanged from round 6/8 — passing at rel_err 2.1e-5)
// ===========================================================================
#define AK_LD 36
#define AV_LD 72
#define AK_U32 (64 * AK_LD)
#define AV_U32 (32 * AV_LD)
#define ATTN_STAGE_U32 (2 * AK_U32 + 2 * AV_U32)
#define ATTN_SMEM (3 * ATTN_STAGE_U32 * 4)

__global__ __launch_bounds__(256, 2)
void attn_kernel()
{
    extern __shared__ uint32_t dsm[];
    const uint32_t sb = (uint32_t)__cvta_generic_to_shared(dsm);

    const int tid  = threadIdx.x;
    const int lane = tid & 31;
    const int warp = tid >> 5;
    const int qt   = blockIdx.x;
    const int pair = blockIdx.y;
    const int r0 = lane >> 2;
    const int j2 = 2 * (lane & 3);

    const uint32_t* Qp  = g_Q + ((size_t)pair * QDIM + qt * 128 + warp * 16) * HD;
    const size_t kbase = (size_t)pair * GG * (HD / 2);
    const size_t vbase = (size_t)pair * (GG / 2) * HD;

    auto prefetch = [&](int st, int c) {
        uint32_t base = sb + st * (ATTN_STAGE_U32 * 4);
        #pragma unroll
        for (int j = 0; j < 2; j++) {
            int idx = tid + j * 256;
            int row = idx >> 3, seg = idx & 7;
            cpa16(base + row * (AK_LD * 4) + seg * 16,
                  g_Kh + kbase + (size_t)(c * 64 + row) * (HD / 2) + seg * 4);
            cpa16(base + AK_U32 * 4 + row * (AK_LD * 4) + seg * 16,
                  g_Kl + kbase + (size_t)(c * 64 + row) * (HD / 2) + seg * 4);
        }
        #pragma unroll
        for (int j = 0; j < 2; j++) {
            int idx = tid + j * 256;
            int row = idx >> 4, seg = idx & 15;
            cpa16(base + 2 * AK_U32 * 4 + row * (AV_LD * 4) + seg * 16,
                  g_V2h + vbase + (size_t)(c * 32 + row) * HD + seg * 4);
            cpa16(base + (2 * AK_U32 + AV_U32) * 4 + row * (AV_LD * 4) + seg * 16,
                  g_V2l + vbase + (size_t)(c * 32 + row) * HD + seg * 4);
        }
    };

    uint32_t qh[4][4], ql[4][4];
    #pragma unroll
    for (int kk = 0; kk < 4; kk++) {
        int d0 = kk * 16 + j2;
        uint2 w01 = *reinterpret_cast<const uint2*>(Qp + (size_t)r0 * HD + d0);
        uint2 w23 = *reinterpret_cast<const uint2*>(Qp + (size_t)(r0 + 8) * HD + d0);
        uint2 w45 = *reinterpret_cast<const uint2*>(Qp + (size_t)r0 * HD + d0 + 8);
        uint2 w67 = *reinterpret_cast<const uint2*>(Qp + (size_t)(r0 + 8) * HD + d0 + 8);
        qh[kk][0] = h2scale8(HI_PAIR(w01.x, w01.y)); ql[kk][0] = h2scale8(LO_PAIR(w01.x, w01.y));
        qh[kk][1] = h2scale8(HI_PAIR(w23.x, w23.y)); ql[kk][1] = h2scale8(LO_PAIR(w23.x, w23.y));
        qh[kk][2] = h2scale8(HI_PAIR(w45.x, w45.y)); ql[kk][2] = h2scale8(LO_PAIR(w45.x, w45.y));
        qh[kk][3] = h2scale8(HI_PAIR(w67.x, w67.y)); ql[kk][3] = h2scale8(LO_PAIR(w67.x, w67.y));
    }

    float oacc[8][4];
    #pragma unroll
    for (int t = 0; t < 8; t++)
        #pragma unroll
        for (int i = 0; i < 4; i++) oacc[t][i] = 0.f;
    float m0 = -1e30f, m1 = -1e30f, l0 = 0.f, l1 = 0.f;

    prefetch(0, 0);
    asm volatile("cp.async.commit_group;");
    prefetch(1, 1);
    asm volatile("cp.async.commit_group;");

    for (int c = 0; c < NCHUNK; c++) {
        asm volatile("cp.async.wait_group 1;");
        __syncthreads();
        if (c + 2 < NCHUNK) prefetch((c + 2) % 3, c + 2);
        asm volatile("cp.async.commit_group;");

        const uint32_t* Kh = dsm + (c % 3) * ATTN_STAGE_U32;
        const uint32_t* Kl = Kh + AK_U32;
        const uint32_t* Vh = Kh + 2 * AK_U32;
        const uint32_t* Vl = Vh + AV_U32;

        float sacc[8][4];
        #pragma unroll
        for (int t = 0; t < 8; t++)
            #pragma unroll
            for (int i = 0; i < 4; i++) sacc[t][i] = 0.f;

        #pragma unroll
        for (int kk = 0; kk < 4; kk++) {
            #pragma unroll
            for (int nt = 0; nt < 8; nt++) {
                int cidx = (nt * 8 + r0) * AK_LD + kk * 8 + (lane & 3);
                uint32_t bh[2], bl[2];
                bh[0] = Kh[cidx]; bh[1] = Kh[cidx + 4];
                bl[0] = Kl[cidx]; bl[1] = Kl[cidx + 4];
                mma3(sacc[nt], qh[kk], ql[kk], bh, bl);
            }
        }

        float mx0 = -1e30f, mx1 = -1e30f;
        #pragma unroll
        for (int t = 0; t < 8; t++) {
            mx0 = fmaxf(mx0, fmaxf(sacc[t][0], sacc[t][1]));
            mx1 = fmaxf(mx1, fmaxf(sacc[t][2], sacc[t][3]));
        }
        mx0 = fmaxf(mx0, __shfl_xor_sync(0xffffffffu, mx0, 1));
        mx0 = fmaxf(mx0, __shfl_xor_sync(0xffffffffu, mx0, 2));
        mx1 = fmaxf(mx1, __shfl_xor_sync(0xffffffffu, mx1, 1));
        mx1 = fmaxf(mx1, __shfl_xor_sync(0xffffffffu, mx1, 2));

        float mn0 = fmaxf(m0, mx0), mn1 = fmaxf(m1, mx1);
        float al0 = __expf(m0 - mn0), al1 = __expf(m1 - mn1);
        float s0 = 0.f, s1 = 0.f;
        #pragma unroll
        for (int t = 0; t < 8; t++) {
            sacc[t][0] = __expf(sacc[t][0] - mn0);
            sacc[t][1] = __expf(sacc[t][1] - mn0);
            sacc[t][2] = __expf(sacc[t][2] - mn1);
            sacc[t][3] = __expf(sacc[t][3] - mn1);
            s0 += sacc[t][0] + sacc[t][1];
            s1 += sacc[t][2] + sacc[t][3];
        }
        s0 += __shfl_xor_sync(0xffffffffu, s0, 1);
        s0 += __shfl_xor_sync(0xffffffffu, s0, 2);
        s1 += __shfl_xor_sync(0xffffffffu, s1, 1);
        s1 += __shfl_xor_sync(0xffffffffu, s1, 2);
        l0 = l0 * al0 + s0;
        l1 = l1 * al1 + s1;
        m0 = mn0; m1 = mn1;
        #pragma unroll
        for (int nt = 0; nt < 8; nt++) {
            oacc[nt][0] *= al0; oacc[nt][1] *= al0;
            oacc[nt][2] *= al1; oacc[nt][3] *= al1;
        }

        #pragma unroll
        for (int kk = 0; kk < 4; kk++) {
            uint32_t pah[4], pal[4];
            psplit2(sacc[2 * kk][0],     sacc[2 * kk][1],     pah[0], pal[0]);
            psplit2(sacc[2 * kk][2],     sacc[2 * kk][3],     pah[1], pal[1]);
            psplit2(sacc[2 * kk + 1][0], sacc[2 * kk + 1][1], pah[2], pal[2]);
            psplit2(sacc[2 * kk + 1][2], sacc[2 * kk + 1][3], pah[3], pal[3]);
            int gp = kk * 8 + (lane & 3);
            #pragma unroll
            for (int nt = 0; nt < 8; nt++) {
                int d = nt * 8 + r0;
                uint32_t bh[2], bl[2];
                bh[0] = Vh[gp * AV_LD + d]; bh[1] = Vh[(gp + 4) * AV_LD + d];
                bl[0] = Vl[gp * AV_LD + d]; bl[1] = Vl[(gp + 4) * AV_LD + d];
                mma3(oacc[nt], pah, pal, bh, bl);
            }
        }
    }

    float inv0 = 1.f / l0, inv1 = 1.f / l1;
    int h = pair >> 3, b = pair & 7;
    #pragma unroll
    for (int nt = 0; nt < 8; nt++) {
        int q = qt * 128 + warp * 16 + r0;
        int dp = h * 32 + nt * 4 + (lane & 3);
        uint32_t h0, l0u, h1, l1u;
        psplit2(oacc[nt][0] * inv0, oacc[nt][1] * inv0, h0, l0u);
        psplit2(oacc[nt][2] * inv1, oacc[nt][3] * inv1, h1, l1u);
        size_t o = ((size_t)(b * QDIM + q)) * (DIM / 2) + dp;
        g_Hdh[o] = h0; g_Hdl[o] = l0u;
        g_Hdh[o + 8 * (DIM / 2)] = h1; g_Hdl[o + 8 * (DIM / 2)] = l1u;
    }
}

extern "C" void kernel_launch(void* const* d_in, const int* in_sizes, int n_in,
                              void* d_out, int out_size)
{
    (void)in_sizes; (void)n_in; (void)out_size;
    const float* q  = (const float*)d_in[0];
    const float* Wq = (const float*)d_in[1];
    const float* Wk = (const float*)d_in[2];
    const float* Wv = (const float*)d_in[3];
    const float* Wo = (const float*)d_in[4];
    float* out = (float*)d_out;

    static bool attrs_set = false;
    if (!attrs_set) {
        cudaFuncSetAttribute(qkv_kernel,   cudaFuncAttributeMaxDynamicSharedMemorySize, PJ_SMEM);
        cudaFuncSetAttribute(attn_kernel,  cudaFuncAttributeMaxDynamicSharedMemorySize, ATTN_SMEM);
        cudaFuncSetAttribute(oproj_kernel, cudaFuncAttributeMaxDynamicSharedMemorySize, PJ_SMEM);
        attrs_set = true;
    }

    splitx_kernel<<<16384, 256>>>(q);
    splitw_qkv_kernel<<<1536, 256>>>(Wq, Wk, Wv);
    splitw_o_kernel<<<512, 256>>>(Wo);
    qkv_kernel<<<dim3(8, 480), 256, PJ_SMEM>>>();
    attn_kernel<<<dim3(4, 64), 256, ATTN_SMEM>>>();
    oproj_kernel<<<dim3(8, 32), 256, PJ_SMEM>>>(out);
}

// round 10
// speedup vs baseline: 1.0474x; 1.0474x over previous
#include <cuda_runtime.h>
#include <cuda_fp16.h>
#include <cstdint>

#define BATCH 8
#define TT    4096
#define DIM   512
#define NH    8
#define HD    64
#define QDIM  512
#define GG    3584
#define NCHUNK 56

// ---- global scratch ----
// X / W / Wo / Hd planes use k-INTERLEAVED storage: within each 8-u32 group,
// original u32 index j is stored at p(j) = (j&3)*2 + (j>>2)  ({0,4,1,5,2,6,3,7}).
// Q / K / V layouts are unchanged (attn hot loop untouched).
__device__ __align__(256) uint32_t g_Q  [(size_t)NH*BATCH*QDIM*HD];        // packed (hi|lo) per element
__device__ __align__(256) uint32_t g_Kh [(size_t)NH*BATCH*GG*(HD/2)];      // [pair][g][dpair]
__device__ __align__(256) uint32_t g_Kl [(size_t)NH*BATCH*GG*(HD/2)];
__device__ __align__(256) uint32_t g_V2h[(size_t)NH*BATCH*(GG/2)*HD];      // [pair][gpair][d]
__device__ __align__(256) uint32_t g_V2l[(size_t)NH*BATCH*(GG/2)*HD];
__device__ __align__(256) uint32_t g_Hdh[(size_t)BATCH*QDIM*(DIM/2)];      // interleaved
__device__ __align__(256) uint32_t g_Hdl[(size_t)BATCH*QDIM*(DIM/2)];
__device__ __align__(256) uint32_t g_Xh [(size_t)BATCH*TT*(DIM/2)];        // interleaved
__device__ __align__(256) uint32_t g_Xl [(size_t)BATCH*TT*(DIM/2)];
__device__ __align__(256) uint32_t g_Wth[(size_t)3*NH*HD*(DIM/2)];         // interleaved
__device__ __align__(256) uint32_t g_Wtl[(size_t)3*NH*HD*(DIM/2)];
__device__ __align__(256) uint32_t g_Woth[(size_t)DIM*(DIM/2)];            // interleaved
__device__ __align__(256) uint32_t g_Wotl[(size_t)DIM*(DIM/2)];

__device__ __forceinline__ uint32_t packsplit(float v) {
    __half h = __float2half_rn(v);
    __half l = __float2half_rn(v - __half2float(h));
    return (uint32_t)__half_as_ushort(h) | ((uint32_t)__half_as_ushort(l) << 16);
}
__device__ __forceinline__ void psplit2(float p0, float p1, uint32_t& hi, uint32_t& lo) {
    __half2 h = __floats2half2_rn(p0, p1);
    float2 hf = __half22float2(h);
    __half2 l = __floats2half2_rn(p0 - hf.x, p1 - hf.y);
    hi = *reinterpret_cast<uint32_t*>(&h);
    lo = *reinterpret_cast<uint32_t*>(&l);
}
__device__ __forceinline__ uint32_t h2scale8(uint32_t a) {   // *=0.125 exact
    __half2 s = __float2half2_rn(0.125f);
    __half2 r = __hmul2(*reinterpret_cast<__half2*>(&a), s);
    return *reinterpret_cast<uint32_t*>(&r);
}
#define HI_PAIR(v0, v1) __byte_perm((v0), (v1), 0x5410)
#define LO_PAIR(v0, v1) __byte_perm((v0), (v1), 0x7632)

__device__ __forceinline__ void mma16(float* c, const uint32_t* a, const uint32_t* b) {
    asm volatile(
        "mma.sync.aligned.m16n8k16.row.col.f32.f16.f16.f32 "
        "{%0,%1,%2,%3},{%4,%5,%6,%7},{%8,%9},{%0,%1,%2,%3};"
        : "+f"(c[0]), "+f"(c[1]), "+f"(c[2]), "+f"(c[3])
        : "r"(a[0]), "r"(a[1]), "r"(a[2]), "r"(a[3]), "r"(b[0]), "r"(b[1]));
}
__device__ __forceinline__ void mma3(float* c, const uint32_t* ah, const uint32_t* al,
                                     const uint32_t* bh, const uint32_t* bl) {
    mma16(c, ah, bl);
    mma16(c, al, bh);
    mma16(c, ah, bh);
}
__device__ __forceinline__ void cpa16(uint32_t dst, const void* src) {
    asm volatile("cp.async.cg.shared.global [%0], [%1], 16;" :: "r"(dst), "l"(src));
}

// ===========================================================================
// Prep kernels (write interleaved planes)
// ===========================================================================
__global__ __launch_bounds__(256) void splitx_kernel(const float* __restrict__ X) {
    size_t g = (size_t)blockIdx.x * 256 + threadIdx.x;     // one 8-u32 group
    const float4* s = reinterpret_cast<const float4*>(X) + g * 4;
    float4 v0 = s[0], v1 = s[1], v2 = s[2], v3 = s[3];
    uint32_t h[8], l[8];
    psplit2(v0.x, v0.y, h[0], l[0]); psplit2(v0.z, v0.w, h[1], l[1]);
    psplit2(v1.x, v1.y, h[2], l[2]); psplit2(v1.z, v1.w, h[3], l[3]);
    psplit2(v2.x, v2.y, h[4], l[4]); psplit2(v2.z, v2.w, h[5], l[5]);
    psplit2(v3.x, v3.y, h[6], l[6]); psplit2(v3.z, v3.w, h[7], l[7]);
    // storage order {0,4,1,5,2,6,3,7}
    *reinterpret_cast<uint4*>(g_Xh + g * 8)     = make_uint4(h[0], h[4], h[1], h[5]);
    *reinterpret_cast<uint4*>(g_Xh + g * 8 + 4) = make_uint4(h[2], h[6], h[3], h[7]);
    *reinterpret_cast<uint4*>(g_Xl + g * 8)     = make_uint4(l[0], l[4], l[1], l[5]);
    *reinterpret_cast<uint4*>(g_Xl + g * 8 + 4) = make_uint4(l[2], l[6], l[3], l[7]);
}
__global__ __launch_bounds__(256) void splitw_qkv_kernel(const float* __restrict__ Wq,
                                                         const float* __restrict__ Wk,
                                                         const float* __restrict__ Wv) {
    int idx = blockIdx.x * 256 + threadIdx.x;   // storage index [w][h][n][kp_storage]
    int s7 = idx & 7;
    int jorig = (s7 >> 1) + ((s7 & 1) << 2);    // inverse permutation
    int kp = ((idx & 255) & ~7) | jorig;
    int n = (idx >> 8) & 63, h = (idx >> 14) & 7, w = idx >> 17;
    const float* W = (w == 0) ? Wq : (w == 1) ? Wk : Wv;
    const float* b = W + ((size_t)h * DIM + 2 * kp) * HD + n;
    uint32_t hi, lo;
    psplit2(b[0], b[HD], hi, lo);
    g_Wth[idx] = hi; g_Wtl[idx] = lo;
}
__global__ __launch_bounds__(256) void splitw_o_kernel(const float* __restrict__ Wo) {
    int idx = blockIdx.x * 256 + threadIdx.x;   // [n][kp_storage]
    int s7 = idx & 7;
    int jorig = (s7 >> 1) + ((s7 & 1) << 2);
    int kp = ((idx & 255) & ~7) | jorig;
    int n = idx >> 8;
    const float* b = Wo + (size_t)(2 * kp) * DIM + n;
    uint32_t hi, lo;
    psplit2(b[0], b[DIM], hi, lo);
    g_Woth[idx] = hi; g_Wotl[idx] = lo;
}

// ===========================================================================
// QKV projection (fused K+V, round-8 structure): 256 thr, 8 warps (4M x 2N),
// warp 32x32 per weight, K-chunk 16, 3-stage cp.async, 1 bar/iter.
// GLD=8 (no pad; interleaved layout makes uint2 frag loads conflict-free).
// grid (8 heads, 256): bm<224 -> K+V tiles, bm>=224 -> Q tiles.
// ===========================================================================
#define GLD 8
#define QKV_A_U32 (128 * GLD)                      // 1024 per plane
#define QKV_B_U32 (64 * GLD)                       // 512 per plane per weight
#define QKV_STAGE_U32 (2 * QKV_A_U32 + 4 * QKV_B_U32) // 4096
#define QKV_SMEM (3 * QKV_STAGE_U32 * 4)           // 49152

__global__ __launch_bounds__(256, 2)
void qkv_kernel()
{
    extern __shared__ uint32_t dsm[];
    const uint32_t sb = (uint32_t)__cvta_generic_to_shared(dsm);

    const int tid  = threadIdx.x;
    const int lane = tid & 31;
    const int warp = tid >> 5;
    const int wm   = warp >> 1;      // 0..3
    const int wn   = warp & 1;       // 0..1
    const int bn   = blockIdx.x;     // head
    const int bm   = blockIdx.y;     // 0..255
    const bool isQ = bm >= 224;
    const int r0 = lane >> 2;
    const int q2 = 2 * (lane & 3);   // interleaved frag offset
    const int j2 = 2 * (lane & 3);

    int bidx, t0, rowoff, w0sel, w1sel;
    if (isQ) {
        int qbm = bm - 224;
        bidx = qbm >> 2; t0 = (qbm & 3) * 128; rowoff = 0; w0sel = 0; w1sel = 0;
    } else {
        bidx = bm / 28; t0 = (bm % 28) * 128; rowoff = QDIM; w0sel = 1; w1sel = 2;
    }
    const int nw = isQ ? 1 : 2;

    const uint32_t* Xhp = g_Xh + ((size_t)bidx * TT + rowoff + t0) * (DIM / 2);
    const uint32_t* Xlp = g_Xl + ((size_t)bidx * TT + rowoff + t0) * (DIM / 2);
    const size_t wb0 = ((size_t)(w0sel * NH + bn)) * HD * (DIM / 2);
    const size_t wb1 = ((size_t)(w1sel * NH + bn)) * HD * (DIM / 2);

    auto prefetch = [&](int st, int c) {
        uint32_t base = sb + st * (QKV_STAGE_U32 * 4);
        #pragma unroll
        for (int j = 0; j < 2; j++) {      // A: 2 planes x 128 rows x 2 segs = 512
            int idx = tid + j * 256;
            int p = idx >> 8, rem = idx & 255;
            int row = rem >> 1, seg = rem & 1;
            cpa16(base + p * (QKV_A_U32 * 4) + row * (GLD * 4) + seg * 16,
                  (p ? Xlp : Xhp) + (size_t)row * (DIM / 2) + c * 8 + seg * 4);
        }
        #pragma unroll
        for (int j = 0; j < 2; j++) {      // B: 2w x 2p x 64 rows x 2 segs = 512
            int idx = tid + j * 256;
            int w = idx >> 8, rem = idx & 255;
            int p = (rem >> 7) & 1, r2 = rem & 127;
            int row = r2 >> 1, seg = r2 & 1;
            if (w < nw) {
                const uint32_t* src = (p ? g_Wtl : g_Wth) + (w ? wb1 : wb0)
                                      + (size_t)row * (DIM / 2) + c * 8 + seg * 4;
                cpa16(base + (2 * QKV_A_U32 + (w * 2 + p) * QKV_B_U32) * 4
                           + row * (GLD * 4) + seg * 16, src);
            }
        }
    };

    float acc[2][2][4][4];     // [w][mt][nt][i]
    #pragma unroll
    for (int w = 0; w < 2; w++)
        #pragma unroll
        for (int a = 0; a < 2; a++)
            #pragma unroll
            for (int b = 0; b < 4; b++)
                #pragma unroll
                for (int c = 0; c < 4; c++) acc[w][a][b][c] = 0.f;

    prefetch(0, 0);
    asm volatile("cp.async.commit_group;");
    prefetch(1, 1);
    asm volatile("cp.async.commit_group;");

    for (int it = 0; it < 32; it++) {
        asm volatile("cp.async.wait_group 1;");
        __syncthreads();
        if (it + 2 < 32) prefetch((it + 2) % 3, it + 2);
        asm volatile("cp.async.commit_group;");

        const uint32_t* Ah = dsm + (it % 3) * QKV_STAGE_U32;
        const uint32_t* Al = Ah + QKV_A_U32;
        const uint32_t* Bb = Ah + 2 * QKV_A_U32;

        uint32_t ah[2][4], al[2][4];
        #pragma unroll
        for (int mt = 0; mt < 2; mt++) {
            int base = (wm * 32 + mt * 16 + r0) * GLD + q2;
            uint2 h0 = *reinterpret_cast<const uint2*>(&Ah[base]);
            uint2 h1 = *reinterpret_cast<const uint2*>(&Ah[base + 8 * GLD]);
            uint2 l0 = *reinterpret_cast<const uint2*>(&Al[base]);
            uint2 l1 = *reinterpret_cast<const uint2*>(&Al[base + 8 * GLD]);
            ah[mt][0] = h0.x; ah[mt][2] = h0.y;
            ah[mt][1] = h1.x; ah[mt][3] = h1.y;
            al[mt][0] = l0.x; al[mt][2] = l0.y;
            al[mt][1] = l1.x; al[mt][3] = l1.y;
        }
        #pragma unroll
        for (int nt = 0; nt < 4; nt++) {
            int cidx = (wn * 32 + nt * 8 + r0) * GLD + q2;
            #pragma unroll
            for (int w = 0; w < 2; w++)
                if (w < nw) {
                    const uint32_t* Bh = Bb + (w * 2 + 0) * QKV_B_U32;
                    const uint32_t* Bl = Bb + (w * 2 + 1) * QKV_B_U32;
                    uint2 bhp = *reinterpret_cast<const uint2*>(&Bh[cidx]);
                    uint2 blp = *reinterpret_cast<const uint2*>(&Bl[cidx]);
                    uint32_t bh[2] = { bhp.x, bhp.y };
                    uint32_t bl[2] = { blp.x, blp.y };
                    #pragma unroll
                    for (int mt = 0; mt < 2; mt++)
                        mma3(acc[w][mt][nt], ah[mt], al[mt], bh, bl);
                }
        }
        __syncthreads();
    }

    // Epilogues (Q/K/V global layouts unchanged)
    if (isQ) {
        #pragma unroll
        for (int mt = 0; mt < 2; mt++)
            #pragma unroll
            for (int nt = 0; nt < 4; nt++)
                #pragma unroll
                for (int i = 0; i < 4; i++) {
                    int mloc = wm * 32 + mt * 16 + r0 + ((i & 2) ? 8 : 0);
                    int nloc = wn * 32 + nt * 8 + j2 + (i & 1);
                    g_Q[(((size_t)(bn * BATCH + bidx)) * QDIM + t0 + mloc) * HD + nloc] =
                        packsplit(acc[0][mt][nt][i]);
                }
    } else {
        const size_t pb = (size_t)(bn * BATCH + bidx);
        #pragma unroll
        for (int mt = 0; mt < 2; mt++)
            #pragma unroll
            for (int nt = 0; nt < 4; nt++) {
                int grow = t0 + wm * 32 + mt * 16 + r0;
                int dp = wn * 16 + nt * 4 + (lane & 3);
                uint32_t h0, l0, h1, l1;
                psplit2(acc[0][mt][nt][0], acc[0][mt][nt][1], h0, l0);
                psplit2(acc[0][mt][nt][2], acc[0][mt][nt][3], h1, l1);
                size_t kb = (pb * GG + grow) * (HD / 2) + dp;
                g_Kh[kb] = h0; g_Kl[kb] = l0;
                g_Kh[kb + 8 * (HD / 2)] = h1; g_Kl[kb + 8 * (HD / 2)] = l1;
                uint32_t p0 = packsplit(acc[1][mt][nt][0]);
                uint32_t p1 = packsplit(acc[1][mt][nt][1]);
                uint32_t p2 = packsplit(acc[1][mt][nt][2]);
                uint32_t p3 = packsplit(acc[1][mt][nt][3]);
                uint32_t q0 = __shfl_down_sync(0xffffffffu, p0, 4);
                uint32_t q1 = __shfl_down_sync(0xffffffffu, p1, 4);
                uint32_t q2s = __shfl_down_sync(0xffffffffu, p2, 4);
                uint32_t q3 = __shfl_down_sync(0xffffffffu, p3, 4);
                if ((r0 & 1) == 0) {
                    int d0 = wn * 32 + nt * 8 + j2;
                    size_t vb = (pb * (GG / 2) + (grow >> 1)) * HD + d0;
                    g_V2h[vb]     = HI_PAIR(p0, q0); g_V2l[vb]     = LO_PAIR(p0, q0);
                    g_V2h[vb + 1] = HI_PAIR(p1, q1); g_V2l[vb + 1] = LO_PAIR(p1, q1);
                    g_V2h[vb + 4 * HD]     = HI_PAIR(p2, q2s); g_V2l[vb + 4 * HD]     = LO_PAIR(p2, q2s);
                    g_V2h[vb + 4 * HD + 1] = HI_PAIR(p3, q3);  g_V2l[vb + 4 * HD + 1] = LO_PAIR(p3, q3);
                }
            }
    }
}

// ===========================================================================
// Out projection: same structure, interleaved Hd/Wo planes, GLD=8.
// ===========================================================================
#define OP_A_U32 (128 * GLD)                       // 1024 per plane
#define OP_B_U32 (64 * GLD)                        // 512 per plane
#define OP_STAGE_U32 (2 * OP_A_U32 + 2 * OP_B_U32) // 3072
#define OP_SMEM (3 * OP_STAGE_U32 * 4)             // 36864

__global__ __launch_bounds__(256, 2)
void oproj_kernel(float* __restrict__ Outp)
{
    extern __shared__ uint32_t dsm[];
    const uint32_t sb = (uint32_t)__cvta_generic_to_shared(dsm);

    const int tid  = threadIdx.x;
    const int lane = tid & 31;
    const int warp = tid >> 5;
    const int wm   = warp >> 1;
    const int wn   = warp & 1;
    const int bm   = blockIdx.y;
    const int bn   = blockIdx.x;
    const int r0 = lane >> 2;
    const int q2 = 2 * (lane & 3);
    const int j2 = 2 * (lane & 3);

    const size_t arow = (size_t)bm * 128;
    const size_t brow = (size_t)bn * 64;

    auto prefetch = [&](int st, int c) {
        uint32_t base = sb + st * (OP_STAGE_U32 * 4);
        #pragma unroll
        for (int j = 0; j < 2; j++) {
            int idx = tid + j * 256;
            int p = idx >> 8, rem = idx & 255;
            int row = rem >> 1, seg = rem & 1;
            cpa16(base + p * (OP_A_U32 * 4) + row * (GLD * 4) + seg * 16,
                  (p ? g_Hdl : g_Hdh) + (arow + row) * (DIM / 2) + c * 8 + seg * 4);
        }
        {
            int p = tid >> 7, rem = tid & 127;
            int row = rem >> 1, seg = rem & 1;
            cpa16(base + (2 * OP_A_U32 + p * OP_B_U32) * 4 + row * (GLD * 4) + seg * 16,
                  (p ? g_Wotl : g_Woth) + (brow + row) * (DIM / 2) + c * 8 + seg * 4);
        }
    };

    float acc[2][4][4];
    #pragma unroll
    for (int a = 0; a < 2; a++)
        #pragma unroll
        for (int b = 0; b < 4; b++)
            #pragma unroll
            for (int c = 0; c < 4; c++) acc[a][b][c] = 0.f;

    prefetch(0, 0);
    asm volatile("cp.async.commit_group;");
    prefetch(1, 1);
    asm volatile("cp.async.commit_group;");

    for (int it = 0; it < 32; it++) {
        asm volatile("cp.async.wait_group 1;");
        __syncthreads();
        if (it + 2 < 32) prefetch((it + 2) % 3, it + 2);
        asm volatile("cp.async.commit_group;");

        const uint32_t* Ah = dsm + (it % 3) * OP_STAGE_U32;
        const uint32_t* Al = Ah + OP_A_U32;
        const uint32_t* Bh = Ah + 2 * OP_A_U32;
        const uint32_t* Bl = Bh + OP_B_U32;

        uint32_t ah[2][4], al[2][4];
        #pragma unroll
        for (int mt = 0; mt < 2; mt++) {
            int base = (wm * 32 + mt * 16 + r0) * GLD + q2;
            uint2 h0 = *reinterpret_cast<const uint2*>(&Ah[base]);
            uint2 h1 = *reinterpret_cast<const uint2*>(&Ah[base + 8 * GLD]);
            uint2 l0 = *reinterpret_cast<const uint2*>(&Al[base]);
            uint2 l1 = *reinterpret_cast<const uint2*>(&Al[base + 8 * GLD]);
            ah[mt][0] = h0.x; ah[mt][2] = h0.y;
            ah[mt][1] = h1.x; ah[mt][3] = h1.y;
            al[mt][0] = l0.x; al[mt][2] = l0.y;
            al[mt][1] = l1.x; al[mt][3] = l1.y;
        }
        #pragma unroll
        for (int nt = 0; nt < 4; nt++) {
            int cidx = (wn * 32 + nt * 8 + r0) * GLD + q2;
            uint2 bhp = *reinterpret_cast<const uint2*>(&Bh[cidx]);
            uint2 blp = *reinterpret_cast<const uint2*>(&Bl[cidx]);
            uint32_t bh[2] = { bhp.x, bhp.y };
            uint32_t bl[2] = { blp.x, blp.y };
            #pragma unroll
            for (int mt = 0; mt < 2; mt++)
                mma3(acc[mt][nt], ah[mt], al[mt], bh, bl);
        }
        __syncthreads();
    }

    #pragma unroll
    for (int mt = 0; mt < 2; mt++)
        #pragma unroll
        for (int nt = 0; nt < 4; nt++)
            #pragma unroll
            for (int i = 0; i < 4; i++) {
                int mloc = wm * 32 + mt * 16 + r0 + ((i & 2) ? 8 : 0);
                int nloc = wn * 32 + nt * 8 + j2 + (i & 1);
                Outp[(size_t)(bm * 128 + mloc) * DIM + bn * 64 + nloc] = acc[mt][nt][i];
            }
}

// ===========================================================================
// Flash attention: unchanged hot loop; Hd-epilogue writes interleaved positions.
// ===========================================================================
#define AK_LD 36
#define AV_LD 72
#define AK_U32 (64 * AK_LD)
#define AV_U32 (32 * AV_LD)
#define ATTN_STAGE_U32 (2 * AK_U32 + 2 * AV_U32)
#define ATTN_SMEM (3 * ATTN_STAGE_U32 * 4)

__global__ __launch_bounds__(256, 2)
void attn_kernel()
{
    extern __shared__ uint32_t dsm[];
    const uint32_t sb = (uint32_t)__cvta_generic_to_shared(dsm);

    const int tid  = threadIdx.x;
    const int lane = tid & 31;
    const int warp = tid >> 5;
    const int qt   = blockIdx.x;
    const int pair = blockIdx.y;
    const int r0 = lane >> 2;
    const int j2 = 2 * (lane & 3);

    const uint32_t* Qp  = g_Q + ((size_t)pair * QDIM + qt * 128 + warp * 16) * HD;
    const size_t kbase = (size_t)pair * GG * (HD / 2);
    const size_t vbase = (size_t)pair * (GG / 2) * HD;

    auto prefetch = [&](int st, int c) {
        uint32_t base = sb + st * (ATTN_STAGE_U32 * 4);
        #pragma unroll
        for (int j = 0; j < 2; j++) {
            int idx = tid + j * 256;
            int row = idx >> 3, seg = idx & 7;
            cpa16(base + row * (AK_LD * 4) + seg * 16,
                  g_Kh + kbase + (size_t)(c * 64 + row) * (HD / 2) + seg * 4);
            cpa16(base + AK_U32 * 4 + row * (AK_LD * 4) + seg * 16,
                  g_Kl + kbase + (size_t)(c * 64 + row) * (HD / 2) + seg * 4);
        }
        #pragma unroll
        for (int j = 0; j < 2; j++) {
            int idx = tid + j * 256;
            int row = idx >> 4, seg = idx & 15;
            cpa16(base + 2 * AK_U32 * 4 + row * (AV_LD * 4) + seg * 16,
                  g_V2h + vbase + (size_t)(c * 32 + row) * HD + seg * 4);
            cpa16(base + (2 * AK_U32 + AV_U32) * 4 + row * (AV_LD * 4) + seg * 16,
                  g_V2l + vbase + (size_t)(c * 32 + row) * HD + seg * 4);
        }
    };

    uint32_t qh[4][4], ql[4][4];
    #pragma unroll
    for (int kk = 0; kk < 4; kk++) {
        int d0 = kk * 16 + j2;
        uint2 w01 = *reinterpret_cast<const uint2*>(Qp + (size_t)r0 * HD + d0);
        uint2 w23 = *reinterpret_cast<const uint2*>(Qp + (size_t)(r0 + 8) * HD + d0);
        uint2 w45 = *reinterpret_cast<const uint2*>(Qp + (size_t)r0 * HD + d0 + 8);
        uint2 w67 = *reinterpret_cast<const uint2*>(Qp + (size_t)(r0 + 8) * HD + d0 + 8);
        qh[kk][0] = h2scale8(HI_PAIR(w01.x, w01.y)); ql[kk][0] = h2scale8(LO_PAIR(w01.x, w01.y));
        qh[kk][1] = h2scale8(HI_PAIR(w23.x, w23.y)); ql[kk][1] = h2scale8(LO_PAIR(w23.x, w23.y));
        qh[kk][2] = h2scale8(HI_PAIR(w45.x, w45.y)); ql[kk][2] = h2scale8(LO_PAIR(w45.x, w45.y));
        qh[kk][3] = h2scale8(HI_PAIR(w67.x, w67.y)); ql[kk][3] = h2scale8(LO_PAIR(w67.x, w67.y));
    }

    float oacc[8][4];
    #pragma unroll
    for (int t = 0; t < 8; t++)
        #pragma unroll
        for (int i = 0; i < 4; i++) oacc[t][i] = 0.f;
    float m0 = -1e30f, m1 = -1e30f, l0 = 0.f, l1 = 0.f;

    prefetch(0, 0);
    asm volatile("cp.async.commit_group;");
    prefetch(1, 1);
    asm volatile("cp.async.commit_group;");

    for (int c = 0; c < NCHUNK; c++) {
        asm volatile("cp.async.wait_group 1;");
        __syncthreads();
        if (c + 2 < NCHUNK) prefetch((c + 2) % 3, c + 2);
        asm volatile("cp.async.commit_group;");

        const uint32_t* Kh = dsm + (c % 3) * ATTN_STAGE_U32;
        const uint32_t* Kl = Kh + AK_U32;
        const uint32_t* Vh = Kh + 2 * AK_U32;
        const uint32_t* Vl = Vh + AV_U32;

        float sacc[8][4];
        #pragma unroll
        for (int t = 0; t < 8; t++)
            #pragma unroll
            for (int i = 0; i < 4; i++) sacc[t][i] = 0.f;

        #pragma unroll
        for (int kk = 0; kk < 4; kk++) {
            #pragma unroll
            for (int nt = 0; nt < 8; nt++) {
                int cidx = (nt * 8 + r0) * AK_LD + kk * 8 + (lane & 3);
                uint32_t bh[2], bl[2];
                bh[0] = Kh[cidx]; bh[1] = Kh[cidx + 4];
                bl[0] = Kl[cidx]; bl[1] = Kl[cidx + 4];
                mma3(sacc[nt], qh[kk], ql[kk], bh, bl);
            }
        }

        float mx0 = -1e30f, mx1 = -1e30f;
        #pragma unroll
        for (int t = 0; t < 8; t++) {
            mx0 = fmaxf(mx0, fmaxf(sacc[t][0], sacc[t][1]));
            mx1 = fmaxf(mx1, fmaxf(sacc[t][2], sacc[t][3]));
        }
        mx0 = fmaxf(mx0, __shfl_xor_sync(0xffffffffu, mx0, 1));
        mx0 = fmaxf(mx0, __shfl_xor_sync(0xffffffffu, mx0, 2));
        mx1 = fmaxf(mx1, __shfl_xor_sync(0xffffffffu, mx1, 1));
        mx1 = fmaxf(mx1, __shfl_xor_sync(0xffffffffu, mx1, 2));

        float mn0 = fmaxf(m0, mx0), mn1 = fmaxf(m1, mx1);
        float al0 = __expf(m0 - mn0), al1 = __expf(m1 - mn1);
        float s0 = 0.f, s1 = 0.f;
        #pragma unroll
        for (int t = 0; t < 8; t++) {
            sacc[t][0] = __expf(sacc[t][0] - mn0);
            sacc[t][1] = __expf(sacc[t][1] - mn0);
            sacc[t][2] = __expf(sacc[t][2] - mn1);
            sacc[t][3] = __expf(sacc[t][3] - mn1);
            s0 += sacc[t][0] + sacc[t][1];
            s1 += sacc[t][2] + sacc[t][3];
        }
        s0 += __shfl_xor_sync(0xffffffffu, s0, 1);
        s0 += __shfl_xor_sync(0xffffffffu, s0, 2);
        s1 += __shfl_xor_sync(0xffffffffu, s1, 1);
        s1 += __shfl_xor_sync(0xffffffffu, s1, 2);
        l0 = l0 * al0 + s0;
        l1 = l1 * al1 + s1;
        m0 = mn0; m1 = mn1;
        #pragma unroll
        for (int nt = 0; nt < 8; nt++) {
            oacc[nt][0] *= al0; oacc[nt][1] *= al0;
            oacc[nt][2] *= al1; oacc[nt][3] *= al1;
        }

        #pragma unroll
        for (int kk = 0; kk < 4; kk++) {
            uint32_t pah[4], pal[4];
            psplit2(sacc[2 * kk][0],     sacc[2 * kk][1],     pah[0], pal[0]);
            psplit2(sacc[2 * kk][2],     sacc[2 * kk][3],     pah[1], pal[1]);
            psplit2(sacc[2 * kk + 1][0], sacc[2 * kk + 1][1], pah[2], pal[2]);
            psplit2(sacc[2 * kk + 1][2], sacc[2 * kk + 1][3], pah[3], pal[3]);
            int gp = kk * 8 + (lane & 3);
            #pragma unroll
            for (int nt = 0; nt < 8; nt++) {
                int d = nt * 8 + r0;
                uint32_t bh[2], bl[2];
                bh[0] = Vh[gp * AV_LD + d]; bh[1] = Vh[(gp + 4) * AV_LD + d];
                bl[0] = Vl[gp * AV_LD + d]; bl[1] = Vl[(gp + 4) * AV_LD + d];
                mma3(oacc[nt], pah, pal, bh, bl);
            }
        }
    }

    // Epilogue: write Hd planes at INTERLEAVED positions
    float inv0 = 1.f / l0, inv1 = 1.f / l1;
    int h = pair >> 3, b = pair & 7;
    #pragma unroll
    for (int nt = 0; nt < 8; nt++) {
        int q = qt * 128 + warp * 16 + r0;
        int dps = h * 32 + (nt >> 1) * 8 + ((lane & 3) * 2) + (nt & 1);  // permuted
        uint32_t h0, l0u, h1, l1u;
        psplit2(oacc[nt][0] * inv0, oacc[nt][1] * inv0, h0, l0u);
        psplit2(oacc[nt][2] * inv1, oacc[nt][3] * inv1, h1, l1u);
        size_t o = ((size_t)(b * QDIM + q)) * (DIM / 2) + dps;
        g_Hdh[o] = h0; g_Hdl[o] = l0u;
        g_Hdh[o + 8 * (DIM / 2)] = h1; g_Hdl[o + 8 * (DIM / 2)] = l1u;
    }
}

extern "C" void kernel_launch(void* const* d_in, const int* in_sizes, int n_in,
                              void* d_out, int out_size)
{
    (void)in_sizes; (void)n_in; (void)out_size;
    const float* q  = (const float*)d_in[0];
    const float* Wq = (const float*)d_in[1];
    const float* Wk = (const float*)d_in[2];
    const float* Wv = (const float*)d_in[3];
    const float* Wo = (const float*)d_in[4];
    float* out = (float*)d_out;

    static bool attrs_set = false;
    if (!attrs_set) {
        cudaFuncSetAttribute(qkv_kernel,   cudaFuncAttributeMaxDynamicSharedMemorySize, QKV_SMEM);
        cudaFuncSetAttribute(attn_kernel,  cudaFuncAttributeMaxDynamicSharedMemorySize, ATTN_SMEM);
        cudaFuncSetAttribute(oproj_kernel, cudaFuncAttributeMaxDynamicSharedMemorySize, OP_SMEM);
        attrs_set = true;
    }

    splitx_kernel<<<4096, 256>>>(q);                        // 1 thread per 8-u32 group
    splitw_qkv_kernel<<<1536, 256>>>(Wq, Wk, Wv);
    splitw_o_kernel<<<512, 256>>>(Wo);
    qkv_kernel<<<dim3(8, 256), 256, QKV_SMEM>>>();
    attn_kernel<<<dim3(4, 64), 256, ATTN_SMEM>>>();
    oproj_kernel<<<dim3(8, 32), 256, OP_SMEM>>>(out);
}

// round 11
// speedup vs baseline: 1.0907x; 1.0414x over previous
#include <cuda_runtime.h>
#include <cuda_fp16.h>
#include <cstdint>

#define BATCH 8
#define TT    4096
#define DIM   512
#define NH    8
#define HD    64
#define QDIM  512
#define GG    3584
#define NCHUNK 56

// ---- global scratch (u32 = half2 of adjacent elements of ONE plane) ----
__device__ __align__(256) uint32_t g_Q  [(size_t)NH*BATCH*QDIM*HD];        // packed (hi|lo) per element
__device__ __align__(256) uint32_t g_Kh [(size_t)NH*BATCH*GG*(HD/2)];      // [pair][g][dpair]
__device__ __align__(256) uint32_t g_Kl [(size_t)NH*BATCH*GG*(HD/2)];
__device__ __align__(256) uint32_t g_V2h[(size_t)NH*BATCH*(GG/2)*HD];      // [pair][gpair][d]
__device__ __align__(256) uint32_t g_V2l[(size_t)NH*BATCH*(GG/2)*HD];
__device__ __align__(256) uint32_t g_Hdh[(size_t)BATCH*QDIM*(DIM/2)];      // [b][q][epair]
__device__ __align__(256) uint32_t g_Hdl[(size_t)BATCH*QDIM*(DIM/2)];
__device__ __align__(256) uint32_t g_Xh [(size_t)BATCH*TT*(DIM/2)];        // [b][t][kpair]
__device__ __align__(256) uint32_t g_Xl [(size_t)BATCH*TT*(DIM/2)];
__device__ __align__(256) uint32_t g_Wth[(size_t)3*NH*HD*(DIM/2)];         // [w][h][n][kpair]
__device__ __align__(256) uint32_t g_Wtl[(size_t)3*NH*HD*(DIM/2)];
__device__ __align__(256) uint32_t g_Woth[(size_t)DIM*(DIM/2)];            // [n][kpair]
__device__ __align__(256) uint32_t g_Wotl[(size_t)DIM*(DIM/2)];

__device__ __forceinline__ uint32_t packsplit(float v) {
    __half h = __float2half_rn(v);
    __half l = __float2half_rn(v - __half2float(h));
    return (uint32_t)__half_as_ushort(h) | ((uint32_t)__half_as_ushort(l) << 16);
}
__device__ __forceinline__ void psplit2(float p0, float p1, uint32_t& hi, uint32_t& lo) {
    __half2 h = __floats2half2_rn(p0, p1);
    float2 hf = __half22float2(h);
    __half2 l = __floats2half2_rn(p0 - hf.x, p1 - hf.y);
    hi = *reinterpret_cast<uint32_t*>(&h);
    lo = *reinterpret_cast<uint32_t*>(&l);
}
__device__ __forceinline__ uint32_t h2scale8(uint32_t a) {   // *=0.125 exact
    __half2 s = __float2half2_rn(0.125f);
    __half2 r = __hmul2(*reinterpret_cast<__half2*>(&a), s);
    return *reinterpret_cast<uint32_t*>(&r);
}
#define HI_PAIR(v0, v1) __byte_perm((v0), (v1), 0x5410)
#define LO_PAIR(v0, v1) __byte_perm((v0), (v1), 0x7632)

__device__ __forceinline__ void mma16(float* c, const uint32_t* a, const uint32_t* b) {
    asm volatile(
        "mma.sync.aligned.m16n8k16.row.col.f32.f16.f16.f32 "
        "{%0,%1,%2,%3},{%4,%5,%6,%7},{%8,%9},{%0,%1,%2,%3};"
        : "+f"(c[0]), "+f"(c[1]), "+f"(c[2]), "+f"(c[3])
        : "r"(a[0]), "r"(a[1]), "r"(a[2]), "r"(a[3]), "r"(b[0]), "r"(b[1]));
}
__device__ __forceinline__ void mma3(float* c, const uint32_t* ah, const uint32_t* al,
                                     const uint32_t* bh, const uint32_t* bl) {
    mma16(c, ah, bl);
    mma16(c, al, bh);
    mma16(c, ah, bh);
}
__device__ __forceinline__ void cpa16(uint32_t dst, const void* src) {
    asm volatile("cp.async.cg.shared.global [%0], [%1], 16;" :: "r"(dst), "l"(src));
}

// ===========================================================================
// Prep kernels: split inputs into hi/lo half planes (transposed weights)
// ===========================================================================
__global__ __launch_bounds__(256) void splitx_kernel(const float* __restrict__ X) {
    int i = blockIdx.x * 256 + threadIdx.x;              // per float4
    float4 v = reinterpret_cast<const float4*>(X)[i];
    uint32_t h0, l0, h1, l1;
    psplit2(v.x, v.y, h0, l0);
    psplit2(v.z, v.w, h1, l1);
    g_Xh[2 * i] = h0; g_Xh[2 * i + 1] = h1;
    g_Xl[2 * i] = l0; g_Xl[2 * i + 1] = l1;
}
__global__ __launch_bounds__(256) void splitw_qkv_kernel(const float* __restrict__ Wq,
                                                         const float* __restrict__ Wk,
                                                         const float* __restrict__ Wv) {
    int idx = blockIdx.x * 256 + threadIdx.x;   // [w][h][n][kpair] flattened
    int kp = idx & 255, n = (idx >> 8) & 63, h = (idx >> 14) & 7, w = idx >> 17;
    const float* W = (w == 0) ? Wq : (w == 1) ? Wk : Wv;
    const float* b = W + ((size_t)h * DIM + 2 * kp) * HD + n;
    uint32_t hi, lo;
    psplit2(b[0], b[HD], hi, lo);
    g_Wth[idx] = hi; g_Wtl[idx] = lo;
}
__global__ __launch_bounds__(256) void splitw_o_kernel(const float* __restrict__ Wo) {
    int idx = blockIdx.x * 256 + threadIdx.x;   // [n][kpair]
    int kp = idx & 255, n = idx >> 8;
    const float* b = Wo + (size_t)(2 * kp) * DIM + n;
    uint32_t hi, lo;
    psplit2(b[0], b[DIM], hi, lo);
    g_Woth[idx] = hi; g_Wotl[idx] = lo;
}

// ===========================================================================
// QKV projection (round-8 structure; MMA issue reordered breadth-first):
// 256 thr, 8 warps (4M x 2N), warp 32x32 per weight, K-chunk 16,
// 3-stage cp.async, 1 bar/iter, 2 blocks/SM.
// grid (8 heads, 256): bm<224 -> K+V tiles, bm>=224 -> Q tiles.
// ===========================================================================
#define GLD 12                                     // row stride u32 (8 data + 4 pad)
#define QKV_A_U32 (128 * GLD)                      // 1536 per plane
#define QKV_B_U32 (64 * GLD)                       // 768 per plane per weight
#define QKV_STAGE_U32 (2 * QKV_A_U32 + 4 * QKV_B_U32) // 6144
#define QKV_SMEM (3 * QKV_STAGE_U32 * 4)           // 73728

__global__ __launch_bounds__(256, 2)
void qkv_kernel()
{
    extern __shared__ uint32_t dsm[];
    const uint32_t sb = (uint32_t)__cvta_generic_to_shared(dsm);

    const int tid  = threadIdx.x;
    const int lane = tid & 31;
    const int warp = tid >> 5;
    const int wm   = warp >> 1;      // 0..3
    const int wn   = warp & 1;       // 0..1
    const int bn   = blockIdx.x;     // head
    const int bm   = blockIdx.y;     // 0..255
    const bool isQ = bm >= 224;
    const int r0 = lane >> 2;
    const int j2 = 2 * (lane & 3);

    int bidx, t0, rowoff, w0sel, w1sel;
    if (isQ) {
        int qbm = bm - 224;
        bidx = qbm >> 2; t0 = (qbm & 3) * 128; rowoff = 0; w0sel = 0; w1sel = 0;
    } else {
        bidx = bm / 28; t0 = (bm % 28) * 128; rowoff = QDIM; w0sel = 1; w1sel = 2;
    }
    const int nw = isQ ? 1 : 2;

    const uint32_t* Xhp = g_Xh + ((size_t)bidx * TT + rowoff + t0) * (DIM / 2);
    const uint32_t* Xlp = g_Xl + ((size_t)bidx * TT + rowoff + t0) * (DIM / 2);
    const size_t wb0 = ((size_t)(w0sel * NH + bn)) * HD * (DIM / 2);
    const size_t wb1 = ((size_t)(w1sel * NH + bn)) * HD * (DIM / 2);

    auto prefetch = [&](int st, int c) {
        uint32_t base = sb + st * (QKV_STAGE_U32 * 4);
        #pragma unroll
        for (int j = 0; j < 2; j++) {      // A: 2 planes x 128 rows x 2 segs = 512
            int idx = tid + j * 256;
            int p = idx >> 8, rem = idx & 255;
            int row = rem >> 1, seg = rem & 1;
            cpa16(base + p * (QKV_A_U32 * 4) + row * (GLD * 4) + seg * 16,
                  (p ? Xlp : Xhp) + (size_t)row * (DIM / 2) + c * 8 + seg * 4);
        }
        #pragma unroll
        for (int j = 0; j < 2; j++) {      // B: 2w x 2p x 64 rows x 2 segs = 512
            int idx = tid + j * 256;
            int w = idx >> 8, rem = idx & 255;
            int p = (rem >> 7) & 1, r2 = rem & 127;
            int row = r2 >> 1, seg = r2 & 1;
            if (w < nw) {
                const uint32_t* src = (p ? g_Wtl : g_Wth) + (w ? wb1 : wb0)
                                      + (size_t)row * (DIM / 2) + c * 8 + seg * 4;
                cpa16(base + (2 * QKV_A_U32 + (w * 2 + p) * QKV_B_U32) * 4
                           + row * (GLD * 4) + seg * 16, src);
            }
        }
    };

    float acc[2][2][4][4];     // [w][mt][nt][i]
    #pragma unroll
    for (int w = 0; w < 2; w++)
        #pragma unroll
        for (int a = 0; a < 2; a++)
            #pragma unroll
            for (int b = 0; b < 4; b++)
                #pragma unroll
                for (int c = 0; c < 4; c++) acc[w][a][b][c] = 0.f;

    prefetch(0, 0);
    asm volatile("cp.async.commit_group;");
    prefetch(1, 1);
    asm volatile("cp.async.commit_group;");

    for (int it = 0; it < 32; it++) {
        asm volatile("cp.async.wait_group 1;");
        __syncthreads();
        if (it + 2 < 32) prefetch((it + 2) % 3, it + 2);
        asm volatile("cp.async.commit_group;");

        const uint32_t* Ah = dsm + (it % 3) * QKV_STAGE_U32;
        const uint32_t* Al = Ah + QKV_A_U32;
        const uint32_t* Bb = Ah + 2 * QKV_A_U32;

        // ---- load ALL fragments for this iteration first ----
        uint32_t ah[2][4], al[2][4];
        #pragma unroll
        for (int mt = 0; mt < 2; mt++) {
            int base = (wm * 32 + mt * 16 + r0) * GLD + (lane & 3);
            ah[mt][0] = Ah[base];           al[mt][0] = Al[base];
            ah[mt][1] = Ah[base + 8 * GLD]; al[mt][1] = Al[base + 8 * GLD];
            ah[mt][2] = Ah[base + 4];       al[mt][2] = Al[base + 4];
            ah[mt][3] = Ah[base + 8 * GLD + 4]; al[mt][3] = Al[base + 8 * GLD + 4];
        }
        uint32_t bh[4][2][2], bl[4][2][2];   // [nt][w][2]
        #pragma unroll
        for (int nt = 0; nt < 4; nt++) {
            int cidx = (wn * 32 + nt * 8 + r0) * GLD + (lane & 3);
            #pragma unroll
            for (int w = 0; w < 2; w++)
                if (w < nw) {
                    const uint32_t* Bh = Bb + (w * 2 + 0) * QKV_B_U32;
                    const uint32_t* Bl = Bb + (w * 2 + 1) * QKV_B_U32;
                    bh[nt][w][0] = Bh[cidx]; bh[nt][w][1] = Bh[cidx + 4];
                    bl[nt][w][0] = Bl[cidx]; bl[nt][w][1] = Bl[cidx + 4];
                }
        }

        // ---- 3 breadth-first passes: all accs per term (dep distance 16) ----
        #pragma unroll
        for (int nt = 0; nt < 4; nt++)
            #pragma unroll
            for (int w = 0; w < 2; w++)
                if (w < nw)
                    #pragma unroll
                    for (int mt = 0; mt < 2; mt++)
                        mma16(acc[w][mt][nt], ah[mt], bl[nt][w]);
        #pragma unroll
        for (int nt = 0; nt < 4; nt++)
            #pragma unroll
            for (int w = 0; w < 2; w++)
                if (w < nw)
                    #pragma unroll
                    for (int mt = 0; mt < 2; mt++)
                        mma16(acc[w][mt][nt], al[mt], bh[nt][w]);
        #pragma unroll
        for (int nt = 0; nt < 4; nt++)
            #pragma unroll
            for (int w = 0; w < 2; w++)
                if (w < nw)
                    #pragma unroll
                    for (int mt = 0; mt < 2; mt++)
                        mma16(acc[w][mt][nt], ah[mt], bh[nt][w]);
        __syncthreads();
    }

    // Epilogues
    if (isQ) {
        #pragma unroll
        for (int mt = 0; mt < 2; mt++)
            #pragma unroll
            for (int nt = 0; nt < 4; nt++)
                #pragma unroll
                for (int i = 0; i < 4; i++) {
                    int mloc = wm * 32 + mt * 16 + r0 + ((i & 2) ? 8 : 0);
                    int nloc = wn * 32 + nt * 8 + j2 + (i & 1);
                    g_Q[(((size_t)(bn * BATCH + bidx)) * QDIM + t0 + mloc) * HD + nloc] =
                        packsplit(acc[0][mt][nt][i]);
                }
    } else {
        const size_t pb = (size_t)(bn * BATCH + bidx);
        #pragma unroll
        for (int mt = 0; mt < 2; mt++)
            #pragma unroll
            for (int nt = 0; nt < 4; nt++) {
                int grow = t0 + wm * 32 + mt * 16 + r0;
                int dp = wn * 16 + nt * 4 + (lane & 3);
                uint32_t h0, l0, h1, l1;
                psplit2(acc[0][mt][nt][0], acc[0][mt][nt][1], h0, l0);
                psplit2(acc[0][mt][nt][2], acc[0][mt][nt][3], h1, l1);
                size_t kb = (pb * GG + grow) * (HD / 2) + dp;
                g_Kh[kb] = h0; g_Kl[kb] = l0;
                g_Kh[kb + 8 * (HD / 2)] = h1; g_Kl[kb + 8 * (HD / 2)] = l1;
                uint32_t p0 = packsplit(acc[1][mt][nt][0]);
                uint32_t p1 = packsplit(acc[1][mt][nt][1]);
                uint32_t p2 = packsplit(acc[1][mt][nt][2]);
                uint32_t p3 = packsplit(acc[1][mt][nt][3]);
                uint32_t q0 = __shfl_down_sync(0xffffffffu, p0, 4);
                uint32_t q1 = __shfl_down_sync(0xffffffffu, p1, 4);
                uint32_t q2 = __shfl_down_sync(0xffffffffu, p2, 4);
                uint32_t q3 = __shfl_down_sync(0xffffffffu, p3, 4);
                if ((r0 & 1) == 0) {
                    int d0 = wn * 32 + nt * 8 + j2;
                    size_t vb = (pb * (GG / 2) + (grow >> 1)) * HD + d0;
                    g_V2h[vb]     = HI_PAIR(p0, q0); g_V2l[vb]     = LO_PAIR(p0, q0);
                    g_V2h[vb + 1] = HI_PAIR(p1, q1); g_V2l[vb + 1] = LO_PAIR(p1, q1);
                    g_V2h[vb + 4 * HD]     = HI_PAIR(p2, q2); g_V2l[vb + 4 * HD]     = LO_PAIR(p2, q2);
                    g_V2h[vb + 4 * HD + 1] = HI_PAIR(p3, q3); g_V2l[vb + 4 * HD + 1] = LO_PAIR(p3, q3);
                }
            }
    }
}

// ===========================================================================
// Out projection: same breadth-first MMA ordering. 2 blocks/SM (54KB smem).
// ===========================================================================
#define OP_A_U32 (128 * GLD)                       // 1536 per plane
#define OP_B_U32 (64 * GLD)                        // 768 per plane
#define OP_STAGE_U32 (2 * OP_A_U32 + 2 * OP_B_U32) // 4608
#define OP_SMEM (3 * OP_STAGE_U32 * 4)             // 55296

__global__ __launch_bounds__(256, 2)
void oproj_kernel(float* __restrict__ Outp)
{
    extern __shared__ uint32_t dsm[];
    const uint32_t sb = (uint32_t)__cvta_generic_to_shared(dsm);

    const int tid  = threadIdx.x;
    const int lane = tid & 31;
    const int warp = tid >> 5;
    const int wm   = warp >> 1;
    const int wn   = warp & 1;
    const int bm   = blockIdx.y;
    const int bn   = blockIdx.x;
    const int r0 = lane >> 2;
    const int j2 = 2 * (lane & 3);

    const size_t arow = (size_t)bm * 128;
    const size_t brow = (size_t)bn * 64;

    auto prefetch = [&](int st, int c) {
        uint32_t base = sb + st * (OP_STAGE_U32 * 4);
        #pragma unroll
        for (int j = 0; j < 2; j++) {
            int idx = tid + j * 256;
            int p = idx >> 8, rem = idx & 255;
            int row = rem >> 1, seg = rem & 1;
            cpa16(base + p * (OP_A_U32 * 4) + row * (GLD * 4) + seg * 16,
                  (p ? g_Hdl : g_Hdh) + (arow + row) * (DIM / 2) + c * 8 + seg * 4);
        }
        {
            int p = tid >> 7, rem = tid & 127;
            int row = rem >> 1, seg = rem & 1;
            cpa16(base + (2 * OP_A_U32 + p * OP_B_U32) * 4 + row * (GLD * 4) + seg * 16,
                  (p ? g_Wotl : g_Woth) + (brow + row) * (DIM / 2) + c * 8 + seg * 4);
        }
    };

    float acc[2][4][4];
    #pragma unroll
    for (int a = 0; a < 2; a++)
        #pragma unroll
        for (int b = 0; b < 4; b++)
            #pragma unroll
            for (int c = 0; c < 4; c++) acc[a][b][c] = 0.f;

    prefetch(0, 0);
    asm volatile("cp.async.commit_group;");
    prefetch(1, 1);
    asm volatile("cp.async.commit_group;");

    for (int it = 0; it < 32; it++) {
        asm volatile("cp.async.wait_group 1;");
        __syncthreads();
        if (it + 2 < 32) prefetch((it + 2) % 3, it + 2);
        asm volatile("cp.async.commit_group;");

        const uint32_t* Ah = dsm + (it % 3) * OP_STAGE_U32;
        const uint32_t* Al = Ah + OP_A_U32;
        const uint32_t* Bhp = Ah + 2 * OP_A_U32;
        const uint32_t* Blp = Bhp + OP_B_U32;

        uint32_t ah[2][4], al[2][4];
        #pragma unroll
        for (int mt = 0; mt < 2; mt++) {
            int base = (wm * 32 + mt * 16 + r0) * GLD + (lane & 3);
            ah[mt][0] = Ah[base];           al[mt][0] = Al[base];
            ah[mt][1] = Ah[base + 8 * GLD]; al[mt][1] = Al[base + 8 * GLD];
            ah[mt][2] = Ah[base + 4];       al[mt][2] = Al[base + 4];
            ah[mt][3] = Ah[base + 8 * GLD + 4]; al[mt][3] = Al[base + 8 * GLD + 4];
        }
        uint32_t bh[4][2], bl[4][2];
        #pragma unroll
        for (int nt = 0; nt < 4; nt++) {
            int cidx = (wn * 32 + nt * 8 + r0) * GLD + (lane & 3);
            bh[nt][0] = Bhp[cidx]; bh[nt][1] = Bhp[cidx + 4];
            bl[nt][0] = Blp[cidx]; bl[nt][1] = Blp[cidx + 4];
        }

        // 3 breadth-first passes (dep distance 8)
        #pragma unroll
        for (int nt = 0; nt < 4; nt++)
            #pragma unroll
            for (int mt = 0; mt < 2; mt++)
                mma16(acc[mt][nt], ah[mt], bl[nt]);
        #pragma unroll
        for (int nt = 0; nt < 4; nt++)
            #pragma unroll
            for (int mt = 0; mt < 2; mt++)
                mma16(acc[mt][nt], al[mt], bh[nt]);
        #pragma unroll
        for (int nt = 0; nt < 4; nt++)
            #pragma unroll
            for (int mt = 0; mt < 2; mt++)
                mma16(acc[mt][nt], ah[mt], bh[nt]);
        __syncthreads();
    }

    #pragma unroll
    for (int mt = 0; mt < 2; mt++)
        #pragma unroll
        for (int nt = 0; nt < 4; nt++)
            #pragma unroll
            for (int i = 0; i < 4; i++) {
                int mloc = wm * 32 + mt * 16 + r0 + ((i & 2) ? 8 : 0);
                int nloc = wn * 32 + nt * 8 + j2 + (i & 1);
                Outp[(size_t)(bm * 128 + mloc) * DIM + bn * 64 + nloc] = acc[mt][nt][i];
            }
}

// ===========================================================================
// Flash attention: UNCHANGED from round 8 (fault isolation).
// ===========================================================================
#define AK_LD 36
#define AV_LD 72
#define AK_U32 (64 * AK_LD)
#define AV_U32 (32 * AV_LD)
#define ATTN_STAGE_U32 (2 * AK_U32 + 2 * AV_U32)
#define ATTN_SMEM (3 * ATTN_STAGE_U32 * 4)

__global__ __launch_bounds__(256, 2)
void attn_kernel()
{
    extern __shared__ uint32_t dsm[];
    const uint32_t sb = (uint32_t)__cvta_generic_to_shared(dsm);

    const int tid  = threadIdx.x;
    const int lane = tid & 31;
    const int warp = tid >> 5;
    const int qt   = blockIdx.x;
    const int pair = blockIdx.y;
    const int r0 = lane >> 2;
    const int j2 = 2 * (lane & 3);

    const uint32_t* Qp  = g_Q + ((size_t)pair * QDIM + qt * 128 + warp * 16) * HD;
    const size_t kbase = (size_t)pair * GG * (HD / 2);
    const size_t vbase = (size_t)pair * (GG / 2) * HD;

    auto prefetch = [&](int st, int c) {
        uint32_t base = sb + st * (ATTN_STAGE_U32 * 4);
        #pragma unroll
        for (int j = 0; j < 2; j++) {
            int idx = tid + j * 256;
            int row = idx >> 3, seg = idx & 7;
            cpa16(base + row * (AK_LD * 4) + seg * 16,
                  g_Kh + kbase + (size_t)(c * 64 + row) * (HD / 2) + seg * 4);
            cpa16(base + AK_U32 * 4 + row * (AK_LD * 4) + seg * 16,
                  g_Kl + kbase + (size_t)(c * 64 + row) * (HD / 2) + seg * 4);
        }
        #pragma unroll
        for (int j = 0; j < 2; j++) {
            int idx = tid + j * 256;
            int row = idx >> 4, seg = idx & 15;
            cpa16(base + 2 * AK_U32 * 4 + row * (AV_LD * 4) + seg * 16,
                  g_V2h + vbase + (size_t)(c * 32 + row) * HD + seg * 4);
            cpa16(base + (2 * AK_U32 + AV_U32) * 4 + row * (AV_LD * 4) + seg * 16,
                  g_V2l + vbase + (size_t)(c * 32 + row) * HD + seg * 4);
        }
    };

    uint32_t qh[4][4], ql[4][4];
    #pragma unroll
    for (int kk = 0; kk < 4; kk++) {
        int d0 = kk * 16 + j2;
        uint2 w01 = *reinterpret_cast<const uint2*>(Qp + (size_t)r0 * HD + d0);
        uint2 w23 = *reinterpret_cast<const uint2*>(Qp + (size_t)(r0 + 8) * HD + d0);
        uint2 w45 = *reinterpret_cast<const uint2*>(Qp + (size_t)r0 * HD + d0 + 8);
        uint2 w67 = *reinterpret_cast<const uint2*>(Qp + (size_t)(r0 + 8) * HD + d0 + 8);
        qh[kk][0] = h2scale8(HI_PAIR(w01.x, w01.y)); ql[kk][0] = h2scale8(LO_PAIR(w01.x, w01.y));
        qh[kk][1] = h2scale8(HI_PAIR(w23.x, w23.y)); ql[kk][1] = h2scale8(LO_PAIR(w23.x, w23.y));
        qh[kk][2] = h2scale8(HI_PAIR(w45.x, w45.y)); ql[kk][2] = h2scale8(LO_PAIR(w45.x, w45.y));
        qh[kk][3] = h2scale8(HI_PAIR(w67.x, w67.y)); ql[kk][3] = h2scale8(LO_PAIR(w67.x, w67.y));
    }

    float oacc[8][4];
    #pragma unroll
    for (int t = 0; t < 8; t++)
        #pragma unroll
        for (int i = 0; i < 4; i++) oacc[t][i] = 0.f;
    float m0 = -1e30f, m1 = -1e30f, l0 = 0.f, l1 = 0.f;

    prefetch(0, 0);
    asm volatile("cp.async.commit_group;");
    prefetch(1, 1);
    asm volatile("cp.async.commit_group;");

    for (int c = 0; c < NCHUNK; c++) {
        asm volatile("cp.async.wait_group 1;");
        __syncthreads();
        if (c + 2 < NCHUNK) prefetch((c + 2) % 3, c + 2);
        asm volatile("cp.async.commit_group;");

        const uint32_t* Kh = dsm + (c % 3) * ATTN_STAGE_U32;
        const uint32_t* Kl = Kh + AK_U32;
        const uint32_t* Vh = Kh + 2 * AK_U32;
        const uint32_t* Vl = Vh + AV_U32;

        float sacc[8][4];
        #pragma unroll
        for (int t = 0; t < 8; t++)
            #pragma unroll
            for (int i = 0; i < 4; i++) sacc[t][i] = 0.f;

        #pragma unroll
        for (int kk = 0; kk < 4; kk++) {
            #pragma unroll
            for (int nt = 0; nt < 8; nt++) {
                int cidx = (nt * 8 + r0) * AK_LD + kk * 8 + (lane & 3);
                uint32_t bh[2], bl[2];
                bh[0] = Kh[cidx]; bh[1] = Kh[cidx + 4];
                bl[0] = Kl[cidx]; bl[1] = Kl[cidx + 4];
                mma3(sacc[nt], qh[kk], ql[kk], bh, bl);
            }
        }

        float mx0 = -1e30f, mx1 = -1e30f;
        #pragma unroll
        for (int t = 0; t < 8; t++) {
            mx0 = fmaxf(mx0, fmaxf(sacc[t][0], sacc[t][1]));
            mx1 = fmaxf(mx1, fmaxf(sacc[t][2], sacc[t][3]));
        }
        mx0 = fmaxf(mx0, __shfl_xor_sync(0xffffffffu, mx0, 1));
        mx0 = fmaxf(mx0, __shfl_xor_sync(0xffffffffu, mx0, 2));
        mx1 = fmaxf(mx1, __shfl_xor_sync(0xffffffffu, mx1, 1));
        mx1 = fmaxf(mx1, __shfl_xor_sync(0xffffffffu, mx1, 2));

        float mn0 = fmaxf(m0, mx0), mn1 = fmaxf(m1, mx1);
        float al0 = __expf(m0 - mn0), al1 = __expf(m1 - mn1);
        float s0 = 0.f, s1 = 0.f;
        #pragma unroll
        for (int t = 0; t < 8; t++) {
            sacc[t][0] = __expf(sacc[t][0] - mn0);
            sacc[t][1] = __expf(sacc[t][1] - mn0);
            sacc[t][2] = __expf(sacc[t][2] - mn1);
            sacc[t][3] = __expf(sacc[t][3] - mn1);
            s0 += sacc[t][0] + sacc[t][1];
            s1 += sacc[t][2] + sacc[t][3];
        }
        s0 += __shfl_xor_sync(0xffffffffu, s0, 1);
        s0 += __shfl_xor_sync(0xffffffffu, s0, 2);
        s1 += __shfl_xor_sync(0xffffffffu, s1, 1);
        s1 += __shfl_xor_sync(0xffffffffu, s1, 2);
        l0 = l0 * al0 + s0;
        l1 = l1 * al1 + s1;
        m0 = mn0; m1 = mn1;
        #pragma unroll
        for (int nt = 0; nt < 8; nt++) {
            oacc[nt][0] *= al0; oacc[nt][1] *= al0;
            oacc[nt][2] *= al1; oacc[nt][3] *= al1;
        }

        #pragma unroll
        for (int kk = 0; kk < 4; kk++) {
            uint32_t pah[4], pal[4];
            psplit2(sacc[2 * kk][0],     sacc[2 * kk][1],     pah[0], pal[0]);
            psplit2(sacc[2 * kk][2],     sacc[2 * kk][3],     pah[1], pal[1]);
            psplit2(sacc[2 * kk + 1][0], sacc[2 * kk + 1][1], pah[2], pal[2]);
            psplit2(sacc[2 * kk + 1][2], sacc[2 * kk + 1][3], pah[3], pal[3]);
            int gp = kk * 8 + (lane & 3);
            #pragma unroll
            for (int nt = 0; nt < 8; nt++) {
                int d = nt * 8 + r0;
                uint32_t bh[2], bl[2];
                bh[0] = Vh[gp * AV_LD + d]; bh[1] = Vh[(gp + 4) * AV_LD + d];
                bl[0] = Vl[gp * AV_LD + d]; bl[1] = Vl[(gp + 4) * AV_LD + d];
                mma3(oacc[nt], pah, pal, bh, bl);
            }
        }
    }

    float inv0 = 1.f / l0, inv1 = 1.f / l1;
    int h = pair >> 3, b = pair & 7;
    #pragma unroll
    for (int nt = 0; nt < 8; nt++) {
        int q = qt * 128 + warp * 16 + r0;
        int dp = h * 32 + nt * 4 + (lane & 3);
        uint32_t h0, l0u, h1, l1u;
        psplit2(oacc[nt][0] * inv0, oacc[nt][1] * inv0, h0, l0u);
        psplit2(oacc[nt][2] * inv1, oacc[nt][3] * inv1, h1, l1u);
        size_t o = ((size_t)(b * QDIM + q)) * (DIM / 2) + dp;
        g_Hdh[o] = h0; g_Hdl[o] = l0u;
        g_Hdh[o + 8 * (DIM / 2)] = h1; g_Hdl[o + 8 * (DIM / 2)] = l1u;
    }
}

extern "C" void kernel_launch(void* const* d_in, const int* in_sizes, int n_in,
                              void* d_out, int out_size)
{
    (void)in_sizes; (void)n_in; (void)out_size;
    const float* q  = (const float*)d_in[0];
    const float* Wq = (const float*)d_in[1];
    const float* Wk = (const float*)d_in[2];
    const float* Wv = (const float*)d_in[3];
    const float* Wo = (const float*)d_in[4];
    float* out = (float*)d_out;

    static bool attrs_set = false;
    if (!attrs_set) {
        cudaFuncSetAttribute(qkv_kernel,   cudaFuncAttributeMaxDynamicSharedMemorySize, QKV_SMEM);
        cudaFuncSetAttribute(attn_kernel,  cudaFuncAttributeMaxDynamicSharedMemorySize, ATTN_SMEM);
        cudaFuncSetAttribute(oproj_kernel, cudaFuncAttributeMaxDynamicSharedMemorySize, OP_SMEM);
        attrs_set = true;
    }

    splitx_kernel<<<16384, 256>>>(q);
    splitw_qkv_kernel<<<1536, 256>>>(Wq, Wk, Wv);
    splitw_o_kernel<<<512, 256>>>(Wo);
    qkv_kernel<<<dim3(8, 256), 256, QKV_SMEM>>>();
    attn_kernel<<<dim3(4, 64), 256, ATTN_SMEM>>>();
    oproj_kernel<<<dim3(8, 32), 256, OP_SMEM>>>(out);
}

// round 12
// speedup vs baseline: 1.1857x; 1.0871x over previous
#include <cuda_runtime.h>
#include <cuda_fp16.h>
#include <cstdint>

#define BATCH 8
#define TT    4096
#define DIM   512
#define NH    8
#define HD    64
#define QDIM  512
#define GG    3584
#define NCHUNK 56

// ---- global scratch (u32 = half2 of adjacent elements of ONE plane) ----
__device__ __align__(256) uint32_t g_Q  [(size_t)NH*BATCH*QDIM*HD];        // packed (hi|lo) per element
__device__ __align__(256) uint32_t g_Kh [(size_t)NH*BATCH*GG*(HD/2)];      // [pair][g][dpair]
__device__ __align__(256) uint32_t g_Kl [(size_t)NH*BATCH*GG*(HD/2)];
__device__ __align__(256) uint32_t g_V2h[(size_t)NH*BATCH*(GG/2)*HD];      // [pair][gpair][d]
__device__ __align__(256) uint32_t g_V2l[(size_t)NH*BATCH*(GG/2)*HD];
__device__ __align__(256) uint32_t g_Hdh[(size_t)BATCH*QDIM*(DIM/2)];      // [b][q][epair]
__device__ __align__(256) uint32_t g_Hdl[(size_t)BATCH*QDIM*(DIM/2)];
__device__ __align__(256) uint32_t g_Xh [(size_t)BATCH*TT*(DIM/2)];        // [b][t][kpair]
__device__ __align__(256) uint32_t g_Xl [(size_t)BATCH*TT*(DIM/2)];
__device__ __align__(256) uint32_t g_Wth[(size_t)3*NH*HD*(DIM/2)];         // [w][h][n][kpair]
__device__ __align__(256) uint32_t g_Wtl[(size_t)3*NH*HD*(DIM/2)];
__device__ __align__(256) uint32_t g_Woth[(size_t)DIM*(DIM/2)];            // [n][kpair]
__device__ __align__(256) uint32_t g_Wotl[(size_t)DIM*(DIM/2)];

__device__ __forceinline__ uint32_t packsplit(float v) {
    __half h = __float2half_rn(v);
    __half l = __float2half_rn(v - __half2float(h));
    return (uint32_t)__half_as_ushort(h) | ((uint32_t)__half_as_ushort(l) << 16);
}
__device__ __forceinline__ void psplit2(float p0, float p1, uint32_t& hi, uint32_t& lo) {
    __half2 h = __floats2half2_rn(p0, p1);
    float2 hf = __half22float2(h);
    __half2 l = __floats2half2_rn(p0 - hf.x, p1 - hf.y);
    hi = *reinterpret_cast<uint32_t*>(&h);
    lo = *reinterpret_cast<uint32_t*>(&l);
}
__device__ __forceinline__ uint32_t h2scale8(uint32_t a) {   // *=0.125 exact
    __half2 s = __float2half2_rn(0.125f);
    __half2 r = __hmul2(*reinterpret_cast<__half2*>(&a), s);
    return *reinterpret_cast<uint32_t*>(&r);
}
#define HI_PAIR(v0, v1) __byte_perm((v0), (v1), 0x5410)
#define LO_PAIR(v0, v1) __byte_perm((v0), (v1), 0x7632)

__device__ __forceinline__ void mma16(float* c, const uint32_t* a, const uint32_t* b) {
    asm volatile(
        "mma.sync.aligned.m16n8k16.row.col.f32.f16.f16.f32 "
        "{%0,%1,%2,%3},{%4,%5,%6,%7},{%8,%9},{%0,%1,%2,%3};"
        : "+f"(c[0]), "+f"(c[1]), "+f"(c[2]), "+f"(c[3])
        : "r"(a[0]), "r"(a[1]), "r"(a[2]), "r"(a[3]), "r"(b[0]), "r"(b[1]));
}
__device__ __forceinline__ void mma3(float* c, const uint32_t* ah, const uint32_t* al,
                                     const uint32_t* bh, const uint32_t* bl) {
    mma16(c, ah, bl);
    mma16(c, al, bh);
    mma16(c, ah, bh);
}
__device__ __forceinline__ void cpa16(uint32_t dst, const void* src) {
    asm volatile("cp.async.cg.shared.global [%0], [%1], 16;" :: "r"(dst), "l"(src));
}

// ===========================================================================
// Prep kernels: split inputs into hi/lo half planes (transposed weights)
// ===========================================================================
__global__ __launch_bounds__(256) void splitx_kernel(const float* __restrict__ X) {
    int i = blockIdx.x * 256 + threadIdx.x;              // per float4
    float4 v = reinterpret_cast<const float4*>(X)[i];
    uint32_t h0, l0, h1, l1;
    psplit2(v.x, v.y, h0, l0);
    psplit2(v.z, v.w, h1, l1);
    g_Xh[2 * i] = h0; g_Xh[2 * i + 1] = h1;
    g_Xl[2 * i] = l0; g_Xl[2 * i + 1] = l1;
}
__global__ __launch_bounds__(256) void splitw_qkv_kernel(const float* __restrict__ Wq,
                                                         const float* __restrict__ Wk,
                                                         const float* __restrict__ Wv) {
    int idx = blockIdx.x * 256 + threadIdx.x;   // [w][h][n][kpair] flattened
    int kp = idx & 255, n = (idx >> 8) & 63, h = (idx >> 14) & 7, w = idx >> 17;
    const float* W = (w == 0) ? Wq : (w == 1) ? Wk : Wv;
    const float* b = W + ((size_t)h * DIM + 2 * kp) * HD + n;
    uint32_t hi, lo;
    psplit2(b[0], b[HD], hi, lo);
    g_Wth[idx] = hi; g_Wtl[idx] = lo;
}
__global__ __launch_bounds__(256) void splitw_o_kernel(const float* __restrict__ Wo) {
    int idx = blockIdx.x * 256 + threadIdx.x;   // [n][kpair]
    int kp = idx & 255, n = idx >> 8;
    const float* b = Wo + (size_t)(2 * kp) * DIM + n;
    uint32_t hi, lo;
    psplit2(b[0], b[DIM], hi, lo);
    g_Woth[idx] = hi; g_Wotl[idx] = lo;
}

// ===========================================================================
// QKV projection: K-chunk 32 halfs, 2-stage double buffer, 16 iters,
// ONE barrier per iteration. 256 thr, 8 warps (4M x 2N), warp 32x32/weight.
// grid (8 heads, 256): bm<224 -> K+V tiles, bm>=224 -> Q tiles.
// ===========================================================================
#define GLD 20                                     // 16 data u32 + 4 pad
#define QKV_A_U32 (128 * GLD)                      // 2560 per plane
#define QKV_B_U32 (64 * GLD)                       // 1280 per plane per weight
#define QKV_STAGE_U32 (2 * QKV_A_U32 + 4 * QKV_B_U32) // 10240
#define QKV_SMEM (2 * QKV_STAGE_U32 * 4)           // 81920

__global__ __launch_bounds__(256, 2)
void qkv_kernel()
{
    extern __shared__ uint32_t dsm[];
    const uint32_t sb = (uint32_t)__cvta_generic_to_shared(dsm);

    const int tid  = threadIdx.x;
    const int lane = tid & 31;
    const int warp = tid >> 5;
    const int wm   = warp >> 1;      // 0..3
    const int wn   = warp & 1;       // 0..1
    const int bn   = blockIdx.x;     // head
    const int bm   = blockIdx.y;     // 0..255
    const bool isQ = bm >= 224;
    const int r0 = lane >> 2;
    const int j2 = 2 * (lane & 3);

    int bidx, t0, rowoff, w0sel, w1sel;
    if (isQ) {
        int qbm = bm - 224;
        bidx = qbm >> 2; t0 = (qbm & 3) * 128; rowoff = 0; w0sel = 0; w1sel = 0;
    } else {
        bidx = bm / 28; t0 = (bm % 28) * 128; rowoff = QDIM; w0sel = 1; w1sel = 2;
    }
    const int nw = isQ ? 1 : 2;

    const uint32_t* Xhp = g_Xh + ((size_t)bidx * TT + rowoff + t0) * (DIM / 2);
    const uint32_t* Xlp = g_Xl + ((size_t)bidx * TT + rowoff + t0) * (DIM / 2);
    const size_t wb0 = ((size_t)(w0sel * NH + bn)) * HD * (DIM / 2);
    const size_t wb1 = ((size_t)(w1sel * NH + bn)) * HD * (DIM / 2);

    auto prefetch = [&](int st, int c) {
        uint32_t base = sb + st * (QKV_STAGE_U32 * 4);
        #pragma unroll
        for (int j = 0; j < 4; j++) {      // A: 2 planes x 128 rows x 4 segs = 1024
            int idx = tid + j * 256;
            int p = idx >> 9, rem = idx & 511;
            int row = rem >> 2, seg = rem & 3;
            cpa16(base + p * (QKV_A_U32 * 4) + row * (GLD * 4) + seg * 16,
                  (p ? Xlp : Xhp) + (size_t)row * (DIM / 2) + c * 16 + seg * 4);
        }
        #pragma unroll
        for (int j = 0; j < 4; j++) {      // B: 2w x 2p x 64 rows x 4 segs = 1024
            int idx = tid + j * 256;
            int w = idx >> 9, rem = idx & 511;
            int p = rem >> 8, r2 = rem & 255;
            int row = r2 >> 2, seg = r2 & 3;
            if (w < nw) {
                const uint32_t* src = (p ? g_Wtl : g_Wth) + (w ? wb1 : wb0)
                                      + (size_t)row * (DIM / 2) + c * 16 + seg * 4;
                cpa16(base + (2 * QKV_A_U32 + (w * 2 + p) * QKV_B_U32) * 4
                           + row * (GLD * 4) + seg * 16, src);
            }
        }
    };

    float acc[2][2][4][4];     // [w][mt][nt][i]
    #pragma unroll
    for (int w = 0; w < 2; w++)
        #pragma unroll
        for (int a = 0; a < 2; a++)
            #pragma unroll
            for (int b = 0; b < 4; b++)
                #pragma unroll
                for (int c = 0; c < 4; c++) acc[w][a][b][c] = 0.f;

    prefetch(0, 0);
    asm volatile("cp.async.commit_group;");

    for (int it = 0; it < 16; it++) {
        const int cur = it & 1;
        asm volatile("cp.async.wait_group 0;");
        __syncthreads();
        if (it + 1 < 16) prefetch(cur ^ 1, it + 1);
        asm volatile("cp.async.commit_group;");

        const uint32_t* Ah = dsm + cur * QKV_STAGE_U32;
        const uint32_t* Al = Ah + QKV_A_U32;
        const uint32_t* Bb = Ah + 2 * QKV_A_U32;

        #pragma unroll
        for (int kk = 0; kk < 2; kk++) {
            uint32_t ah[2][4], al[2][4];
            #pragma unroll
            for (int mt = 0; mt < 2; mt++) {
                int base = (wm * 32 + mt * 16 + r0) * GLD + kk * 8 + (lane & 3);
                ah[mt][0] = Ah[base];           al[mt][0] = Al[base];
                ah[mt][1] = Ah[base + 8 * GLD]; al[mt][1] = Al[base + 8 * GLD];
                ah[mt][2] = Ah[base + 4];       al[mt][2] = Al[base + 4];
                ah[mt][3] = Ah[base + 8 * GLD + 4]; al[mt][3] = Al[base + 8 * GLD + 4];
            }
            uint32_t bh[4][2][2], bl[4][2][2];   // [nt][w][2]
            #pragma unroll
            for (int nt = 0; nt < 4; nt++) {
                int cidx = (wn * 32 + nt * 8 + r0) * GLD + kk * 8 + (lane & 3);
                #pragma unroll
                for (int w = 0; w < 2; w++)
                    if (w < nw) {
                        const uint32_t* Bh = Bb + (w * 2 + 0) * QKV_B_U32;
                        const uint32_t* Bl = Bb + (w * 2 + 1) * QKV_B_U32;
                        bh[nt][w][0] = Bh[cidx]; bh[nt][w][1] = Bh[cidx + 4];
                        bl[nt][w][0] = Bl[cidx]; bl[nt][w][1] = Bl[cidx + 4];
                    }
            }
            // 3 breadth-first passes (dep distance 16)
            #pragma unroll
            for (int nt = 0; nt < 4; nt++)
                #pragma unroll
                for (int w = 0; w < 2; w++)
                    if (w < nw)
                        #pragma unroll
                        for (int mt = 0; mt < 2; mt++)
                            mma16(acc[w][mt][nt], ah[mt], bl[nt][w]);
            #pragma unroll
            for (int nt = 0; nt < 4; nt++)
                #pragma unroll
                for (int w = 0; w < 2; w++)
                    if (w < nw)
                        #pragma unroll
                        for (int mt = 0; mt < 2; mt++)
                            mma16(acc[w][mt][nt], al[mt], bh[nt][w]);
            #pragma unroll
            for (int nt = 0; nt < 4; nt++)
                #pragma unroll
                for (int w = 0; w < 2; w++)
                    if (w < nw)
                        #pragma unroll
                        for (int mt = 0; mt < 2; mt++)
                            mma16(acc[w][mt][nt], ah[mt], bh[nt][w]);
        }
    }

    // Epilogues
    if (isQ) {
        #pragma unroll
        for (int mt = 0; mt < 2; mt++)
            #pragma unroll
            for (int nt = 0; nt < 4; nt++)
                #pragma unroll
                for (int i = 0; i < 4; i++) {
                    int mloc = wm * 32 + mt * 16 + r0 + ((i & 2) ? 8 : 0);
                    int nloc = wn * 32 + nt * 8 + j2 + (i & 1);
                    g_Q[(((size_t)(bn * BATCH + bidx)) * QDIM + t0 + mloc) * HD + nloc] =
                        packsplit(acc[0][mt][nt][i]);
                }
    } else {
        const size_t pb = (size_t)(bn * BATCH + bidx);
        #pragma unroll
        for (int mt = 0; mt < 2; mt++)
            #pragma unroll
            for (int nt = 0; nt < 4; nt++) {
                int grow = t0 + wm * 32 + mt * 16 + r0;
                int dp = wn * 16 + nt * 4 + (lane & 3);
                uint32_t h0, l0, h1, l1;
                psplit2(acc[0][mt][nt][0], acc[0][mt][nt][1], h0, l0);
                psplit2(acc[0][mt][nt][2], acc[0][mt][nt][3], h1, l1);
                size_t kb = (pb * GG + grow) * (HD / 2) + dp;
                g_Kh[kb] = h0; g_Kl[kb] = l0;
                g_Kh[kb + 8 * (HD / 2)] = h1; g_Kl[kb + 8 * (HD / 2)] = l1;
                uint32_t p0 = packsplit(acc[1][mt][nt][0]);
                uint32_t p1 = packsplit(acc[1][mt][nt][1]);
                uint32_t p2 = packsplit(acc[1][mt][nt][2]);
                uint32_t p3 = packsplit(acc[1][mt][nt][3]);
                uint32_t q0 = __shfl_down_sync(0xffffffffu, p0, 4);
                uint32_t q1 = __shfl_down_sync(0xffffffffu, p1, 4);
                uint32_t q2 = __shfl_down_sync(0xffffffffu, p2, 4);
                uint32_t q3 = __shfl_down_sync(0xffffffffu, p3, 4);
                if ((r0 & 1) == 0) {
                    int d0 = wn * 32 + nt * 8 + j2;
                    size_t vb = (pb * (GG / 2) + (grow >> 1)) * HD + d0;
                    g_V2h[vb]     = HI_PAIR(p0, q0); g_V2l[vb]     = LO_PAIR(p0, q0);
                    g_V2h[vb + 1] = HI_PAIR(p1, q1); g_V2l[vb + 1] = LO_PAIR(p1, q1);
                    g_V2h[vb + 4 * HD]     = HI_PAIR(p2, q2); g_V2l[vb + 4 * HD]     = LO_PAIR(p2, q2);
                    g_V2h[vb + 4 * HD + 1] = HI_PAIR(p3, q3); g_V2l[vb + 4 * HD + 1] = LO_PAIR(p3, q3);
                }
            }
    }
}

// ===========================================================================
// Out projection: K-chunk 32, 2-stage, 16 iters, 1 bar/iter. 60KB smem.
// ===========================================================================
#define OP_A_U32 (128 * GLD)                       // 2560 per plane
#define OP_B_U32 (64 * GLD)                        // 1280 per plane
#define OP_STAGE_U32 (2 * OP_A_U32 + 2 * OP_B_U32) // 7680
#define OP_SMEM (2 * OP_STAGE_U32 * 4)             // 61440

__global__ __launch_bounds__(256, 2)
void oproj_kernel(float* __restrict__ Outp)
{
    extern __shared__ uint32_t dsm[];
    const uint32_t sb = (uint32_t)__cvta_generic_to_shared(dsm);

    const int tid  = threadIdx.x;
    const int lane = tid & 31;
    const int warp = tid >> 5;
    const int wm   = warp >> 1;
    const int wn   = warp & 1;
    const int bm   = blockIdx.y;
    const int bn   = blockIdx.x;
    const int r0 = lane >> 2;
    const int j2 = 2 * (lane & 3);

    const size_t arow = (size_t)bm * 128;
    const size_t brow = (size_t)bn * 64;

    auto prefetch = [&](int st, int c) {
        uint32_t base = sb + st * (OP_STAGE_U32 * 4);
        #pragma unroll
        for (int j = 0; j < 4; j++) {      // A: 2 planes x 128 rows x 4 segs
            int idx = tid + j * 256;
            int p = idx >> 9, rem = idx & 511;
            int row = rem >> 2, seg = rem & 3;
            cpa16(base + p * (OP_A_U32 * 4) + row * (GLD * 4) + seg * 16,
                  (p ? g_Hdl : g_Hdh) + (arow + row) * (DIM / 2) + c * 16 + seg * 4);
        }
        #pragma unroll
        for (int j = 0; j < 2; j++) {      // B: 2 planes x 64 rows x 4 segs
            int idx = tid + j * 256;
            int p = idx >> 8, rem = idx & 255;
            int row = rem >> 2, seg = rem & 3;
            cpa16(base + (2 * OP_A_U32 + p * OP_B_U32) * 4 + row * (GLD * 4) + seg * 16,
                  (p ? g_Wotl : g_Woth) + (brow + row) * (DIM / 2) + c * 16 + seg * 4);
        }
    };

    float acc[2][4][4];
    #pragma unroll
    for (int a = 0; a < 2; a++)
        #pragma unroll
        for (int b = 0; b < 4; b++)
            #pragma unroll
            for (int c = 0; c < 4; c++) acc[a][b][c] = 0.f;

    prefetch(0, 0);
    asm volatile("cp.async.commit_group;");

    for (int it = 0; it < 16; it++) {
        const int cur = it & 1;
        asm volatile("cp.async.wait_group 0;");
        __syncthreads();
        if (it + 1 < 16) prefetch(cur ^ 1, it + 1);
        asm volatile("cp.async.commit_group;");

        const uint32_t* Ah = dsm + cur * OP_STAGE_U32;
        const uint32_t* Al = Ah + OP_A_U32;
        const uint32_t* Bhp = Ah + 2 * OP_A_U32;
        const uint32_t* Blp = Bhp + OP_B_U32;

        #pragma unroll
        for (int kk = 0; kk < 2; kk++) {
            uint32_t ah[2][4], al[2][4];
            #pragma unroll
            for (int mt = 0; mt < 2; mt++) {
                int base = (wm * 32 + mt * 16 + r0) * GLD + kk * 8 + (lane & 3);
                ah[mt][0] = Ah[base];           al[mt][0] = Al[base];
                ah[mt][1] = Ah[base + 8 * GLD]; al[mt][1] = Al[base + 8 * GLD];
                ah[mt][2] = Ah[base + 4];       al[mt][2] = Al[base + 4];
                ah[mt][3] = Ah[base + 8 * GLD + 4]; al[mt][3] = Al[base + 8 * GLD + 4];
            }
            uint32_t bh[4][2], bl[4][2];
            #pragma unroll
            for (int nt = 0; nt < 4; nt++) {
                int cidx = (wn * 32 + nt * 8 + r0) * GLD + kk * 8 + (lane & 3);
                bh[nt][0] = Bhp[cidx]; bh[nt][1] = Bhp[cidx + 4];
                bl[nt][0] = Blp[cidx]; bl[nt][1] = Blp[cidx + 4];
            }
            #pragma unroll
            for (int nt = 0; nt < 4; nt++)
                #pragma unroll
                for (int mt = 0; mt < 2; mt++)
                    mma16(acc[mt][nt], ah[mt], bl[nt]);
            #pragma unroll
            for (int nt = 0; nt < 4; nt++)
                #pragma unroll
                for (int mt = 0; mt < 2; mt++)
                    mma16(acc[mt][nt], al[mt], bh[nt]);
            #pragma unroll
            for (int nt = 0; nt < 4; nt++)
                #pragma unroll
                for (int mt = 0; mt < 2; mt++)
                    mma16(acc[mt][nt], ah[mt], bh[nt]);
        }
    }

    #pragma unroll
    for (int mt = 0; mt < 2; mt++)
        #pragma unroll
        for (int nt = 0; nt < 4; nt++)
            #pragma unroll
            for (int i = 0; i < 4; i++) {
                int mloc = wm * 32 + mt * 16 + r0 + ((i & 2) ? 8 : 0);
                int nloc = wn * 32 + nt * 8 + j2 + (i & 1);
                Outp[(size_t)(bm * 128 + mloc) * DIM + bn * 64 + nloc] = acc[mt][nt][i];
            }
}

// ===========================================================================
// Flash attention: UNCHANGED from round 8/11 (fault isolation).
// ===========================================================================
#define AK_LD 36
#define AV_LD 72
#define AK_U32 (64 * AK_LD)
#define AV_U32 (32 * AV_LD)
#define ATTN_STAGE_U32 (2 * AK_U32 + 2 * AV_U32)
#define ATTN_SMEM (3 * ATTN_STAGE_U32 * 4)

__global__ __launch_bounds__(256, 2)
void attn_kernel()
{
    extern __shared__ uint32_t dsm[];
    const uint32_t sb = (uint32_t)__cvta_generic_to_shared(dsm);

    const int tid  = threadIdx.x;
    const int lane = tid & 31;
    const int warp = tid >> 5;
    const int qt   = blockIdx.x;
    const int pair = blockIdx.y;
    const int r0 = lane >> 2;
    const int j2 = 2 * (lane & 3);

    const uint32_t* Qp  = g_Q + ((size_t)pair * QDIM + qt * 128 + warp * 16) * HD;
    const size_t kbase = (size_t)pair * GG * (HD / 2);
    const size_t vbase = (size_t)pair * (GG / 2) * HD;

    auto prefetch = [&](int st, int c) {
        uint32_t base = sb + st * (ATTN_STAGE_U32 * 4);
        #pragma unroll
        for (int j = 0; j < 2; j++) {
            int idx = tid + j * 256;
            int row = idx >> 3, seg = idx & 7;
            cpa16(base + row * (AK_LD * 4) + seg * 16,
                  g_Kh + kbase + (size_t)(c * 64 + row) * (HD / 2) + seg * 4);
            cpa16(base + AK_U32 * 4 + row * (AK_LD * 4) + seg * 16,
                  g_Kl + kbase + (size_t)(c * 64 + row) * (HD / 2) + seg * 4);
        }
        #pragma unroll
        for (int j = 0; j < 2; j++) {
            int idx = tid + j * 256;
            int row = idx >> 4, seg = idx & 15;
            cpa16(base + 2 * AK_U32 * 4 + row * (AV_LD * 4) + seg * 16,
                  g_V2h + vbase + (size_t)(c * 32 + row) * HD + seg * 4);
            cpa16(base + (2 * AK_U32 + AV_U32) * 4 + row * (AV_LD * 4) + seg * 16,
                  g_V2l + vbase + (size_t)(c * 32 + row) * HD + seg * 4);
        }
    };

    uint32_t qh[4][4], ql[4][4];
    #pragma unroll
    for (int kk = 0; kk < 4; kk++) {
        int d0 = kk * 16 + j2;
        uint2 w01 = *reinterpret_cast<const uint2*>(Qp + (size_t)r0 * HD + d0);
        uint2 w23 = *reinterpret_cast<const uint2*>(Qp + (size_t)(r0 + 8) * HD + d0);
        uint2 w45 = *reinterpret_cast<const uint2*>(Qp + (size_t)r0 * HD + d0 + 8);
        uint2 w67 = *reinterpret_cast<const uint2*>(Qp + (size_t)(r0 + 8) * HD + d0 + 8);
        qh[kk][0] = h2scale8(HI_PAIR(w01.x, w01.y)); ql[kk][0] = h2scale8(LO_PAIR(w01.x, w01.y));
        qh[kk][1] = h2scale8(HI_PAIR(w23.x, w23.y)); ql[kk][1] = h2scale8(LO_PAIR(w23.x, w23.y));
        qh[kk][2] = h2scale8(HI_PAIR(w45.x, w45.y)); ql[kk][2] = h2scale8(LO_PAIR(w45.x, w45.y));
        qh[kk][3] = h2scale8(HI_PAIR(w67.x, w67.y)); ql[kk][3] = h2scale8(LO_PAIR(w67.x, w67.y));
    }

    float oacc[8][4];
    #pragma unroll
    for (int t = 0; t < 8; t++)
        #pragma unroll
        for (int i = 0; i < 4; i++) oacc[t][i] = 0.f;
    float m0 = -1e30f, m1 = -1e30f, l0 = 0.f, l1 = 0.f;

    prefetch(0, 0);
    asm volatile("cp.async.commit_group;");
    prefetch(1, 1);
    asm volatile("cp.async.commit_group;");

    for (int c = 0; c < NCHUNK; c++) {
        asm volatile("cp.async.wait_group 1;");
        __syncthreads();
        if (c + 2 < NCHUNK) prefetch((c + 2) % 3, c + 2);
        asm volatile("cp.async.commit_group;");

        const uint32_t* Kh = dsm + (c % 3) * ATTN_STAGE_U32;
        const uint32_t* Kl = Kh + AK_U32;
        const uint32_t* Vh = Kh + 2 * AK_U32;
        const uint32_t* Vl = Vh + AV_U32;

        float sacc[8][4];
        #pragma unroll
        for (int t = 0; t < 8; t++)
            #pragma unroll
            for (int i = 0; i < 4; i++) sacc[t][i] = 0.f;

        #pragma unroll
        for (int kk = 0; kk < 4; kk++) {
            #pragma unroll
            for (int nt = 0; nt < 8; nt++) {
                int cidx = (nt * 8 + r0) * AK_LD + kk * 8 + (lane & 3);
                uint32_t bh[2], bl[2];
                bh[0] = Kh[cidx]; bh[1] = Kh[cidx + 4];
                bl[0] = Kl[cidx]; bl[1] = Kl[cidx + 4];
                mma3(sacc[nt], qh[kk], ql[kk], bh, bl);
            }
        }

        float mx0 = -1e30f, mx1 = -1e30f;
        #pragma unroll
        for (int t = 0; t < 8; t++) {
            mx0 = fmaxf(mx0, fmaxf(sacc[t][0], sacc[t][1]));
            mx1 = fmaxf(mx1, fmaxf(sacc[t][2], sacc[t][3]));
        }
        mx0 = fmaxf(mx0, __shfl_xor_sync(0xffffffffu, mx0, 1));
        mx0 = fmaxf(mx0, __shfl_xor_sync(0xffffffffu, mx0, 2));
        mx1 = fmaxf(mx1, __shfl_xor_sync(0xffffffffu, mx1, 1));
        mx1 = fmaxf(mx1, __shfl_xor_sync(0xffffffffu, mx1, 2));

        float mn0 = fmaxf(m0, mx0), mn1 = fmaxf(m1, mx1);
        float al0 = __expf(m0 - mn0), al1 = __expf(m1 - mn1);
        float s0 = 0.f, s1 = 0.f;
        #pragma unroll
        for (int t = 0; t < 8; t++) {
            sacc[t][0] = __expf(sacc[t][0] - mn0);
            sacc[t][1] = __expf(sacc[t][1] - mn0);
            sacc[t][2] = __expf(sacc[t][2] - mn1);
            sacc[t][3] = __expf(sacc[t][3] - mn1);
            s0 += sacc[t][0] + sacc[t][1];
            s1 += sacc[t][2] + sacc[t][3];
        }
        s0 += __shfl_xor_sync(0xffffffffu, s0, 1);
        s0 += __shfl_xor_sync(0xffffffffu, s0, 2);
        s1 += __shfl_xor_sync(0xffffffffu, s1, 1);
        s1 += __shfl_xor_sync(0xffffffffu, s1, 2);
        l0 = l0 * al0 + s0;
        l1 = l1 * al1 + s1;
        m0 = mn0; m1 = mn1;
        #pragma unroll
        for (int nt = 0; nt < 8; nt++) {
            oacc[nt][0] *= al0; oacc[nt][1] *= al0;
            oacc[nt][2] *= al1; oacc[nt][3] *= al1;
        }

        #pragma unroll
        for (int kk = 0; kk < 4; kk++) {
            uint32_t pah[4], pal[4];
            psplit2(sacc[2 * kk][0],     sacc[2 * kk][1],     pah[0], pal[0]);
            psplit2(sacc[2 * kk][2],     sacc[2 * kk][3],     pah[1], pal[1]);
            psplit2(sacc[2 * kk + 1][0], sacc[2 * kk + 1][1], pah[2], pal[2]);
            psplit2(sacc[2 * kk + 1][2], sacc[2 * kk + 1][3], pah[3], pal[3]);
            int gp = kk * 8 + (lane & 3);
            #pragma unroll
            for (int nt = 0; nt < 8; nt++) {
                int d = nt * 8 + r0;
                uint32_t bh[2], bl[2];
                bh[0] = Vh[gp * AV_LD + d]; bh[1] = Vh[(gp + 4) * AV_LD + d];
                bl[0] = Vl[gp * AV_LD + d]; bl[1] = Vl[(gp + 4) * AV_LD + d];
                mma3(oacc[nt], pah, pal, bh, bl);
            }
        }
    }

    float inv0 = 1.f / l0, inv1 = 1.f / l1;
    int h = pair >> 3, b = pair & 7;
    #pragma unroll
    for (int nt = 0; nt < 8; nt++) {
        int q = qt * 128 + warp * 16 + r0;
        int dp = h * 32 + nt * 4 + (lane & 3);
        uint32_t h0, l0u, h1, l1u;
        psplit2(oacc[nt][0] * inv0, oacc[nt][1] * inv0, h0, l0u);
        psplit2(oacc[nt][2] * inv1, oacc[nt][3] * inv1, h1, l1u);
        size_t o = ((size_t)(b * QDIM + q)) * (DIM / 2) + dp;
        g_Hdh[o] = h0; g_Hdl[o] = l0u;
        g_Hdh[o + 8 * (DIM / 2)] = h1; g_Hdl[o + 8 * (DIM / 2)] = l1u;
    }
}

extern "C" void kernel_launch(void* const* d_in, const int* in_sizes, int n_in,
                              void* d_out, int out_size)
{
    (void)in_sizes; (void)n_in; (void)out_size;
    const float* q  = (const float*)d_in[0];
    const float* Wq = (const float*)d_in[1];
    const float* Wk = (const float*)d_in[2];
    const float* Wv = (const float*)d_in[3];
    const float* Wo = (const float*)d_in[4];
    float* out = (float*)d_out;

    static bool attrs_set = false;
    if (!attrs_set) {
        cudaFuncSetAttribute(qkv_kernel,   cudaFuncAttributeMaxDynamicSharedMemorySize, QKV_SMEM);
        cudaFuncSetAttribute(attn_kernel,  cudaFuncAttributeMaxDynamicSharedMemorySize, ATTN_SMEM);
        cudaFuncSetAttribute(oproj_kernel, cudaFuncAttributeMaxDynamicSharedMemorySize, OP_SMEM);
        attrs_set = true;
    }

    splitx_kernel<<<16384, 256>>>(q);
    splitw_qkv_kernel<<<1536, 256>>>(Wq, Wk, Wv);
    splitw_o_kernel<<<512, 256>>>(Wo);
    qkv_kernel<<<dim3(8, 256), 256, QKV_SMEM>>>();
    attn_kernel<<<dim3(4, 64), 256, ATTN_SMEM>>>();
    oproj_kernel<<<dim3(8, 32), 256, OP_SMEM>>>(out);
}

// round 13
// speedup vs baseline: 1.1958x; 1.0085x over previous
#include <cuda_runtime.h>
#include <cuda_fp16.h>
#include <cstdint>

#define BATCH 8
#define TT    4096
#define DIM   512
#define NH    8
#define HD    64
#define QDIM  512
#define GG    3584
#define NCHUNK 56

// ---- global scratch (u32 = half2 of adjacent elements of ONE plane) ----
__device__ __align__(256) uint32_t g_Q  [(size_t)NH*BATCH*QDIM*HD];        // packed (hi|lo) per element
__device__ __align__(256) uint32_t g_Kh [(size_t)NH*BATCH*GG*(HD/2)];      // [pair][g][dpair]
__device__ __align__(256) uint32_t g_Kl [(size_t)NH*BATCH*GG*(HD/2)];
__device__ __align__(256) uint32_t g_V2h[(size_t)NH*BATCH*(GG/2)*HD];      // [pair][gpair][d]
__device__ __align__(256) uint32_t g_V2l[(size_t)NH*BATCH*(GG/2)*HD];
__device__ __align__(256) uint32_t g_Hdh[(size_t)BATCH*QDIM*(DIM/2)];      // [b][q][epair]
__device__ __align__(256) uint32_t g_Hdl[(size_t)BATCH*QDIM*(DIM/2)];
__device__ __align__(256) uint32_t g_Xh [(size_t)BATCH*TT*(DIM/2)];        // [b][t][kpair]
__device__ __align__(256) uint32_t g_Xl [(size_t)BATCH*TT*(DIM/2)];
__device__ __align__(256) uint32_t g_Wth[(size_t)3*NH*HD*(DIM/2)];         // [w][h][n][kpair]
__device__ __align__(256) uint32_t g_Wtl[(size_t)3*NH*HD*(DIM/2)];
__device__ __align__(256) uint32_t g_Woth[(size_t)DIM*(DIM/2)];            // [n][kpair]
__device__ __align__(256) uint32_t g_Wotl[(size_t)DIM*(DIM/2)];

__device__ __forceinline__ uint32_t packsplit(float v) {
    __half h = __float2half_rn(v);
    __half l = __float2half_rn(v - __half2float(h));
    return (uint32_t)__half_as_ushort(h) | ((uint32_t)__half_as_ushort(l) << 16);
}
__device__ __forceinline__ void psplit2(float p0, float p1, uint32_t& hi, uint32_t& lo) {
    __half2 h = __floats2half2_rn(p0, p1);
    float2 hf = __half22float2(h);
    __half2 l = __floats2half2_rn(p0 - hf.x, p1 - hf.y);
    hi = *reinterpret_cast<uint32_t*>(&h);
    lo = *reinterpret_cast<uint32_t*>(&l);
}
__device__ __forceinline__ uint32_t h2scale8(uint32_t a) {   // *=0.125 exact
    __half2 s = __float2half2_rn(0.125f);
    __half2 r = __hmul2(*reinterpret_cast<__half2*>(&a), s);
    return *reinterpret_cast<uint32_t*>(&r);
}
#define HI_PAIR(v0, v1) __byte_perm((v0), (v1), 0x5410)
#define LO_PAIR(v0, v1) __byte_perm((v0), (v1), 0x7632)

__device__ __forceinline__ void mma16(float* c, const uint32_t* a, const uint32_t* b) {
    asm volatile(
        "mma.sync.aligned.m16n8k16.row.col.f32.f16.f16.f32 "
        "{%0,%1,%2,%3},{%4,%5,%6,%7},{%8,%9},{%0,%1,%2,%3};"
        : "+f"(c[0]), "+f"(c[1]), "+f"(c[2]), "+f"(c[3])
        : "r"(a[0]), "r"(a[1]), "r"(a[2]), "r"(a[3]), "r"(b[0]), "r"(b[1]));
}
__device__ __forceinline__ void cpa16(uint32_t dst, const void* src) {
    asm volatile("cp.async.cg.shared.global [%0], [%1], 16;" :: "r"(dst), "l"(src));
}

// ===========================================================================
// Prep kernels: split inputs into hi/lo half planes (transposed weights)
// ===========================================================================
__global__ __launch_bounds__(256) void splitx_kernel(const float* __restrict__ X) {
    int i = blockIdx.x * 256 + threadIdx.x;              // per float4
    float4 v = reinterpret_cast<const float4*>(X)[i];
    uint32_t h0, l0, h1, l1;
    psplit2(v.x, v.y, h0, l0);
    psplit2(v.z, v.w, h1, l1);
    g_Xh[2 * i] = h0; g_Xh[2 * i + 1] = h1;
    g_Xl[2 * i] = l0; g_Xl[2 * i + 1] = l1;
}
__global__ __launch_bounds__(256) void splitw_qkv_kernel(const float* __restrict__ Wq,
                                                         const float* __restrict__ Wk,
                                                         const float* __restrict__ Wv) {
    int idx = blockIdx.x * 256 + threadIdx.x;   // [w][h][n][kpair] flattened
    int kp = idx & 255, n = (idx >> 8) & 63, h = (idx >> 14) & 7, w = idx >> 17;
    const float* W = (w == 0) ? Wq : (w == 1) ? Wk : Wv;
    const float* b = W + ((size_t)h * DIM + 2 * kp) * HD + n;
    uint32_t hi, lo;
    psplit2(b[0], b[HD], hi, lo);
    g_Wth[idx] = hi; g_Wtl[idx] = lo;
}
__global__ __launch_bounds__(256) void splitw_o_kernel(const float* __restrict__ Wo) {
    int idx = blockIdx.x * 256 + threadIdx.x;   // [n][kpair]
    int kp = idx & 255, n = idx >> 8;
    const float* b = Wo + (size_t)(2 * kp) * DIM + n;
    uint32_t hi, lo;
    psplit2(b[0], b[DIM], hi, lo);
    g_Woth[idx] = hi; g_Wotl[idx] = lo;
}

// ===========================================================================
// QKV projection: K-chunk 32 halfs, 2-stage double buffer, 16 iters,
// ONE barrier per iteration. 256 thr, 8 warps (4M x 2N), warp 32x32/weight.
// grid (8 heads, 256): bm<224 -> K+V tiles, bm>=224 -> Q tiles.
// (UNCHANGED from round 12 — 298.7us, tensor 56.6%)
// ===========================================================================
#define GLD 20                                     // 16 data u32 + 4 pad
#define QKV_A_U32 (128 * GLD)                      // 2560 per plane
#define QKV_B_U32 (64 * GLD)                       // 1280 per plane per weight
#define QKV_STAGE_U32 (2 * QKV_A_U32 + 4 * QKV_B_U32) // 10240
#define QKV_SMEM (2 * QKV_STAGE_U32 * 4)           // 81920

__global__ __launch_bounds__(256, 2)
void qkv_kernel()
{
    extern __shared__ uint32_t dsm[];
    const uint32_t sb = (uint32_t)__cvta_generic_to_shared(dsm);

    const int tid  = threadIdx.x;
    const int lane = tid & 31;
    const int warp = tid >> 5;
    const int wm   = warp >> 1;      // 0..3
    const int wn   = warp & 1;       // 0..1
    const int bn   = blockIdx.x;     // head
    const int bm   = blockIdx.y;     // 0..255
    const bool isQ = bm >= 224;
    const int r0 = lane >> 2;
    const int j2 = 2 * (lane & 3);

    int bidx, t0, rowoff, w0sel, w1sel;
    if (isQ) {
        int qbm = bm - 224;
        bidx = qbm >> 2; t0 = (qbm & 3) * 128; rowoff = 0; w0sel = 0; w1sel = 0;
    } else {
        bidx = bm / 28; t0 = (bm % 28) * 128; rowoff = QDIM; w0sel = 1; w1sel = 2;
    }
    const int nw = isQ ? 1 : 2;

    const uint32_t* Xhp = g_Xh + ((size_t)bidx * TT + rowoff + t0) * (DIM / 2);
    const uint32_t* Xlp = g_Xl + ((size_t)bidx * TT + rowoff + t0) * (DIM / 2);
    const size_t wb0 = ((size_t)(w0sel * NH + bn)) * HD * (DIM / 2);
    const size_t wb1 = ((size_t)(w1sel * NH + bn)) * HD * (DIM / 2);

    auto prefetch = [&](int st, int c) {
        uint32_t base = sb + st * (QKV_STAGE_U32 * 4);
        #pragma unroll
        for (int j = 0; j < 4; j++) {      // A: 2 planes x 128 rows x 4 segs = 1024
            int idx = tid + j * 256;
            int p = idx >> 9, rem = idx & 511;
            int row = rem >> 2, seg = rem & 3;
            cpa16(base + p * (QKV_A_U32 * 4) + row * (GLD * 4) + seg * 16,
                  (p ? Xlp : Xhp) + (size_t)row * (DIM / 2) + c * 16 + seg * 4);
        }
        #pragma unroll
        for (int j = 0; j < 4; j++) {      // B: 2w x 2p x 64 rows x 4 segs = 1024
            int idx = tid + j * 256;
            int w = idx >> 9, rem = idx & 511;
            int p = rem >> 8, r2 = rem & 255;
            int row = r2 >> 2, seg = r2 & 3;
            if (w < nw) {
                const uint32_t* src = (p ? g_Wtl : g_Wth) + (w ? wb1 : wb0)
                                      + (size_t)row * (DIM / 2) + c * 16 + seg * 4;
                cpa16(base + (2 * QKV_A_U32 + (w * 2 + p) * QKV_B_U32) * 4
                           + row * (GLD * 4) + seg * 16, src);
            }
        }
    };

    float acc[2][2][4][4];     // [w][mt][nt][i]
    #pragma unroll
    for (int w = 0; w < 2; w++)
        #pragma unroll
        for (int a = 0; a < 2; a++)
            #pragma unroll
            for (int b = 0; b < 4; b++)
                #pragma unroll
                for (int c = 0; c < 4; c++) acc[w][a][b][c] = 0.f;

    prefetch(0, 0);
    asm volatile("cp.async.commit_group;");

    for (int it = 0; it < 16; it++) {
        const int cur = it & 1;
        asm volatile("cp.async.wait_group 0;");
        __syncthreads();
        if (it + 1 < 16) prefetch(cur ^ 1, it + 1);
        asm volatile("cp.async.commit_group;");

        const uint32_t* Ah = dsm + cur * QKV_STAGE_U32;
        const uint32_t* Al = Ah + QKV_A_U32;
        const uint32_t* Bb = Ah + 2 * QKV_A_U32;

        #pragma unroll
        for (int kk = 0; kk < 2; kk++) {
            uint32_t ah[2][4], al[2][4];
            #pragma unroll
            for (int mt = 0; mt < 2; mt++) {
                int base = (wm * 32 + mt * 16 + r0) * GLD + kk * 8 + (lane & 3);
                ah[mt][0] = Ah[base];           al[mt][0] = Al[base];
                ah[mt][1] = Ah[base + 8 * GLD]; al[mt][1] = Al[base + 8 * GLD];
                ah[mt][2] = Ah[base + 4];       al[mt][2] = Al[base + 4];
                ah[mt][3] = Ah[base + 8 * GLD + 4]; al[mt][3] = Al[base + 8 * GLD + 4];
            }
            uint32_t bh[4][2][2], bl[4][2][2];   // [nt][w][2]
            #pragma unroll
            for (int nt = 0; nt < 4; nt++) {
                int cidx = (wn * 32 + nt * 8 + r0) * GLD + kk * 8 + (lane & 3);
                #pragma unroll
                for (int w = 0; w < 2; w++)
                    if (w < nw) {
                        const uint32_t* Bh = Bb + (w * 2 + 0) * QKV_B_U32;
                        const uint32_t* Bl = Bb + (w * 2 + 1) * QKV_B_U32;
                        bh[nt][w][0] = Bh[cidx]; bh[nt][w][1] = Bh[cidx + 4];
                        bl[nt][w][0] = Bl[cidx]; bl[nt][w][1] = Bl[cidx + 4];
                    }
            }
            // 3 breadth-first passes (dep distance 16)
            #pragma unroll
            for (int nt = 0; nt < 4; nt++)
                #pragma unroll
                for (int w = 0; w < 2; w++)
                    if (w < nw)
                        #pragma unroll
                        for (int mt = 0; mt < 2; mt++)
                            mma16(acc[w][mt][nt], ah[mt], bl[nt][w]);
            #pragma unroll
            for (int nt = 0; nt < 4; nt++)
                #pragma unroll
                for (int w = 0; w < 2; w++)
                    if (w < nw)
                        #pragma unroll
                        for (int mt = 0; mt < 2; mt++)
                            mma16(acc[w][mt][nt], al[mt], bh[nt][w]);
            #pragma unroll
            for (int nt = 0; nt < 4; nt++)
                #pragma unroll
                for (int w = 0; w < 2; w++)
                    if (w < nw)
                        #pragma unroll
                        for (int mt = 0; mt < 2; mt++)
                            mma16(acc[w][mt][nt], ah[mt], bh[nt][w]);
        }
    }

    // Epilogues
    if (isQ) {
        #pragma unroll
        for (int mt = 0; mt < 2; mt++)
            #pragma unroll
            for (int nt = 0; nt < 4; nt++)
                #pragma unroll
                for (int i = 0; i < 4; i++) {
                    int mloc = wm * 32 + mt * 16 + r0 + ((i & 2) ? 8 : 0);
                    int nloc = wn * 32 + nt * 8 + j2 + (i & 1);
                    g_Q[(((size_t)(bn * BATCH + bidx)) * QDIM + t0 + mloc) * HD + nloc] =
                        packsplit(acc[0][mt][nt][i]);
                }
    } else {
        const size_t pb = (size_t)(bn * BATCH + bidx);
        #pragma unroll
        for (int mt = 0; mt < 2; mt++)
            #pragma unroll
            for (int nt = 0; nt < 4; nt++) {
                int grow = t0 + wm * 32 + mt * 16 + r0;
                int dp = wn * 16 + nt * 4 + (lane & 3);
                uint32_t h0, l0, h1, l1;
                psplit2(acc[0][mt][nt][0], acc[0][mt][nt][1], h0, l0);
                psplit2(acc[0][mt][nt][2], acc[0][mt][nt][3], h1, l1);
                size_t kb = (pb * GG + grow) * (HD / 2) + dp;
                g_Kh[kb] = h0; g_Kl[kb] = l0;
                g_Kh[kb + 8 * (HD / 2)] = h1; g_Kl[kb + 8 * (HD / 2)] = l1;
                uint32_t p0 = packsplit(acc[1][mt][nt][0]);
                uint32_t p1 = packsplit(acc[1][mt][nt][1]);
                uint32_t p2 = packsplit(acc[1][mt][nt][2]);
                uint32_t p3 = packsplit(acc[1][mt][nt][3]);
                uint32_t q0 = __shfl_down_sync(0xffffffffu, p0, 4);
                uint32_t q1 = __shfl_down_sync(0xffffffffu, p1, 4);
                uint32_t q2 = __shfl_down_sync(0xffffffffu, p2, 4);
                uint32_t q3 = __shfl_down_sync(0xffffffffu, p3, 4);
                if ((r0 & 1) == 0) {
                    int d0 = wn * 32 + nt * 8 + j2;
                    size_t vb = (pb * (GG / 2) + (grow >> 1)) * HD + d0;
                    g_V2h[vb]     = HI_PAIR(p0, q0); g_V2l[vb]     = LO_PAIR(p0, q0);
                    g_V2h[vb + 1] = HI_PAIR(p1, q1); g_V2l[vb + 1] = LO_PAIR(p1, q1);
                    g_V2h[vb + 4 * HD]     = HI_PAIR(p2, q2); g_V2l[vb + 4 * HD]     = LO_PAIR(p2, q2);
                    g_V2h[vb + 4 * HD + 1] = HI_PAIR(p3, q3); g_V2l[vb + 4 * HD + 1] = LO_PAIR(p3, q3);
                }
            }
    }
}

// ===========================================================================
// Out projection: K-chunk 32, 2-stage, 16 iters, 1 bar/iter. 60KB smem.
// (UNCHANGED from round 12)
// ===========================================================================
#define OP_A_U32 (128 * GLD)                       // 2560 per plane
#define OP_B_U32 (64 * GLD)                        // 1280 per plane
#define OP_STAGE_U32 (2 * OP_A_U32 + 2 * OP_B_U32) // 7680
#define OP_SMEM (2 * OP_STAGE_U32 * 4)             // 61440

__global__ __launch_bounds__(256, 2)
void oproj_kernel(float* __restrict__ Outp)
{
    extern __shared__ uint32_t dsm[];
    const uint32_t sb = (uint32_t)__cvta_generic_to_shared(dsm);

    const int tid  = threadIdx.x;
    const int lane = tid & 31;
    const int warp = tid >> 5;
    const int wm   = warp >> 1;
    const int wn   = warp & 1;
    const int bm   = blockIdx.y;
    const int bn   = blockIdx.x;
    const int r0 = lane >> 2;
    const int j2 = 2 * (lane & 3);

    const size_t arow = (size_t)bm * 128;
    const size_t brow = (size_t)bn * 64;

    auto prefetch = [&](int st, int c) {
        uint32_t base = sb + st * (OP_STAGE_U32 * 4);
        #pragma unroll
        for (int j = 0; j < 4; j++) {      // A: 2 planes x 128 rows x 4 segs
            int idx = tid + j * 256;
            int p = idx >> 9, rem = idx & 511;
            int row = rem >> 2, seg = rem & 3;
            cpa16(base + p * (OP_A_U32 * 4) + row * (GLD * 4) + seg * 16,
                  (p ? g_Hdl : g_Hdh) + (arow + row) * (DIM / 2) + c * 16 + seg * 4);
        }
        #pragma unroll
        for (int j = 0; j < 2; j++) {      // B: 2 planes x 64 rows x 4 segs
            int idx = tid + j * 256;
            int p = idx >> 8, rem = idx & 255;
            int row = rem >> 2, seg = rem & 3;
            cpa16(base + (2 * OP_A_U32 + p * OP_B_U32) * 4 + row * (GLD * 4) + seg * 16,
                  (p ? g_Wotl : g_Woth) + (brow + row) * (DIM / 2) + c * 16 + seg * 4);
        }
    };

    float acc[2][4][4];
    #pragma unroll
    for (int a = 0; a < 2; a++)
        #pragma unroll
        for (int b = 0; b < 4; b++)
            #pragma unroll
            for (int c = 0; c < 4; c++) acc[a][b][c] = 0.f;

    prefetch(0, 0);
    asm volatile("cp.async.commit_group;");

    for (int it = 0; it < 16; it++) {
        const int cur = it & 1;
        asm volatile("cp.async.wait_group 0;");
        __syncthreads();
        if (it + 1 < 16) prefetch(cur ^ 1, it + 1);
        asm volatile("cp.async.commit_group;");

        const uint32_t* Ah = dsm + cur * OP_STAGE_U32;
        const uint32_t* Al = Ah + OP_A_U32;
        const uint32_t* Bhp = Ah + 2 * OP_A_U32;
        const uint32_t* Blp = Bhp + OP_B_U32;

        #pragma unroll
        for (int kk = 0; kk < 2; kk++) {
            uint32_t ah[2][4], al[2][4];
            #pragma unroll
            for (int mt = 0; mt < 2; mt++) {
                int base = (wm * 32 + mt * 16 + r0) * GLD + kk * 8 + (lane & 3);
                ah[mt][0] = Ah[base];           al[mt][0] = Al[base];
                ah[mt][1] = Ah[base + 8 * GLD]; al[mt][1] = Al[base + 8 * GLD];
                ah[mt][2] = Ah[base + 4];       al[mt][2] = Al[base + 4];
                ah[mt][3] = Ah[base + 8 * GLD + 4]; al[mt][3] = Al[base + 8 * GLD + 4];
            }
            uint32_t bh[4][2], bl[4][2];
            #pragma unroll
            for (int nt = 0; nt < 4; nt++) {
                int cidx = (wn * 32 + nt * 8 + r0) * GLD + kk * 8 + (lane & 3);
                bh[nt][0] = Bhp[cidx]; bh[nt][1] = Bhp[cidx + 4];
                bl[nt][0] = Blp[cidx]; bl[nt][1] = Blp[cidx + 4];
            }
            #pragma unroll
            for (int nt = 0; nt < 4; nt++)
                #pragma unroll
                for (int mt = 0; mt < 2; mt++)
                    mma16(acc[mt][nt], ah[mt], bl[nt]);
            #pragma unroll
            for (int nt = 0; nt < 4; nt++)
                #pragma unroll
                for (int mt = 0; mt < 2; mt++)
                    mma16(acc[mt][nt], al[mt], bh[nt]);
            #pragma unroll
            for (int nt = 0; nt < 4; nt++)
                #pragma unroll
                for (int mt = 0; mt < 2; mt++)
                    mma16(acc[mt][nt], ah[mt], bh[nt]);
        }
    }

    #pragma unroll
    for (int mt = 0; mt < 2; mt++)
        #pragma unroll
        for (int nt = 0; nt < 4; nt++)
            #pragma unroll
            for (int i = 0; i < 4; i++) {
                int mloc = wm * 32 + mt * 16 + r0 + ((i & 2) ? 8 : 0);
                int nloc = wn * 32 + nt * 8 + j2 + (i & 1);
                Outp[(size_t)(bm * 128 + mloc) * DIM + bn * 64 + nloc] = acc[mt][nt][i];
            }
}

// ===========================================================================
// Flash attention: breadth-first MMA ordering in S and PV loops
// (groups of 4 accumulators; per-acc order unchanged -> bit-identical).
// ===========================================================================
#define AK_LD 36
#define AV_LD 72
#define AK_U32 (64 * AK_LD)
#define AV_U32 (32 * AV_LD)
#define ATTN_STAGE_U32 (2 * AK_U32 + 2 * AV_U32)
#define ATTN_SMEM (3 * ATTN_STAGE_U32 * 4)

__global__ __launch_bounds__(256, 2)
void attn_kernel()
{
    extern __shared__ uint32_t dsm[];
    const uint32_t sb = (uint32_t)__cvta_generic_to_shared(dsm);

    const int tid  = threadIdx.x;
    const int lane = tid & 31;
    const int warp = tid >> 5;
    const int qt   = blockIdx.x;
    const int pair = blockIdx.y;
    const int r0 = lane >> 2;
    const int j2 = 2 * (lane & 3);

    const uint32_t* Qp  = g_Q + ((size_t)pair * QDIM + qt * 128 + warp * 16) * HD;
    const size_t kbase = (size_t)pair * GG * (HD / 2);
    const size_t vbase = (size_t)pair * (GG / 2) * HD;

    auto prefetch = [&](int st, int c) {
        uint32_t base = sb + st * (ATTN_STAGE_U32 * 4);
        #pragma unroll
        for (int j = 0; j < 2; j++) {
            int idx = tid + j * 256;
            int row = idx >> 3, seg = idx & 7;
            cpa16(base + row * (AK_LD * 4) + seg * 16,
                  g_Kh + kbase + (size_t)(c * 64 + row) * (HD / 2) + seg * 4);
            cpa16(base + AK_U32 * 4 + row * (AK_LD * 4) + seg * 16,
                  g_Kl + kbase + (size_t)(c * 64 + row) * (HD / 2) + seg * 4);
        }
        #pragma unroll
        for (int j = 0; j < 2; j++) {
            int idx = tid + j * 256;
            int row = idx >> 4, seg = idx & 15;
            cpa16(base + 2 * AK_U32 * 4 + row * (AV_LD * 4) + seg * 16,
                  g_V2h + vbase + (size_t)(c * 32 + row) * HD + seg * 4);
            cpa16(base + (2 * AK_U32 + AV_U32) * 4 + row * (AV_LD * 4) + seg * 16,
                  g_V2l + vbase + (size_t)(c * 32 + row) * HD + seg * 4);
        }
    };

    uint32_t qh[4][4], ql[4][4];
    #pragma unroll
    for (int kk = 0; kk < 4; kk++) {
        int d0 = kk * 16 + j2;
        uint2 w01 = *reinterpret_cast<const uint2*>(Qp + (size_t)r0 * HD + d0);
        uint2 w23 = *reinterpret_cast<const uint2*>(Qp + (size_t)(r0 + 8) * HD + d0);
        uint2 w45 = *reinterpret_cast<const uint2*>(Qp + (size_t)r0 * HD + d0 + 8);
        uint2 w67 = *reinterpret_cast<const uint2*>(Qp + (size_t)(r0 + 8) * HD + d0 + 8);
        qh[kk][0] = h2scale8(HI_PAIR(w01.x, w01.y)); ql[kk][0] = h2scale8(LO_PAIR(w01.x, w01.y));
        qh[kk][1] = h2scale8(HI_PAIR(w23.x, w23.y)); ql[kk][1] = h2scale8(LO_PAIR(w23.x, w23.y));
        qh[kk][2] = h2scale8(HI_PAIR(w45.x, w45.y)); ql[kk][2] = h2scale8(LO_PAIR(w45.x, w45.y));
        qh[kk][3] = h2scale8(HI_PAIR(w67.x, w67.y)); ql[kk][3] = h2scale8(LO_PAIR(w67.x, w67.y));
    }

    float oacc[8][4];
    #pragma unroll
    for (int t = 0; t < 8; t++)
        #pragma unroll
        for (int i = 0; i < 4; i++) oacc[t][i] = 0.f;
    float m0 = -1e30f, m1 = -1e30f, l0 = 0.f, l1 = 0.f;

    prefetch(0, 0);
    asm volatile("cp.async.commit_group;");
    prefetch(1, 1);
    asm volatile("cp.async.commit_group;");

    for (int c = 0; c < NCHUNK; c++) {
        asm volatile("cp.async.wait_group 1;");
        __syncthreads();
        if (c + 2 < NCHUNK) prefetch((c + 2) % 3, c + 2);
        asm volatile("cp.async.commit_group;");

        const uint32_t* Kh = dsm + (c % 3) * ATTN_STAGE_U32;
        const uint32_t* Kl = Kh + AK_U32;
        const uint32_t* Vh = Kh + 2 * AK_U32;
        const uint32_t* Vl = Vh + AV_U32;

        float sacc[8][4];
        #pragma unroll
        for (int t = 0; t < 8; t++)
            #pragma unroll
            for (int i = 0; i < 4; i++) sacc[t][i] = 0.f;

        // S = Q @ K^T : breadth-first in groups of 4 accumulators
        #pragma unroll
        for (int kk = 0; kk < 4; kk++) {
            #pragma unroll
            for (int g = 0; g < 2; g++) {
                uint32_t bh[4][2], bl[4][2];
                #pragma unroll
                for (int t = 0; t < 4; t++) {
                    int cidx = ((g * 4 + t) * 8 + r0) * AK_LD + kk * 8 + (lane & 3);
                    bh[t][0] = Kh[cidx]; bh[t][1] = Kh[cidx + 4];
                    bl[t][0] = Kl[cidx]; bl[t][1] = Kl[cidx + 4];
                }
                #pragma unroll
                for (int t = 0; t < 4; t++) mma16(sacc[g * 4 + t], qh[kk], bl[t]);
                #pragma unroll
                for (int t = 0; t < 4; t++) mma16(sacc[g * 4 + t], ql[kk], bh[t]);
                #pragma unroll
                for (int t = 0; t < 4; t++) mma16(sacc[g * 4 + t], qh[kk], bh[t]);
            }
        }

        float mx0 = -1e30f, mx1 = -1e30f;
        #pragma unroll
        for (int t = 0; t < 8; t++) {
            mx0 = fmaxf(mx0, fmaxf(sacc[t][0], sacc[t][1]));
            mx1 = fmaxf(mx1, fmaxf(sacc[t][2], sacc[t][3]));
        }
        mx0 = fmaxf(mx0, __shfl_xor_sync(0xffffffffu, mx0, 1));
        mx0 = fmaxf(mx0, __shfl_xor_sync(0xffffffffu, mx0, 2));
        mx1 = fmaxf(mx1, __shfl_xor_sync(0xffffffffu, mx1, 1));
        mx1 = fmaxf(mx1, __shfl_xor_sync(0xffffffffu, mx1, 2));

        float mn0 = fmaxf(m0, mx0), mn1 = fmaxf(m1, mx1);
        float al0 = __expf(m0 - mn0), al1 = __expf(m1 - mn1);
        float s0 = 0.f, s1 = 0.f;
        #pragma unroll
        for (int t = 0; t < 8; t++) {
            sacc[t][0] = __expf(sacc[t][0] - mn0);
            sacc[t][1] = __expf(sacc[t][1] - mn0);
            sacc[t][2] = __expf(sacc[t][2] - mn1);
            sacc[t][3] = __expf(sacc[t][3] - mn1);
            s0 += sacc[t][0] + sacc[t][1];
            s1 += sacc[t][2] + sacc[t][3];
        }
        s0 += __shfl_xor_sync(0xffffffffu, s0, 1);
        s0 += __shfl_xor_sync(0xffffffffu, s0, 2);
        s1 += __shfl_xor_sync(0xffffffffu, s1, 1);
        s1 += __shfl_xor_sync(0xffffffffu, s1, 2);
        l0 = l0 * al0 + s0;
        l1 = l1 * al1 + s1;
        m0 = mn0; m1 = mn1;
        #pragma unroll
        for (int nt = 0; nt < 8; nt++) {
            oacc[nt][0] *= al0; oacc[nt][1] *= al0;
            oacc[nt][2] *= al1; oacc[nt][3] *= al1;
        }

        // O += P @ V : breadth-first in groups of 4 accumulators
        #pragma unroll
        for (int kk = 0; kk < 4; kk++) {
            uint32_t pah[4], pal[4];
            psplit2(sacc[2 * kk][0],     sacc[2 * kk][1],     pah[0], pal[0]);
            psplit2(sacc[2 * kk][2],     sacc[2 * kk][3],     pah[1], pal[1]);
            psplit2(sacc[2 * kk + 1][0], sacc[2 * kk + 1][1], pah[2], pal[2]);
            psplit2(sacc[2 * kk + 1][2], sacc[2 * kk + 1][3], pah[3], pal[3]);
            int gp = kk * 8 + (lane & 3);
            #pragma unroll
            for (int g = 0; g < 2; g++) {
                uint32_t bh[4][2], bl[4][2];
                #pragma unroll
                for (int t = 0; t < 4; t++) {
                    int d = (g * 4 + t) * 8 + r0;
                    bh[t][0] = Vh[gp * AV_LD + d]; bh[t][1] = Vh[(gp + 4) * AV_LD + d];
                    bl[t][0] = Vl[gp * AV_LD + d]; bl[t][1] = Vl[(gp + 4) * AV_LD + d];
                }
                #pragma unroll
                for (int t = 0; t < 4; t++) mma16(oacc[g * 4 + t], pah, bl[t]);
                #pragma unroll
                for (int t = 0; t < 4; t++) mma16(oacc[g * 4 + t], pal, bh[t]);
                #pragma unroll
                for (int t = 0; t < 4; t++) mma16(oacc[g * 4 + t], pah, bh[t]);
            }
        }
    }

    float inv0 = 1.f / l0, inv1 = 1.f / l1;
    int h = pair >> 3, b = pair & 7;
    #pragma unroll
    for (int nt = 0; nt < 8; nt++) {
        int q = qt * 128 + warp * 16 + r0;
        int dp = h * 32 + nt * 4 + (lane & 3);
        uint32_t h0, l0u, h1, l1u;
        psplit2(oacc[nt][0] * inv0, oacc[nt][1] * inv0, h0, l0u);
        psplit2(oacc[nt][2] * inv1, oacc[nt][3] * inv1, h1, l1u);
        size_t o = ((size_t)(b * QDIM + q)) * (DIM / 2) + dp;
        g_Hdh[o] = h0; g_Hdl[o] = l0u;
        g_Hdh[o + 8 * (DIM / 2)] = h1; g_Hdl[o + 8 * (DIM / 2)] = l1u;
    }
}

extern "C" void kernel_launch(void* const* d_in, const int* in_sizes, int n_in,
                              void* d_out, int out_size)
{
    (void)in_sizes; (void)n_in; (void)out_size;
    const float* q  = (const float*)d_in[0];
    const float* Wq = (const float*)d_in[1];
    const float* Wk = (const float*)d_in[2];
    const float* Wv = (const float*)d_in[3];
    const float* Wo = (const float*)d_in[4];
    float* out = (float*)d_out;

    static bool attrs_set = false;
    if (!attrs_set) {
        cudaFuncSetAttribute(qkv_kernel,   cudaFuncAttributeMaxDynamicSharedMemorySize, QKV_SMEM);
        cudaFuncSetAttribute(attn_kernel,  cudaFuncAttributeMaxDynamicSharedMemorySize, ATTN_SMEM);
        cudaFuncSetAttribute(oproj_kernel, cudaFuncAttributeMaxDynamicSharedMemorySize, OP_SMEM);
        attrs_set = true;
    }

    splitx_kernel<<<16384, 256>>>(q);
    splitw_qkv_kernel<<<1536, 256>>>(Wq, Wk, Wv);
    splitw_o_kernel<<<512, 256>>>(Wo);
    qkv_kernel<<<dim3(8, 256), 256, QKV_SMEM>>>();
    attn_kernel<<<dim3(4, 64), 256, ATTN_SMEM>>>();
    oproj_kernel<<<dim3(8, 32), 256, OP_SMEM>>>(out);
}

// round 14
// speedup vs baseline: 1.2268x; 1.0259x over previous
#include <cuda_runtime.h>
#include <cuda_fp16.h>
#include <cstdint>

#define BATCH 8
#define TT    4096
#define DIM   512
#define NH    8
#define HD    64
#define QDIM  512
#define GG    3584
#define NCHUNK 56

// ---- global scratch (u32 = half2 of adjacent elements of ONE plane) ----
__device__ __align__(256) uint32_t g_Q  [(size_t)NH*BATCH*QDIM*HD];
__device__ __align__(256) uint32_t g_Kh [(size_t)NH*BATCH*GG*(HD/2)];
__device__ __align__(256) uint32_t g_Kl [(size_t)NH*BATCH*GG*(HD/2)];
__device__ __align__(256) uint32_t g_V2h[(size_t)NH*BATCH*(GG/2)*HD];
__device__ __align__(256) uint32_t g_V2l[(size_t)NH*BATCH*(GG/2)*HD];
__device__ __align__(256) uint32_t g_Hdh[(size_t)BATCH*QDIM*(DIM/2)];
__device__ __align__(256) uint32_t g_Hdl[(size_t)BATCH*QDIM*(DIM/2)];
__device__ __align__(256) uint32_t g_Xh [(size_t)BATCH*TT*(DIM/2)];
__device__ __align__(256) uint32_t g_Xl [(size_t)BATCH*TT*(DIM/2)];
__device__ __align__(256) uint32_t g_Wth[(size_t)3*NH*HD*(DIM/2)];
__device__ __align__(256) uint32_t g_Wtl[(size_t)3*NH*HD*(DIM/2)];
__device__ __align__(256) uint32_t g_Woth[(size_t)DIM*(DIM/2)];
__device__ __align__(256) uint32_t g_Wotl[(size_t)DIM*(DIM/2)];

__device__ __forceinline__ uint32_t packsplit(float v) {
    __half h = __float2half_rn(v);
    __half l = __float2half_rn(v - __half2float(h));
    return (uint32_t)__half_as_ushort(h) | ((uint32_t)__half_as_ushort(l) << 16);
}
__device__ __forceinline__ void psplit2(float p0, float p1, uint32_t& hi, uint32_t& lo) {
    __half2 h = __floats2half2_rn(p0, p1);
    float2 hf = __half22float2(h);
    __half2 l = __floats2half2_rn(p0 - hf.x, p1 - hf.y);
    hi = *reinterpret_cast<uint32_t*>(&h);
    lo = *reinterpret_cast<uint32_t*>(&l);
}
__device__ __forceinline__ uint32_t h2scale8(uint32_t a) {   // *=0.125 exact
    __half2 s = __float2half2_rn(0.125f);
    __half2 r = __hmul2(*reinterpret_cast<__half2*>(&a), s);
    return *reinterpret_cast<uint32_t*>(&r);
}
#define HI_PAIR(v0, v1) __byte_perm((v0), (v1), 0x5410)
#define LO_PAIR(v0, v1) __byte_perm((v0), (v1), 0x7632)

__device__ __forceinline__ void mma16(float* c, const uint32_t* a, const uint32_t* b) {
    asm volatile(
        "mma.sync.aligned.m16n8k16.row.col.f32.f16.f16.f32 "
        "{%0,%1,%2,%3},{%4,%5,%6,%7},{%8,%9},{%0,%1,%2,%3};"
        : "+f"(c[0]), "+f"(c[1]), "+f"(c[2]), "+f"(c[3])
        : "r"(a[0]), "r"(a[1]), "r"(a[2]), "r"(a[3]), "r"(b[0]), "r"(b[1]));
}
__device__ __forceinline__ void cpa16(uint32_t dst, const void* src) {
    asm volatile("cp.async.cg.shared.global [%0], [%1], 16;" :: "r"(dst), "l"(src));
}
__device__ __forceinline__ void ldsm4(uint32_t* r, uint32_t saddr) {
    asm volatile("ldmatrix.sync.aligned.m8n8.x4.shared.b16 {%0,%1,%2,%3}, [%4];"
        : "=r"(r[0]), "=r"(r[1]), "=r"(r[2]), "=r"(r[3]) : "r"(saddr));
}

// ===========================================================================
// Prep kernels
// ===========================================================================
__global__ __launch_bounds__(256) void splitx_kernel(const float* __restrict__ X) {
    int i = blockIdx.x * 256 + threadIdx.x;
    float4 v = reinterpret_cast<const float4*>(X)[i];
    uint32_t h0, l0, h1, l1;
    psplit2(v.x, v.y, h0, l0);
    psplit2(v.z, v.w, h1, l1);
    g_Xh[2 * i] = h0; g_Xh[2 * i + 1] = h1;
    g_Xl[2 * i] = l0; g_Xl[2 * i + 1] = l1;
}
__global__ __launch_bounds__(256) void splitw_qkv_kernel(const float* __restrict__ Wq,
                                                         const float* __restrict__ Wk,
                                                         const float* __restrict__ Wv) {
    int idx = blockIdx.x * 256 + threadIdx.x;
    int kp = idx & 255, n = (idx >> 8) & 63, h = (idx >> 14) & 7, w = idx >> 17;
    const float* W = (w == 0) ? Wq : (w == 1) ? Wk : Wv;
    const float* b = W + ((size_t)h * DIM + 2 * kp) * HD + n;
    uint32_t hi, lo;
    psplit2(b[0], b[HD], hi, lo);
    g_Wth[idx] = hi; g_Wtl[idx] = lo;
}
__global__ __launch_bounds__(256) void splitw_o_kernel(const float* __restrict__ Wo) {
    int idx = blockIdx.x * 256 + threadIdx.x;
    int kp = idx & 255, n = idx >> 8;
    const float* b = Wo + (size_t)(2 * kp) * DIM + n;
    uint32_t hi, lo;
    psplit2(b[0], b[DIM], hi, lo);
    g_Woth[idx] = hi; g_Wotl[idx] = lo;
}

// ===========================================================================
// QKV projection: K-chunk 32, 2-stage, 16 iters, 1 bar/iter, LDSM frags.
// ===========================================================================
#define GLD 20
#define QKV_A_U32 (128 * GLD)
#define QKV_B_U32 (64 * GLD)
#define QKV_STAGE_U32 (2 * QKV_A_U32 + 4 * QKV_B_U32)
#define QKV_SMEM (2 * QKV_STAGE_U32 * 4)

__global__ __launch_bounds__(256, 2)
void qkv_kernel()
{
    extern __shared__ uint32_t dsm[];
    const uint32_t sb = (uint32_t)__cvta_generic_to_shared(dsm);

    const int tid  = threadIdx.x;
    const int lane = tid & 31;
    const int warp = tid >> 5;
    const int wm   = warp >> 1;
    const int wn   = warp & 1;
    const int bn   = blockIdx.x;
    const int bm   = blockIdx.y;
    const bool isQ = bm >= 224;
    const int r0 = lane >> 2;
    const int j2 = 2 * (lane & 3);
    const int mi = lane >> 3, ri = lane & 7;   // ldmatrix lane roles

    int bidx, t0, rowoff, w0sel, w1sel;
    if (isQ) {
        int qbm = bm - 224;
        bidx = qbm >> 2; t0 = (qbm & 3) * 128; rowoff = 0; w0sel = 0; w1sel = 0;
    } else {
        bidx = bm / 28; t0 = (bm % 28) * 128; rowoff = QDIM; w0sel = 1; w1sel = 2;
    }
    const int nw = isQ ? 1 : 2;

    const uint32_t* Xhp = g_Xh + ((size_t)bidx * TT + rowoff + t0) * (DIM / 2);
    const uint32_t* Xlp = g_Xl + ((size_t)bidx * TT + rowoff + t0) * (DIM / 2);
    const size_t wb0 = ((size_t)(w0sel * NH + bn)) * HD * (DIM / 2);
    const size_t wb1 = ((size_t)(w1sel * NH + bn)) * HD * (DIM / 2);

    auto prefetch = [&](int st, int c) {
        uint32_t base = sb + st * (QKV_STAGE_U32 * 4);
        #pragma unroll
        for (int j = 0; j < 4; j++) {
            int idx = tid + j * 256;
            int p = idx >> 9, rem = idx & 511;
            int row = rem >> 2, seg = rem & 3;
            cpa16(base + p * (QKV_A_U32 * 4) + row * (GLD * 4) + seg * 16,
                  (p ? Xlp : Xhp) + (size_t)row * (DIM / 2) + c * 16 + seg * 4);
        }
        #pragma unroll
        for (int j = 0; j < 4; j++) {
            int idx = tid + j * 256;
            int w = idx >> 9, rem = idx & 511;
            int p = rem >> 8, r2 = rem & 255;
            int row = r2 >> 2, seg = r2 & 3;
            if (w < nw) {
                const uint32_t* src = (p ? g_Wtl : g_Wth) + (w ? wb1 : wb0)
                                      + (size_t)row * (DIM / 2) + c * 16 + seg * 4;
                cpa16(base + (2 * QKV_A_U32 + (w * 2 + p) * QKV_B_U32) * 4
                           + row * (GLD * 4) + seg * 16, src);
            }
        }
    };

    float acc[2][2][4][4];
    #pragma unroll
    for (int w = 0; w < 2; w++)
        #pragma unroll
        for (int a = 0; a < 2; a++)
            #pragma unroll
            for (int b = 0; b < 4; b++)
                #pragma unroll
                for (int c = 0; c < 4; c++) acc[w][a][b][c] = 0.f;

    prefetch(0, 0);
    asm volatile("cp.async.commit_group;");

    for (int it = 0; it < 16; it++) {
        const int cur = it & 1;
        asm volatile("cp.async.wait_group 0;");
        __syncthreads();
        if (it + 1 < 16) prefetch(cur ^ 1, it + 1);
        asm volatile("cp.async.commit_group;");

        const uint32_t stg = sb + cur * (QKV_STAGE_U32 * 4);
        const uint32_t Ahb = stg;
        const uint32_t Alb = stg + QKV_A_U32 * 4;
        const uint32_t Bbb = stg + 2 * QKV_A_U32 * 4;

        #pragma unroll
        for (int kk = 0; kk < 2; kk++) {
            // A frags via LDSM: matrices {r+0/s0, r+8/s0, r+0/s4, r+8/s4}
            uint32_t ah[2][4], al[2][4];
            const uint32_t aoff = (kk * 8 + ((mi >> 1) << 2)) * 4;
            #pragma unroll
            for (int mt = 0; mt < 2; mt++) {
                uint32_t arow = wm * 32 + mt * 16 + ((mi & 1) << 3) + ri;
                ldsm4(ah[mt], Ahb + arow * (GLD * 4) + aoff);
                ldsm4(al[mt], Alb + arow * (GLD * 4) + aoff);
            }
            // B frags via LDSM: matrices {ntA/s0, ntA/s4, ntB/s0, ntB/s4}
            uint32_t bh[4][2][2], bl[4][2][2];
            const uint32_t boffc = (kk * 8 + ((mi & 1) << 2)) * 4;
            #pragma unroll
            for (int pp = 0; pp < 2; pp++) {
                uint32_t brow = wn * 32 + pp * 16 + ((mi >> 1) << 3) + ri;
                #pragma unroll
                for (int w = 0; w < 2; w++)
                    if (w < nw) {
                        uint32_t r[4];
                        ldsm4(r, Bbb + (w * 2 + 0) * (QKV_B_U32 * 4) + brow * (GLD * 4) + boffc);
                        bh[pp * 2][w][0] = r[0]; bh[pp * 2][w][1] = r[1];
                        bh[pp * 2 + 1][w][0] = r[2]; bh[pp * 2 + 1][w][1] = r[3];
                        ldsm4(r, Bbb + (w * 2 + 1) * (QKV_B_U32 * 4) + brow * (GLD * 4) + boffc);
                        bl[pp * 2][w][0] = r[0]; bl[pp * 2][w][1] = r[1];
                        bl[pp * 2 + 1][w][0] = r[2]; bl[pp * 2 + 1][w][1] = r[3];
                    }
            }
            // 3 breadth-first passes (per-acc order: ah*bl, al*bh, ah*bh)
            #pragma unroll
            for (int nt = 0; nt < 4; nt++)
                #pragma unroll
                for (int w = 0; w < 2; w++)
                    if (w < nw)
                        #pragma unroll
                        for (int mt = 0; mt < 2; mt++)
                            mma16(acc[w][mt][nt], ah[mt], bl[nt][w]);
            #pragma unroll
            for (int nt = 0; nt < 4; nt++)
                #pragma unroll
                for (int w = 0; w < 2; w++)
                    if (w < nw)
                        #pragma unroll
                        for (int mt = 0; mt < 2; mt++)
                            mma16(acc[w][mt][nt], al[mt], bh[nt][w]);
            #pragma unroll
            for (int nt = 0; nt < 4; nt++)
                #pragma unroll
                for (int w = 0; w < 2; w++)
                    if (w < nw)
                        #pragma unroll
                        for (int mt = 0; mt < 2; mt++)
                            mma16(acc[w][mt][nt], ah[mt], bh[nt][w]);
        }
    }

    // Epilogues (unchanged)
    if (isQ) {
        #pragma unroll
        for (int mt = 0; mt < 2; mt++)
            #pragma unroll
            for (int nt = 0; nt < 4; nt++)
                #pragma unroll
                for (int i = 0; i < 4; i++) {
                    int mloc = wm * 32 + mt * 16 + r0 + ((i & 2) ? 8 : 0);
                    int nloc = wn * 32 + nt * 8 + j2 + (i & 1);
                    g_Q[(((size_t)(bn * BATCH + bidx)) * QDIM + t0 + mloc) * HD + nloc] =
                        packsplit(acc[0][mt][nt][i]);
                }
    } else {
        const size_t pb = (size_t)(bn * BATCH + bidx);
        #pragma unroll
        for (int mt = 0; mt < 2; mt++)
            #pragma unroll
            for (int nt = 0; nt < 4; nt++) {
                int grow = t0 + wm * 32 + mt * 16 + r0;
                int dp = wn * 16 + nt * 4 + (lane & 3);
                uint32_t h0, l0, h1, l1;
                psplit2(acc[0][mt][nt][0], acc[0][mt][nt][1], h0, l0);
                psplit2(acc[0][mt][nt][2], acc[0][mt][nt][3], h1, l1);
                size_t kb = (pb * GG + grow) * (HD / 2) + dp;
                g_Kh[kb] = h0; g_Kl[kb] = l0;
                g_Kh[kb + 8 * (HD / 2)] = h1; g_Kl[kb + 8 * (HD / 2)] = l1;
                uint32_t p0 = packsplit(acc[1][mt][nt][0]);
                uint32_t p1 = packsplit(acc[1][mt][nt][1]);
                uint32_t p2 = packsplit(acc[1][mt][nt][2]);
                uint32_t p3 = packsplit(acc[1][mt][nt][3]);
                uint32_t q0 = __shfl_down_sync(0xffffffffu, p0, 4);
                uint32_t q1 = __shfl_down_sync(0xffffffffu, p1, 4);
                uint32_t q2 = __shfl_down_sync(0xffffffffu, p2, 4);
                uint32_t q3 = __shfl_down_sync(0xffffffffu, p3, 4);
                if ((r0 & 1) == 0) {
                    int d0 = wn * 32 + nt * 8 + j2;
                    size_t vb = (pb * (GG / 2) + (grow >> 1)) * HD + d0;
                    g_V2h[vb]     = HI_PAIR(p0, q0); g_V2l[vb]     = LO_PAIR(p0, q0);
                    g_V2h[vb + 1] = HI_PAIR(p1, q1); g_V2l[vb + 1] = LO_PAIR(p1, q1);
                    g_V2h[vb + 4 * HD]     = HI_PAIR(p2, q2); g_V2l[vb + 4 * HD]     = LO_PAIR(p2, q2);
                    g_V2h[vb + 4 * HD + 1] = HI_PAIR(p3, q3); g_V2l[vb + 4 * HD + 1] = LO_PAIR(p3, q3);
                }
            }
    }
}

// ===========================================================================
// Out projection: K-chunk 32, 2-stage, 16 iters, 1 bar/iter, LDSM frags.
// ===========================================================================
#define OP_A_U32 (128 * GLD)
#define OP_B_U32 (64 * GLD)
#define OP_STAGE_U32 (2 * OP_A_U32 + 2 * OP_B_U32)
#define OP_SMEM (2 * OP_STAGE_U32 * 4)

__global__ __launch_bounds__(256, 2)
void oproj_kernel(float* __restrict__ Outp)
{
    extern __shared__ uint32_t dsm[];
    const uint32_t sb = (uint32_t)__cvta_generic_to_shared(dsm);

    const int tid  = threadIdx.x;
    const int lane = tid & 31;
    const int warp = tid >> 5;
    const int wm   = warp >> 1;
    const int wn   = warp & 1;
    const int bm   = blockIdx.y;
    const int bn   = blockIdx.x;
    const int r0 = lane >> 2;
    const int j2 = 2 * (lane & 3);
    const int mi = lane >> 3, ri = lane & 7;

    const size_t arow_g = (size_t)bm * 128;
    const size_t brow_g = (size_t)bn * 64;

    auto prefetch = [&](int st, int c) {
        uint32_t base = sb + st * (OP_STAGE_U32 * 4);
        #pragma unroll
        for (int j = 0; j < 4; j++) {
            int idx = tid + j * 256;
            int p = idx >> 9, rem = idx & 511;
            int row = rem >> 2, seg = rem & 3;
            cpa16(base + p * (OP_A_U32 * 4) + row * (GLD * 4) + seg * 16,
                  (p ? g_Hdl : g_Hdh) + (arow_g + row) * (DIM / 2) + c * 16 + seg * 4);
        }
        #pragma unroll
        for (int j = 0; j < 2; j++) {
            int idx = tid + j * 256;
            int p = idx >> 8, rem = idx & 255;
            int row = rem >> 2, seg = rem & 3;
            cpa16(base + (2 * OP_A_U32 + p * OP_B_U32) * 4 + row * (GLD * 4) + seg * 16,
                  (p ? g_Wotl : g_Woth) + (brow_g + row) * (DIM / 2) + c * 16 + seg * 4);
        }
    };

    float acc[2][4][4];
    #pragma unroll
    for (int a = 0; a < 2; a++)
        #pragma unroll
        for (int b = 0; b < 4; b++)
            #pragma unroll
            for (int c = 0; c < 4; c++) acc[a][b][c] = 0.f;

    prefetch(0, 0);
    asm volatile("cp.async.commit_group;");

    for (int it = 0; it < 16; it++) {
        const int cur = it & 1;
        asm volatile("cp.async.wait_group 0;");
        __syncthreads();
        if (it + 1 < 16) prefetch(cur ^ 1, it + 1);
        asm volatile("cp.async.commit_group;");

        const uint32_t stg = sb + cur * (OP_STAGE_U32 * 4);
        const uint32_t Ahb = stg;
        const uint32_t Alb = stg + OP_A_U32 * 4;
        const uint32_t Bhb = stg + 2 * OP_A_U32 * 4;
        const uint32_t Blb = Bhb + OP_B_U32 * 4;

        #pragma unroll
        for (int kk = 0; kk < 2; kk++) {
            uint32_t ah[2][4], al[2][4];
            const uint32_t aoff = (kk * 8 + ((mi >> 1) << 2)) * 4;
            #pragma unroll
            for (int mt = 0; mt < 2; mt++) {
                uint32_t arow = wm * 32 + mt * 16 + ((mi & 1) << 3) + ri;
                ldsm4(ah[mt], Ahb + arow * (GLD * 4) + aoff);
                ldsm4(al[mt], Alb + arow * (GLD * 4) + aoff);
            }
            uint32_t bh[4][2], bl[4][2];
            const uint32_t boffc = (kk * 8 + ((mi & 1) << 2)) * 4;
            #pragma unroll
            for (int pp = 0; pp < 2; pp++) {
                uint32_t brow = wn * 32 + pp * 16 + ((mi >> 1) << 3) + ri;
                uint32_t r[4];
                ldsm4(r, Bhb + brow * (GLD * 4) + boffc);
                bh[pp * 2][0] = r[0]; bh[pp * 2][1] = r[1];
                bh[pp * 2 + 1][0] = r[2]; bh[pp * 2 + 1][1] = r[3];
                ldsm4(r, Blb + brow * (GLD * 4) + boffc);
                bl[pp * 2][0] = r[0]; bl[pp * 2][1] = r[1];
                bl[pp * 2 + 1][0] = r[2]; bl[pp * 2 + 1][1] = r[3];
            }
            #pragma unroll
            for (int nt = 0; nt < 4; nt++)
                #pragma unroll
                for (int mt = 0; mt < 2; mt++)
                    mma16(acc[mt][nt], ah[mt], bl[nt]);
            #pragma unroll
            for (int nt = 0; nt < 4; nt++)
                #pragma unroll
                for (int mt = 0; mt < 2; mt++)
                    mma16(acc[mt][nt], al[mt], bh[nt]);
            #pragma unroll
            for (int nt = 0; nt < 4; nt++)
                #pragma unroll
                for (int mt = 0; mt < 2; mt++)
                    mma16(acc[mt][nt], ah[mt], bh[nt]);
        }
    }

    #pragma unroll
    for (int mt = 0; mt < 2; mt++)
        #pragma unroll
        for (int nt = 0; nt < 4; nt++)
            #pragma unroll
            for (int i = 0; i < 4; i++) {
                int mloc = wm * 32 + mt * 16 + r0 + ((i & 2) ? 8 : 0);
                int nloc = wn * 32 + nt * 8 + j2 + (i & 1);
                Outp[(size_t)(bm * 128 + mloc) * DIM + bn * 64 + nloc] = acc[mt][nt][i];
            }
}

// ===========================================================================
// Flash attention: LDSM for S-loop K frags; PV unchanged (LDS).
// ===========================================================================
#define AK_LD 36
#define AV_LD 72
#define AK_U32 (64 * AK_LD)
#define AV_U32 (32 * AV_LD)
#define ATTN_STAGE_U32 (2 * AK_U32 + 2 * AV_U32)
#define ATTN_SMEM (3 * ATTN_STAGE_U32 * 4)

__global__ __launch_bounds__(256, 2)
void attn_kernel()
{
    extern __shared__ uint32_t dsm[];
    const uint32_t sb = (uint32_t)__cvta_generic_to_shared(dsm);

    const int tid  = threadIdx.x;
    const int lane = tid & 31;
    const int warp = tid >> 5;
    const int qt   = blockIdx.x;
    const int pair = blockIdx.y;
    const int r0 = lane >> 2;
    const int j2 = 2 * (lane & 3);
    const int mi = lane >> 3, ri = lane & 7;

    const uint32_t* Qp  = g_Q + ((size_t)pair * QDIM + qt * 128 + warp * 16) * HD;
    const size_t kbase = (size_t)pair * GG * (HD / 2);
    const size_t vbase = (size_t)pair * (GG / 2) * HD;

    auto prefetch = [&](int st, int c) {
        uint32_t base = sb + st * (ATTN_STAGE_U32 * 4);
        #pragma unroll
        for (int j = 0; j < 2; j++) {
            int idx = tid + j * 256;
            int row = idx >> 3, seg = idx & 7;
            cpa16(base + row * (AK_LD * 4) + seg * 16,
                  g_Kh + kbase + (size_t)(c * 64 + row) * (HD / 2) + seg * 4);
            cpa16(base + AK_U32 * 4 + row * (AK_LD * 4) + seg * 16,
                  g_Kl + kbase + (size_t)(c * 64 + row) * (HD / 2) + seg * 4);
        }
        #pragma unroll
        for (int j = 0; j < 2; j++) {
            int idx = tid + j * 256;
            int row = idx >> 4, seg = idx & 15;
            cpa16(base + 2 * AK_U32 * 4 + row * (AV_LD * 4) + seg * 16,
                  g_V2h + vbase + (size_t)(c * 32 + row) * HD + seg * 4);
            cpa16(base + (2 * AK_U32 + AV_U32) * 4 + row * (AV_LD * 4) + seg * 16,
                  g_V2l + vbase + (size_t)(c * 32 + row) * HD + seg * 4);
        }
    };

    uint32_t qh[4][4], ql[4][4];
    #pragma unroll
    for (int kk = 0; kk < 4; kk++) {
        int d0 = kk * 16 + j2;
        uint2 w01 = *reinterpret_cast<const uint2*>(Qp + (size_t)r0 * HD + d0);
        uint2 w23 = *reinterpret_cast<const uint2*>(Qp + (size_t)(r0 + 8) * HD + d0);
        uint2 w45 = *reinterpret_cast<const uint2*>(Qp + (size_t)r0 * HD + d0 + 8);
        uint2 w67 = *reinterpret_cast<const uint2*>(Qp + (size_t)(r0 + 8) * HD + d0 + 8);
        qh[kk][0] = h2scale8(HI_PAIR(w01.x, w01.y)); ql[kk][0] = h2scale8(LO_PAIR(w01.x, w01.y));
        qh[kk][1] = h2scale8(HI_PAIR(w23.x, w23.y)); ql[kk][1] = h2scale8(LO_PAIR(w23.x, w23.y));
        qh[kk][2] = h2scale8(HI_PAIR(w45.x, w45.y)); ql[kk][2] = h2scale8(LO_PAIR(w45.x, w45.y));
        qh[kk][3] = h2scale8(HI_PAIR(w67.x, w67.y)); ql[kk][3] = h2scale8(LO_PAIR(w67.x, w67.y));
    }

    float oacc[8][4];
    #pragma unroll
    for (int t = 0; t < 8; t++)
        #pragma unroll
        for (int i = 0; i < 4; i++) oacc[t][i] = 0.f;
    float m0 = -1e30f, m1 = -1e30f, l0 = 0.f, l1 = 0.f;

    prefetch(0, 0);
    asm volatile("cp.async.commit_group;");
    prefetch(1, 1);
    asm volatile("cp.async.commit_group;");

    for (int c = 0; c < NCHUNK; c++) {
        asm volatile("cp.async.wait_group 1;");
        __syncthreads();
        if (c + 2 < NCHUNK) prefetch((c + 2) % 3, c + 2);
        asm volatile("cp.async.commit_group;");

        const uint32_t stg = sb + (c % 3) * (ATTN_STAGE_U32 * 4);
        const uint32_t Khb = stg;
        const uint32_t Klb = stg + AK_U32 * 4;
        const uint32_t* Vh = dsm + (c % 3) * ATTN_STAGE_U32 + 2 * AK_U32;
        const uint32_t* Vl = Vh + AV_U32;

        float sacc[8][4];
        #pragma unroll
        for (int t = 0; t < 8; t++)
            #pragma unroll
            for (int i = 0; i < 4; i++) sacc[t][i] = 0.f;

        // S = Q @ K^T : LDSM K-frags, breadth-first groups of 4
        #pragma unroll
        for (int kk = 0; kk < 4; kk++) {
            const uint32_t goff = (kk * 8 + ((mi & 1) << 2)) * 4;
            #pragma unroll
            for (int g = 0; g < 2; g++) {
                uint32_t bh[4][2], bl[4][2];
                #pragma unroll
                for (int tp = 0; tp < 2; tp++) {
                    uint32_t grow = (g * 4 + tp * 2) * 8 + ((mi >> 1) << 3) + ri;
                    uint32_t r[4];
                    ldsm4(r, Khb + grow * (AK_LD * 4) + goff);
                    bh[tp * 2][0] = r[0]; bh[tp * 2][1] = r[1];
                    bh[tp * 2 + 1][0] = r[2]; bh[tp * 2 + 1][1] = r[3];
                    ldsm4(r, Klb + grow * (AK_LD * 4) + goff);
                    bl[tp * 2][0] = r[0]; bl[tp * 2][1] = r[1];
                    bl[tp * 2 + 1][0] = r[2]; bl[tp * 2 + 1][1] = r[3];
                }
                #pragma unroll
                for (int t = 0; t < 4; t++) mma16(sacc[g * 4 + t], qh[kk], bl[t]);
                #pragma unroll
                for (int t = 0; t < 4; t++) mma16(sacc[g * 4 + t], ql[kk], bh[t]);
                #pragma unroll
                for (int t = 0; t < 4; t++) mma16(sacc[g * 4 + t], qh[kk], bh[t]);
            }
        }

        float mx0 = -1e30f, mx1 = -1e30f;
        #pragma unroll
        for (int t = 0; t < 8; t++) {
            mx0 = fmaxf(mx0, fmaxf(sacc[t][0], sacc[t][1]));
            mx1 = fmaxf(mx1, fmaxf(sacc[t][2], sacc[t][3]));
        }
        mx0 = fmaxf(mx0, __shfl_xor_sync(0xffffffffu, mx0, 1));
        mx0 = fmaxf(mx0, __shfl_xor_sync(0xffffffffu, mx0, 2));
        mx1 = fmaxf(mx1, __shfl_xor_sync(0xffffffffu, mx1, 1));
        mx1 = fmaxf(mx1, __shfl_xor_sync(0xffffffffu, mx1, 2));

        float mn0 = fmaxf(m0, mx0), mn1 = fmaxf(m1, mx1);
        float al0 = __expf(m0 - mn0), al1 = __expf(m1 - mn1);
        float s0 = 0.f, s1 = 0.f;
        #pragma unroll
        for (int t = 0; t < 8; t++) {
            sacc[t][0] = __expf(sacc[t][0] - mn0);
            sacc[t][1] = __expf(sacc[t][1] - mn0);
            sacc[t][2] = __expf(sacc[t][2] - mn1);
            sacc[t][3] = __expf(sacc[t][3] - mn1);
            s0 += sacc[t][0] + sacc[t][1];
            s1 += sacc[t][2] + sacc[t][3];
        }
        s0 += __shfl_xor_sync(0xffffffffu, s0, 1);
        s0 += __shfl_xor_sync(0xffffffffu, s0, 2);
        s1 += __shfl_xor_sync(0xffffffffu, s1, 1);
        s1 += __shfl_xor_sync(0xffffffffu, s1, 2);
        l0 = l0 * al0 + s0;
        l1 = l1 * al1 + s1;
        m0 = mn0; m1 = mn1;
        #pragma unroll
        for (int nt = 0; nt < 8; nt++) {
            oacc[nt][0] *= al0; oacc[nt][1] *= al0;
            oacc[nt][2] *= al1; oacc[nt][3] *= al1;
        }

        // O += P @ V : breadth-first groups of 4 (LDS; pair lies along k)
        #pragma unroll
        for (int kk = 0; kk < 4; kk++) {
            uint32_t pah[4], pal[4];
            psplit2(sacc[2 * kk][0],     sacc[2 * kk][1],     pah[0], pal[0]);
            psplit2(sacc[2 * kk][2],     sacc[2 * kk][3],     pah[1], pal[1]);
            psplit2(sacc[2 * kk + 1][0], sacc[2 * kk + 1][1], pah[2], pal[2]);
            psplit2(sacc[2 * kk + 1][2], sacc[2 * kk + 1][3], pah[3], pal[3]);
            int gp = kk * 8 + (lane & 3);
            #pragma unroll
            for (int g = 0; g < 2; g++) {
                uint32_t bh[4][2], bl[4][2];
                #pragma unroll
                for (int t = 0; t < 4; t++) {
                    int d = (g * 4 + t) * 8 + r0;
                    bh[t][0] = Vh[gp * AV_LD + d]; bh[t][1] = Vh[(gp + 4) * AV_LD + d];
                    bl[t][0] = Vl[gp * AV_LD + d]; bl[t][1] = Vl[(gp + 4) * AV_LD + d];
                }
                #pragma unroll
                for (int t = 0; t < 4; t++) mma16(oacc[g * 4 + t], pah, bl[t]);
                #pragma unroll
                for (int t = 0; t < 4; t++) mma16(oacc[g * 4 + t], pal, bh[t]);
                #pragma unroll
                for (int t = 0; t < 4; t++) mma16(oacc[g * 4 + t], pah, bh[t]);
            }
        }
    }

    float inv0 = 1.f / l0, inv1 = 1.f / l1;
    int h = pair >> 3, b = pair & 7;
    #pragma unroll
    for (int nt = 0; nt < 8; nt++) {
        int q = qt * 128 + warp * 16 + r0;
        int dp = h * 32 + nt * 4 + (lane & 3);
        uint32_t h0, l0u, h1, l1u;
        psplit2(oacc[nt][0] * inv0, oacc[nt][1] * inv0, h0, l0u);
        psplit2(oacc[nt][2] * inv1, oacc[nt][3] * inv1, h1, l1u);
        size_t o = ((size_t)(b * QDIM + q)) * (DIM / 2) + dp;
        g_Hdh[o] = h0; g_Hdl[o] = l0u;
        g_Hdh[o + 8 * (DIM / 2)] = h1; g_Hdl[o + 8 * (DIM / 2)] = l1u;
    }
}

extern "C" void kernel_launch(void* const* d_in, const int* in_sizes, int n_in,
                              void* d_out, int out_size)
{
    (void)in_sizes; (void)n_in; (void)out_size;
    const float* q  = (const float*)d_in[0];
    const float* Wq = (const float*)d_in[1];
    const float* Wk = (const float*)d_in[2];
    const float* Wv = (const float*)d_in[3];
    const float* Wo = (const float*)d_in[4];
    float* out = (float*)d_out;

    static bool attrs_set = false;
    if (!attrs_set) {
        cudaFuncSetAttribute(qkv_kernel,   cudaFuncAttributeMaxDynamicSharedMemorySize, QKV_SMEM);
        cudaFuncSetAttribute(attn_kernel,  cudaFuncAttributeMaxDynamicSharedMemorySize, ATTN_SMEM);
        cudaFuncSetAttribute(oproj_kernel, cudaFuncAttributeMaxDynamicSharedMemorySize, OP_SMEM);
        attrs_set = true;
    }

    splitx_kernel<<<16384, 256>>>(q);
    splitw_qkv_kernel<<<1536, 256>>>(Wq, Wk, Wv);
    splitw_o_kernel<<<512, 256>>>(Wo);
    qkv_kernel<<<dim3(8, 256), 256, QKV_SMEM>>>();
    attn_kernel<<<dim3(4, 64), 256, ATTN_SMEM>>>();
    oproj_kernel<<<dim3(8, 32), 256, OP_SMEM>>>(out);
}

// round 15
// speedup vs baseline: 1.2329x; 1.0050x over previous
#include <cuda_runtime.h>
#include <cuda_fp16.h>
#include <cstdint>

#define BATCH 8
#define TT    4096
#define DIM   512
#define NH    8
#define HD    64
#define QDIM  512
#define GG    3584
#define NCHUNK 56

// ---- global scratch (u32 = half2 of adjacent elements of ONE plane) ----
__device__ __align__(256) uint32_t g_Q  [(size_t)NH*BATCH*QDIM*HD];
__device__ __align__(256) uint32_t g_Kh [(size_t)NH*BATCH*GG*(HD/2)];
__device__ __align__(256) uint32_t g_Kl [(size_t)NH*BATCH*GG*(HD/2)];
__device__ __align__(256) uint32_t g_V2th[(size_t)NH*BATCH*HD*(GG/2)];  // [pair][d][gpair]
__device__ __align__(256) uint32_t g_V2tl[(size_t)NH*BATCH*HD*(GG/2)];
__device__ __align__(256) uint32_t g_Hdh[(size_t)BATCH*QDIM*(DIM/2)];
__device__ __align__(256) uint32_t g_Hdl[(size_t)BATCH*QDIM*(DIM/2)];
__device__ __align__(256) uint32_t g_Xh [(size_t)BATCH*TT*(DIM/2)];
__device__ __align__(256) uint32_t g_Xl [(size_t)BATCH*TT*(DIM/2)];
__device__ __align__(256) uint32_t g_Wth[(size_t)3*NH*HD*(DIM/2)];
__device__ __align__(256) uint32_t g_Wtl[(size_t)3*NH*HD*(DIM/2)];
__device__ __align__(256) uint32_t g_Woth[(size_t)DIM*(DIM/2)];
__device__ __align__(256) uint32_t g_Wotl[(size_t)DIM*(DIM/2)];

__device__ __forceinline__ uint32_t packsplit(float v) {
    __half h = __float2half_rn(v);
    __half l = __float2half_rn(v - __half2float(h));
    return (uint32_t)__half_as_ushort(h) | ((uint32_t)__half_as_ushort(l) << 16);
}
__device__ __forceinline__ void psplit2(float p0, float p1, uint32_t& hi, uint32_t& lo) {
    __half2 h = __floats2half2_rn(p0, p1);
    float2 hf = __half22float2(h);
    __half2 l = __floats2half2_rn(p0 - hf.x, p1 - hf.y);
    hi = *reinterpret_cast<uint32_t*>(&h);
    lo = *reinterpret_cast<uint32_t*>(&l);
}
__device__ __forceinline__ uint32_t h2scale8(uint32_t a) {   // *=0.125 exact
    __half2 s = __float2half2_rn(0.125f);
    __half2 r = __hmul2(*reinterpret_cast<__half2*>(&a), s);
    return *reinterpret_cast<uint32_t*>(&r);
}
#define HI_PAIR(v0, v1) __byte_perm((v0), (v1), 0x5410)
#define LO_PAIR(v0, v1) __byte_perm((v0), (v1), 0x7632)

__device__ __forceinline__ void mma16(float* c, const uint32_t* a, const uint32_t* b) {
    asm volatile(
        "mma.sync.aligned.m16n8k16.row.col.f32.f16.f16.f32 "
        "{%0,%1,%2,%3},{%4,%5,%6,%7},{%8,%9},{%0,%1,%2,%3};"
        : "+f"(c[0]), "+f"(c[1]), "+f"(c[2]), "+f"(c[3])
        : "r"(a[0]), "r"(a[1]), "r"(a[2]), "r"(a[3]), "r"(b[0]), "r"(b[1]));
}
__device__ __forceinline__ void cpa16(uint32_t dst, const void* src) {
    asm volatile("cp.async.cg.shared.global [%0], [%1], 16;" :: "r"(dst), "l"(src));
}
__device__ __forceinline__ void ldsm4(uint32_t* r, uint32_t saddr) {
    asm volatile("ldmatrix.sync.aligned.m8n8.x4.shared.b16 {%0,%1,%2,%3}, [%4];"
        : "=r"(r[0]), "=r"(r[1]), "=r"(r[2]), "=r"(r[3]) : "r"(saddr));
}

// ===========================================================================
// Prep kernels
// ===========================================================================
__global__ __launch_bounds__(256) void splitx_kernel(const float* __restrict__ X) {
    int i = blockIdx.x * 256 + threadIdx.x;
    float4 v = reinterpret_cast<const float4*>(X)[i];
    uint32_t h0, l0, h1, l1;
    psplit2(v.x, v.y, h0, l0);
    psplit2(v.z, v.w, h1, l1);
    g_Xh[2 * i] = h0; g_Xh[2 * i + 1] = h1;
    g_Xl[2 * i] = l0; g_Xl[2 * i + 1] = l1;
}
__global__ __launch_bounds__(256) void splitw_qkv_kernel(const float* __restrict__ Wq,
                                                         const float* __restrict__ Wk,
                                                         const float* __restrict__ Wv) {
    int idx = blockIdx.x * 256 + threadIdx.x;
    int kp = idx & 255, n = (idx >> 8) & 63, h = (idx >> 14) & 7, w = idx >> 17;
    const float* W = (w == 0) ? Wq : (w == 1) ? Wk : Wv;
    const float* b = W + ((size_t)h * DIM + 2 * kp) * HD + n;
    uint32_t hi, lo;
    psplit2(b[0], b[HD], hi, lo);
    g_Wth[idx] = hi; g_Wtl[idx] = lo;
}
__global__ __launch_bounds__(256) void splitw_o_kernel(const float* __restrict__ Wo) {
    int idx = blockIdx.x * 256 + threadIdx.x;
    int kp = idx & 255, n = idx >> 8;
    const float* b = Wo + (size_t)(2 * kp) * DIM + n;
    uint32_t hi, lo;
    psplit2(b[0], b[DIM], hi, lo);
    g_Woth[idx] = hi; g_Wotl[idx] = lo;
}

// ===========================================================================
// QKV projection: K-chunk 32, 2-stage, 16 iters, 1 bar/iter, LDSM frags.
// ===========================================================================
#define GLD 20
#define QKV_A_U32 (128 * GLD)
#define QKV_B_U32 (64 * GLD)
#define QKV_STAGE_U32 (2 * QKV_A_U32 + 4 * QKV_B_U32)
#define QKV_SMEM (2 * QKV_STAGE_U32 * 4)

__global__ __launch_bounds__(256, 2)
void qkv_kernel()
{
    extern __shared__ uint32_t dsm[];
    const uint32_t sb = (uint32_t)__cvta_generic_to_shared(dsm);

    const int tid  = threadIdx.x;
    const int lane = tid & 31;
    const int warp = tid >> 5;
    const int wm   = warp >> 1;
    const int wn   = warp & 1;
    const int bn   = blockIdx.x;
    const int bm   = blockIdx.y;
    const bool isQ = bm >= 224;
    const int r0 = lane >> 2;
    const int j2 = 2 * (lane & 3);
    const int mi = lane >> 3, ri = lane & 7;

    int bidx, t0, rowoff, w0sel, w1sel;
    if (isQ) {
        int qbm = bm - 224;
        bidx = qbm >> 2; t0 = (qbm & 3) * 128; rowoff = 0; w0sel = 0; w1sel = 0;
    } else {
        bidx = bm / 28; t0 = (bm % 28) * 128; rowoff = QDIM; w0sel = 1; w1sel = 2;
    }
    const int nw = isQ ? 1 : 2;

    const uint32_t* Xhp = g_Xh + ((size_t)bidx * TT + rowoff + t0) * (DIM / 2);
    const uint32_t* Xlp = g_Xl + ((size_t)bidx * TT + rowoff + t0) * (DIM / 2);
    const size_t wb0 = ((size_t)(w0sel * NH + bn)) * HD * (DIM / 2);
    const size_t wb1 = ((size_t)(w1sel * NH + bn)) * HD * (DIM / 2);

    auto prefetch = [&](int st, int c) {
        uint32_t base = sb + st * (QKV_STAGE_U32 * 4);
        #pragma unroll
        for (int j = 0; j < 4; j++) {
            int idx = tid + j * 256;
            int p = idx >> 9, rem = idx & 511;
            int row = rem >> 2, seg = rem & 3;
            cpa16(base + p * (QKV_A_U32 * 4) + row * (GLD * 4) + seg * 16,
                  (p ? Xlp : Xhp) + (size_t)row * (DIM / 2) + c * 16 + seg * 4);
        }
        #pragma unroll
        for (int j = 0; j < 4; j++) {
            int idx = tid + j * 256;
            int w = idx >> 9, rem = idx & 511;
            int p = rem >> 8, r2 = rem & 255;
            int row = r2 >> 2, seg = r2 & 3;
            if (w < nw) {
                const uint32_t* src = (p ? g_Wtl : g_Wth) + (w ? wb1 : wb0)
                                      + (size_t)row * (DIM / 2) + c * 16 + seg * 4;
                cpa16(base + (2 * QKV_A_U32 + (w * 2 + p) * QKV_B_U32) * 4
                           + row * (GLD * 4) + seg * 16, src);
            }
        }
    };

    float acc[2][2][4][4];
    #pragma unroll
    for (int w = 0; w < 2; w++)
        #pragma unroll
        for (int a = 0; a < 2; a++)
            #pragma unroll
            for (int b = 0; b < 4; b++)
                #pragma unroll
                for (int c = 0; c < 4; c++) acc[w][a][b][c] = 0.f;

    prefetch(0, 0);
    asm volatile("cp.async.commit_group;");

    for (int it = 0; it < 16; it++) {
        const int cur = it & 1;
        asm volatile("cp.async.wait_group 0;");
        __syncthreads();
        if (it + 1 < 16) prefetch(cur ^ 1, it + 1);
        asm volatile("cp.async.commit_group;");

        const uint32_t stg = sb + cur * (QKV_STAGE_U32 * 4);
        const uint32_t Ahb = stg;
        const uint32_t Alb = stg + QKV_A_U32 * 4;
        const uint32_t Bbb = stg + 2 * QKV_A_U32 * 4;

        #pragma unroll
        for (int kk = 0; kk < 2; kk++) {
            uint32_t ah[2][4], al[2][4];
            const uint32_t aoff = (kk * 8 + ((mi >> 1) << 2)) * 4;
            #pragma unroll
            for (int mt = 0; mt < 2; mt++) {
                uint32_t arow = wm * 32 + mt * 16 + ((mi & 1) << 3) + ri;
                ldsm4(ah[mt], Ahb + arow * (GLD * 4) + aoff);
                ldsm4(al[mt], Alb + arow * (GLD * 4) + aoff);
            }
            uint32_t bh[4][2][2], bl[4][2][2];
            const uint32_t boffc = (kk * 8 + ((mi & 1) << 2)) * 4;
            #pragma unroll
            for (int pp = 0; pp < 2; pp++) {
                uint32_t brow = wn * 32 + pp * 16 + ((mi >> 1) << 3) + ri;
                #pragma unroll
                for (int w = 0; w < 2; w++)
                    if (w < nw) {
                        uint32_t r[4];
                        ldsm4(r, Bbb + (w * 2 + 0) * (QKV_B_U32 * 4) + brow * (GLD * 4) + boffc);
                        bh[pp * 2][w][0] = r[0]; bh[pp * 2][w][1] = r[1];
                        bh[pp * 2 + 1][w][0] = r[2]; bh[pp * 2 + 1][w][1] = r[3];
                        ldsm4(r, Bbb + (w * 2 + 1) * (QKV_B_U32 * 4) + brow * (GLD * 4) + boffc);
                        bl[pp * 2][w][0] = r[0]; bl[pp * 2][w][1] = r[1];
                        bl[pp * 2 + 1][w][0] = r[2]; bl[pp * 2 + 1][w][1] = r[3];
                    }
            }
            #pragma unroll
            for (int nt = 0; nt < 4; nt++)
                #pragma unroll
                for (int w = 0; w < 2; w++)
                    if (w < nw)
                        #pragma unroll
                        for (int mt = 0; mt < 2; mt++)
                            mma16(acc[w][mt][nt], ah[mt], bl[nt][w]);
            #pragma unroll
            for (int nt = 0; nt < 4; nt++)
                #pragma unroll
                for (int w = 0; w < 2; w++)
                    if (w < nw)
                        #pragma unroll
                        for (int mt = 0; mt < 2; mt++)
                            mma16(acc[w][mt][nt], al[mt], bh[nt][w]);
            #pragma unroll
            for (int nt = 0; nt < 4; nt++)
                #pragma unroll
                for (int w = 0; w < 2; w++)
                    if (w < nw)
                        #pragma unroll
                        for (int mt = 0; mt < 2; mt++)
                            mma16(acc[w][mt][nt], ah[mt], bh[nt][w]);
        }
    }

    // Epilogues
    if (isQ) {
        #pragma unroll
        for (int mt = 0; mt < 2; mt++)
            #pragma unroll
            for (int nt = 0; nt < 4; nt++)
                #pragma unroll
                for (int i = 0; i < 4; i++) {
                    int mloc = wm * 32 + mt * 16 + r0 + ((i & 2) ? 8 : 0);
                    int nloc = wn * 32 + nt * 8 + j2 + (i & 1);
                    g_Q[(((size_t)(bn * BATCH + bidx)) * QDIM + t0 + mloc) * HD + nloc] =
                        packsplit(acc[0][mt][nt][i]);
                }
    } else {
        const size_t pb = (size_t)(bn * BATCH + bidx);
        #pragma unroll
        for (int mt = 0; mt < 2; mt++)
            #pragma unroll
            for (int nt = 0; nt < 4; nt++) {
                int grow = t0 + wm * 32 + mt * 16 + r0;
                int dp = wn * 16 + nt * 4 + (lane & 3);
                uint32_t h0, l0, h1, l1;
                psplit2(acc[0][mt][nt][0], acc[0][mt][nt][1], h0, l0);
                psplit2(acc[0][mt][nt][2], acc[0][mt][nt][3], h1, l1);
                size_t kb = (pb * GG + grow) * (HD / 2) + dp;
                g_Kh[kb] = h0; g_Kl[kb] = l0;
                g_Kh[kb + 8 * (HD / 2)] = h1; g_Kl[kb + 8 * (HD / 2)] = l1;
                uint32_t p0 = packsplit(acc[1][mt][nt][0]);
                uint32_t p1 = packsplit(acc[1][mt][nt][1]);
                uint32_t p2 = packsplit(acc[1][mt][nt][2]);
                uint32_t p3 = packsplit(acc[1][mt][nt][3]);
                uint32_t q0 = __shfl_down_sync(0xffffffffu, p0, 4);
                uint32_t q1 = __shfl_down_sync(0xffffffffu, p1, 4);
                uint32_t q2 = __shfl_down_sync(0xffffffffu, p2, 4);
                uint32_t q3 = __shfl_down_sync(0xffffffffu, p3, 4);
                if ((r0 & 1) == 0) {
                    int d0 = wn * 32 + nt * 8 + j2;
                    // transposed layout [pair][d][gpair]
                    size_t vb = ((size_t)pb * HD + d0) * (GG / 2) + (grow >> 1);
                    g_V2th[vb] = HI_PAIR(p0, q0);
                    g_V2tl[vb] = LO_PAIR(p0, q0);
                    g_V2th[vb + (GG / 2)] = HI_PAIR(p1, q1);
                    g_V2tl[vb + (GG / 2)] = LO_PAIR(p1, q1);
                    g_V2th[vb + 4] = HI_PAIR(p2, q2);
                    g_V2tl[vb + 4] = LO_PAIR(p2, q2);
                    g_V2th[vb + (GG / 2) + 4] = HI_PAIR(p3, q3);
                    g_V2tl[vb + (GG / 2) + 4] = LO_PAIR(p3, q3);
                }
            }
    }
}

// ===========================================================================
// Out projection: K-chunk 32, 2-stage, 16 iters, 1 bar/iter, LDSM frags.
// (UNCHANGED from round 14)
// ===========================================================================
#define OP_A_U32 (128 * GLD)
#define OP_B_U32 (64 * GLD)
#define OP_STAGE_U32 (2 * OP_A_U32 + 2 * OP_B_U32)
#define OP_SMEM (2 * OP_STAGE_U32 * 4)

__global__ __launch_bounds__(256, 2)
void oproj_kernel(float* __restrict__ Outp)
{
    extern __shared__ uint32_t dsm[];
    const uint32_t sb = (uint32_t)__cvta_generic_to_shared(dsm);

    const int tid  = threadIdx.x;
    const int lane = tid & 31;
    const int warp = tid >> 5;
    const int wm   = warp >> 1;
    const int wn   = warp & 1;
    const int bm   = blockIdx.y;
    const int bn   = blockIdx.x;
    const int r0 = lane >> 2;
    const int j2 = 2 * (lane & 3);
    const int mi = lane >> 3, ri = lane & 7;

    const size_t arow_g = (size_t)bm * 128;
    const size_t brow_g = (size_t)bn * 64;

    auto prefetch = [&](int st, int c) {
        uint32_t base = sb + st * (OP_STAGE_U32 * 4);
        #pragma unroll
        for (int j = 0; j < 4; j++) {
            int idx = tid + j * 256;
            int p = idx >> 9, rem = idx & 511;
            int row = rem >> 2, seg = rem & 3;
            cpa16(base + p * (OP_A_U32 * 4) + row * (GLD * 4) + seg * 16,
                  (p ? g_Hdl : g_Hdh) + (arow_g + row) * (DIM / 2) + c * 16 + seg * 4);
        }
        #pragma unroll
        for (int j = 0; j < 2; j++) {
            int idx = tid + j * 256;
            int p = idx >> 8, rem = idx & 255;
            int row = rem >> 2, seg = rem & 3;
            cpa16(base + (2 * OP_A_U32 + p * OP_B_U32) * 4 + row * (GLD * 4) + seg * 16,
                  (p ? g_Wotl : g_Woth) + (brow_g + row) * (DIM / 2) + c * 16 + seg * 4);
        }
    };

    float acc[2][4][4];
    #pragma unroll
    for (int a = 0; a < 2; a++)
        #pragma unroll
        for (int b = 0; b < 4; b++)
            #pragma unroll
            for (int c = 0; c < 4; c++) acc[a][b][c] = 0.f;

    prefetch(0, 0);
    asm volatile("cp.async.commit_group;");

    for (int it = 0; it < 16; it++) {
        const int cur = it & 1;
        asm volatile("cp.async.wait_group 0;");
        __syncthreads();
        if (it + 1 < 16) prefetch(cur ^ 1, it + 1);
        asm volatile("cp.async.commit_group;");

        const uint32_t stg = sb + cur * (OP_STAGE_U32 * 4);
        const uint32_t Ahb = stg;
        const uint32_t Alb = stg + OP_A_U32 * 4;
        const uint32_t Bhb = stg + 2 * OP_A_U32 * 4;
        const uint32_t Blb = Bhb + OP_B_U32 * 4;

        #pragma unroll
        for (int kk = 0; kk < 2; kk++) {
            uint32_t ah[2][4], al[2][4];
            const uint32_t aoff = (kk * 8 + ((mi >> 1) << 2)) * 4;
            #pragma unroll
            for (int mt = 0; mt < 2; mt++) {
                uint32_t arow = wm * 32 + mt * 16 + ((mi & 1) << 3) + ri;
                ldsm4(ah[mt], Ahb + arow * (GLD * 4) + aoff);
                ldsm4(al[mt], Alb + arow * (GLD * 4) + aoff);
            }
            uint32_t bh[4][2], bl[4][2];
            const uint32_t boffc = (kk * 8 + ((mi & 1) << 2)) * 4;
            #pragma unroll
            for (int pp = 0; pp < 2; pp++) {
                uint32_t brow = wn * 32 + pp * 16 + ((mi >> 1) << 3) + ri;
                uint32_t r[4];
                ldsm4(r, Bhb + brow * (GLD * 4) + boffc);
                bh[pp * 2][0] = r[0]; bh[pp * 2][1] = r[1];
                bh[pp * 2 + 1][0] = r[2]; bh[pp * 2 + 1][1] = r[3];
                ldsm4(r, Blb + brow * (GLD * 4) + boffc);
                bl[pp * 2][0] = r[0]; bl[pp * 2][1] = r[1];
                bl[pp * 2 + 1][0] = r[2]; bl[pp * 2 + 1][1] = r[3];
            }
            #pragma unroll
            for (int nt = 0; nt < 4; nt++)
                #pragma unroll
                for (int mt = 0; mt < 2; mt++)
                    mma16(acc[mt][nt], ah[mt], bl[nt]);
            #pragma unroll
            for (int nt = 0; nt < 4; nt++)
                #pragma unroll
                for (int mt = 0; mt < 2; mt++)
                    mma16(acc[mt][nt], al[mt], bh[nt]);
            #pragma unroll
            for (int nt = 0; nt < 4; nt++)
                #pragma unroll
                for (int mt = 0; mt < 2; mt++)
                    mma16(acc[mt][nt], ah[mt], bh[nt]);
        }
    }

    #pragma unroll
    for (int mt = 0; mt < 2; mt++)
        #pragma unroll
        for (int nt = 0; nt < 4; nt++)
            #pragma unroll
            for (int i = 0; i < 4; i++) {
                int mloc = wm * 32 + mt * 16 + r0 + ((i & 2) ? 8 : 0);
                int nloc = wn * 32 + nt * 8 + j2 + (i & 1);
                Outp[(size_t)(bm * 128 + mloc) * DIM + bn * 64 + nloc] = acc[mt][nt][i];
            }
}

// ===========================================================================
// Flash attention: LDSM for BOTH S-loop K frags and PV-loop V frags
// (V now stored transposed [d][gpair]).
// ===========================================================================
#define AK_LD 36
#define VT_LD 36
#define AK_U32 (64 * AK_LD)
#define VT_U32 (64 * VT_LD)
#define ATTN_STAGE_U32 (2 * AK_U32 + 2 * VT_U32)
#define ATTN_SMEM (3 * ATTN_STAGE_U32 * 4)

__global__ __launch_bounds__(256, 2)
void attn_kernel()
{
    extern __shared__ uint32_t dsm[];
    const uint32_t sb = (uint32_t)__cvta_generic_to_shared(dsm);

    const int tid  = threadIdx.x;
    const int lane = tid & 31;
    const int warp = tid >> 5;
    const int qt   = blockIdx.x;
    const int pair = blockIdx.y;
    const int r0 = lane >> 2;
    const int j2 = 2 * (lane & 3);
    const int mi = lane >> 3, ri = lane & 7;

    const uint32_t* Qp  = g_Q + ((size_t)pair * QDIM + qt * 128 + warp * 16) * HD;
    const size_t kbase = (size_t)pair * GG * (HD / 2);
    const size_t vtbase = (size_t)pair * HD * (GG / 2);

    auto prefetch = [&](int st, int c) {
        uint32_t base = sb + st * (ATTN_STAGE_U32 * 4);
        #pragma unroll
        for (int j = 0; j < 2; j++) {          // K planes: 64 rows x 8 segs
            int idx = tid + j * 256;
            int row = idx >> 3, seg = idx & 7;
            cpa16(base + row * (AK_LD * 4) + seg * 16,
                  g_Kh + kbase + (size_t)(c * 64 + row) * (HD / 2) + seg * 4);
            cpa16(base + AK_U32 * 4 + row * (AK_LD * 4) + seg * 16,
                  g_Kl + kbase + (size_t)(c * 64 + row) * (HD / 2) + seg * 4);
        }
        #pragma unroll
        for (int j = 0; j < 2; j++) {          // Vt planes: 64 d-rows x 8 segs
            int idx = tid + j * 256;
            int row = idx >> 3, seg = idx & 7;
            cpa16(base + 2 * AK_U32 * 4 + row * (VT_LD * 4) + seg * 16,
                  g_V2th + vtbase + (size_t)row * (GG / 2) + c * 32 + seg * 4);
            cpa16(base + (2 * AK_U32 + VT_U32) * 4 + row * (VT_LD * 4) + seg * 16,
                  g_V2tl + vtbase + (size_t)row * (GG / 2) + c * 32 + seg * 4);
        }
    };

    uint32_t qh[4][4], ql[4][4];
    #pragma unroll
    for (int kk = 0; kk < 4; kk++) {
        int d0 = kk * 16 + j2;
        uint2 w01 = *reinterpret_cast<const uint2*>(Qp + (size_t)r0 * HD + d0);
        uint2 w23 = *reinterpret_cast<const uint2*>(Qp + (size_t)(r0 + 8) * HD + d0);
        uint2 w45 = *reinterpret_cast<const uint2*>(Qp + (size_t)r0 * HD + d0 + 8);
        uint2 w67 = *reinterpret_cast<const uint2*>(Qp + (size_t)(r0 + 8) * HD + d0 + 8);
        qh[kk][0] = h2scale8(HI_PAIR(w01.x, w01.y)); ql[kk][0] = h2scale8(LO_PAIR(w01.x, w01.y));
        qh[kk][1] = h2scale8(HI_PAIR(w23.x, w23.y)); ql[kk][1] = h2scale8(LO_PAIR(w23.x, w23.y));
        qh[kk][2] = h2scale8(HI_PAIR(w45.x, w45.y)); ql[kk][2] = h2scale8(LO_PAIR(w45.x, w45.y));
        qh[kk][3] = h2scale8(HI_PAIR(w67.x, w67.y)); ql[kk][3] = h2scale8(LO_PAIR(w67.x, w67.y));
    }

    float oacc[8][4];
    #pragma unroll
    for (int t = 0; t < 8; t++)
        #pragma unroll
        for (int i = 0; i < 4; i++) oacc[t][i] = 0.f;
    float m0 = -1e30f, m1 = -1e30f, l0 = 0.f, l1 = 0.f;

    prefetch(0, 0);
    asm volatile("cp.async.commit_group;");
    prefetch(1, 1);
    asm volatile("cp.async.commit_group;");

    for (int c = 0; c < NCHUNK; c++) {
        asm volatile("cp.async.wait_group 1;");
        __syncthreads();
        if (c + 2 < NCHUNK) prefetch((c + 2) % 3, c + 2);
        asm volatile("cp.async.commit_group;");

        const uint32_t stg = sb + (c % 3) * (ATTN_STAGE_U32 * 4);
        const uint32_t Khb = stg;
        const uint32_t Klb = stg + AK_U32 * 4;
        const uint32_t Vthb = stg + 2 * AK_U32 * 4;
        const uint32_t Vtlb = Vthb + VT_U32 * 4;

        float sacc[8][4];
        #pragma unroll
        for (int t = 0; t < 8; t++)
            #pragma unroll
            for (int i = 0; i < 4; i++) sacc[t][i] = 0.f;

        // S = Q @ K^T : LDSM K-frags, breadth-first groups of 4
        #pragma unroll
        for (int kk = 0; kk < 4; kk++) {
            const uint32_t goff = (kk * 8 + ((mi & 1) << 2)) * 4;
            #pragma unroll
            for (int g = 0; g < 2; g++) {
                uint32_t bh[4][2], bl[4][2];
                #pragma unroll
                for (int tp = 0; tp < 2; tp++) {
                    uint32_t grow = (g * 4 + tp * 2) * 8 + ((mi >> 1) << 3) + ri;
                    uint32_t r[4];
                    ldsm4(r, Khb + grow * (AK_LD * 4) + goff);
                    bh[tp * 2][0] = r[0]; bh[tp * 2][1] = r[1];
                    bh[tp * 2 + 1][0] = r[2]; bh[tp * 2 + 1][1] = r[3];
                    ldsm4(r, Klb + grow * (AK_LD * 4) + goff);
                    bl[tp * 2][0] = r[0]; bl[tp * 2][1] = r[1];
                    bl[tp * 2 + 1][0] = r[2]; bl[tp * 2 + 1][1] = r[3];
                }
                #pragma unroll
                for (int t = 0; t < 4; t++) mma16(sacc[g * 4 + t], qh[kk], bl[t]);
                #pragma unroll
                for (int t = 0; t < 4; t++) mma16(sacc[g * 4 + t], ql[kk], bh[t]);
                #pragma unroll
                for (int t = 0; t < 4; t++) mma16(sacc[g * 4 + t], qh[kk], bh[t]);
            }
        }

        float mx0 = -1e30f, mx1 = -1e30f;
        #pragma unroll
        for (int t = 0; t < 8; t++) {
            mx0 = fmaxf(mx0, fmaxf(sacc[t][0], sacc[t][1]));
            mx1 = fmaxf(mx1, fmaxf(sacc[t][2], sacc[t][3]));
        }
        mx0 = fmaxf(mx0, __shfl_xor_sync(0xffffffffu, mx0, 1));
        mx0 = fmaxf(mx0, __shfl_xor_sync(0xffffffffu, mx0, 2));
        mx1 = fmaxf(mx1, __shfl_xor_sync(0xffffffffu, mx1, 1));
        mx1 = fmaxf(mx1, __shfl_xor_sync(0xffffffffu, mx1, 2));

        float mn0 = fmaxf(m0, mx0), mn1 = fmaxf(m1, mx1);
        float al0 = __expf(m0 - mn0), al1 = __expf(m1 - mn1);
        float s0 = 0.f, s1 = 0.f;
        #pragma unroll
        for (int t = 0; t < 8; t++) {
            sacc[t][0] = __expf(sacc[t][0] - mn0);
            sacc[t][1] = __expf(sacc[t][1] - mn0);
            sacc[t][2] = __expf(sacc[t][2] - mn1);
            sacc[t][3] = __expf(sacc[t][3] - mn1);
            s0 += sacc[t][0] + sacc[t][1];
            s1 += sacc[t][2] + sacc[t][3];
        }
        s0 += __shfl_xor_sync(0xffffffffu, s0, 1);
        s0 += __shfl_xor_sync(0xffffffffu, s0, 2);
        s1 += __shfl_xor_sync(0xffffffffu, s1, 1);
        s1 += __shfl_xor_sync(0xffffffffu, s1, 2);
        l0 = l0 * al0 + s0;
        l1 = l1 * al1 + s1;
        m0 = mn0; m1 = mn1;
        #pragma unroll
        for (int nt = 0; nt < 8; nt++) {
            oacc[nt][0] *= al0; oacc[nt][1] *= al0;
            oacc[nt][2] *= al1; oacc[nt][3] *= al1;
        }

        // O += P @ V : LDSM V-frags (transposed layout), groups of 4
        #pragma unroll
        for (int kk = 0; kk < 4; kk++) {
            uint32_t pah[4], pal[4];
            psplit2(sacc[2 * kk][0],     sacc[2 * kk][1],     pah[0], pal[0]);
            psplit2(sacc[2 * kk][2],     sacc[2 * kk][3],     pah[1], pal[1]);
            psplit2(sacc[2 * kk + 1][0], sacc[2 * kk + 1][1], pah[2], pal[2]);
            psplit2(sacc[2 * kk + 1][2], sacc[2 * kk + 1][3], pah[3], pal[3]);
            const uint32_t goff = (kk * 8 + ((mi & 1) << 2)) * 4;
            #pragma unroll
            for (int g = 0; g < 2; g++) {
                uint32_t bh[4][2], bl[4][2];
                #pragma unroll
                for (int tp = 0; tp < 2; tp++) {
                    uint32_t drow = (g * 4 + tp * 2) * 8 + ((mi >> 1) << 3) + ri;
                    uint32_t r[4];
                    ldsm4(r, Vthb + drow * (VT_LD * 4) + goff);
                    bh[tp * 2][0] = r[0]; bh[tp * 2][1] = r[1];
                    bh[tp * 2 + 1][0] = r[2]; bh[tp * 2 + 1][1] = r[3];
                    ldsm4(r, Vtlb + drow * (VT_LD * 4) + goff);
                    bl[tp * 2][0] = r[0]; bl[tp * 2][1] = r[1];
                    bl[tp * 2 + 1][0] = r[2]; bl[tp * 2 + 1][1] = r[3];
                }
                #pragma unroll
                for (int t = 0; t < 4; t++) mma16(oacc[g * 4 + t], pah, bl[t]);
                #pragma unroll
                for (int t = 0; t < 4; t++) mma16(oacc[g * 4 + t], pal, bh[t]);
                #pragma unroll
                for (int t = 0; t < 4; t++) mma16(oacc[g * 4 + t], pah, bh[t]);
            }
        }
    }

    float inv0 = 1.f / l0, inv1 = 1.f / l1;
    int h = pair >> 3, b = pair & 7;
    #pragma unroll
    for (int nt = 0; nt < 8; nt++) {
        int q = qt * 128 + warp * 16 + r0;
        int dp = h * 32 + nt * 4 + (lane & 3);
        uint32_t h0, l0u, h1, l1u;
        psplit2(oacc[nt][0] * inv0, oacc[nt][1] * inv0, h0, l0u);
        psplit2(oacc[nt][2] * inv1, oacc[nt][3] * inv1, h1, l1u);
        size_t o = ((size_t)(b * QDIM + q)) * (DIM / 2) + dp;
        g_Hdh[o] = h0; g_Hdl[o] = l0u;
        g_Hdh[o + 8 * (DIM / 2)] = h1; g_Hdl[o + 8 * (DIM / 2)] = l1u;
    }
}

extern "C" void kernel_launch(void* const* d_in, const int* in_sizes, int n_in,
                              void* d_out, int out_size)
{
    (void)in_sizes; (void)n_in; (void)out_size;
    const float* q  = (const float*)d_in[0];
    const float* Wq = (const float*)d_in[1];
    const float* Wk = (const float*)d_in[2];
    const float* Wv = (const float*)d_in[3];
    const float* Wo = (const float*)d_in[4];
    float* out = (float*)d_out;

    static bool attrs_set = false;
    if (!attrs_set) {
        cudaFuncSetAttribute(qkv_kernel,   cudaFuncAttributeMaxDynamicSharedMemorySize, QKV_SMEM);
        cudaFuncSetAttribute(attn_kernel,  cudaFuncAttributeMaxDynamicSharedMemorySize, ATTN_SMEM);
        cudaFuncSetAttribute(oproj_kernel, cudaFuncAttributeMaxDynamicSharedMemorySize, OP_SMEM);
        attrs_set = true;
    }

    splitx_kernel<<<16384, 256>>>(q);
    splitw_qkv_kernel<<<1536, 256>>>(Wq, Wk, Wv);
    splitw_o_kernel<<<512, 256>>>(Wo);
    qkv_kernel<<<dim3(8, 256), 256, QKV_SMEM>>>();
    attn_kernel<<<dim3(4, 64), 256, ATTN_SMEM>>>();
    oproj_kernel<<<dim3(8, 32), 256, OP_SMEM>>>(out);
}

// round 16
// speedup vs baseline: 1.2688x; 1.0291x over previous
#include <cuda_runtime.h>
#include <cuda_fp16.h>
#include <cstdint>

#define BATCH 8
#define TT    4096
#define DIM   512
#define NH    8
#define HD    64
#define QDIM  512
#define GG    3584
#define NCHUNK 56

// ---- global scratch (u32 = half2 of adjacent elements of ONE plane) ----
__device__ __align__(256) uint32_t g_Q  [(size_t)NH*BATCH*QDIM*HD];
__device__ __align__(256) uint32_t g_Kh [(size_t)NH*BATCH*GG*(HD/2)];
__device__ __align__(256) uint32_t g_Kl [(size_t)NH*BATCH*GG*(HD/2)];
__device__ __align__(256) uint32_t g_V2th[(size_t)NH*BATCH*HD*(GG/2)];  // [pair][d][gpair]
__device__ __align__(256) uint32_t g_V2tl[(size_t)NH*BATCH*HD*(GG/2)];
__device__ __align__(256) uint32_t g_Hdh[(size_t)BATCH*QDIM*(DIM/2)];
__device__ __align__(256) uint32_t g_Hdl[(size_t)BATCH*QDIM*(DIM/2)];
__device__ __align__(256) uint32_t g_Xh [(size_t)BATCH*TT*(DIM/2)];
__device__ __align__(256) uint32_t g_Xl [(size_t)BATCH*TT*(DIM/2)];
__device__ __align__(256) uint32_t g_Wth[(size_t)3*NH*HD*(DIM/2)];
__device__ __align__(256) uint32_t g_Wtl[(size_t)3*NH*HD*(DIM/2)];
__device__ __align__(256) uint32_t g_Woth[(size_t)DIM*(DIM/2)];
__device__ __align__(256) uint32_t g_Wotl[(size_t)DIM*(DIM/2)];

__device__ __forceinline__ uint32_t packsplit(float v) {
    __half h = __float2half_rn(v);
    __half l = __float2half_rn(v - __half2float(h));
    return (uint32_t)__half_as_ushort(h) | ((uint32_t)__half_as_ushort(l) << 16);
}
__device__ __forceinline__ void psplit2(float p0, float p1, uint32_t& hi, uint32_t& lo) {
    __half2 h = __floats2half2_rn(p0, p1);
    float2 hf = __half22float2(h);
    __half2 l = __floats2half2_rn(p0 - hf.x, p1 - hf.y);
    hi = *reinterpret_cast<uint32_t*>(&h);
    lo = *reinterpret_cast<uint32_t*>(&l);
}
__device__ __forceinline__ uint32_t h2scale8(uint32_t a) {   // *=0.125 exact
    __half2 s = __float2half2_rn(0.125f);
    __half2 r = __hmul2(*reinterpret_cast<__half2*>(&a), s);
    return *reinterpret_cast<uint32_t*>(&r);
}
#define HI_PAIR(v0, v1) __byte_perm((v0), (v1), 0x5410)
#define LO_PAIR(v0, v1) __byte_perm((v0), (v1), 0x7632)

__device__ __forceinline__ void mma16(float* c, const uint32_t* a, const uint32_t* b) {
    asm volatile(
        "mma.sync.aligned.m16n8k16.row.col.f32.f16.f16.f32 "
        "{%0,%1,%2,%3},{%4,%5,%6,%7},{%8,%9},{%0,%1,%2,%3};"
        : "+f"(c[0]), "+f"(c[1]), "+f"(c[2]), "+f"(c[3])
        : "r"(a[0]), "r"(a[1]), "r"(a[2]), "r"(a[3]), "r"(b[0]), "r"(b[1]));
}
__device__ __forceinline__ void cpa16(uint32_t dst, const void* src) {
    asm volatile("cp.async.cg.shared.global [%0], [%1], 16;" :: "r"(dst), "l"(src));
}
__device__ __forceinline__ void ldsm4(uint32_t* r, uint32_t saddr) {
    asm volatile("ldmatrix.sync.aligned.m8n8.x4.shared.b16 {%0,%1,%2,%3}, [%4];"
        : "=r"(r[0]), "=r"(r[1]), "=r"(r[2]), "=r"(r[3]) : "r"(saddr));
}

// ===========================================================================
// Prep kernels
// ===========================================================================
__global__ __launch_bounds__(256) void splitx_kernel(const float* __restrict__ X) {
    int i = blockIdx.x * 256 + threadIdx.x;
    float4 v = reinterpret_cast<const float4*>(X)[i];
    uint32_t h0, l0, h1, l1;
    psplit2(v.x, v.y, h0, l0);
    psplit2(v.z, v.w, h1, l1);
    g_Xh[2 * i] = h0; g_Xh[2 * i + 1] = h1;
    g_Xl[2 * i] = l0; g_Xl[2 * i + 1] = l1;
}
__global__ __launch_bounds__(256) void splitw_qkv_kernel(const float* __restrict__ Wq,
                                                         const float* __restrict__ Wk,
                                                         const float* __restrict__ Wv) {
    int idx = blockIdx.x * 256 + threadIdx.x;
    int kp = idx & 255, n = (idx >> 8) & 63, h = (idx >> 14) & 7, w = idx >> 17;
    const float* W = (w == 0) ? Wq : (w == 1) ? Wk : Wv;
    const float* b = W + ((size_t)h * DIM + 2 * kp) * HD + n;
    uint32_t hi, lo;
    psplit2(b[0], b[HD], hi, lo);
    g_Wth[idx] = hi; g_Wtl[idx] = lo;
}
__global__ __launch_bounds__(256) void splitw_o_kernel(const float* __restrict__ Wo) {
    int idx = blockIdx.x * 256 + threadIdx.x;
    int kp = idx & 255, n = idx >> 8;
    const float* b = Wo + (size_t)(2 * kp) * DIM + n;
    uint32_t hi, lo;
    psplit2(b[0], b[DIM], hi, lo);
    g_Woth[idx] = hi; g_Wotl[idx] = lo;
}

// ===========================================================================
// Projection: ONE weight per block (K/V/Q modes). 256 thr, 8 warps (4Mx2N),
// warp 32x32, K-chunk 32, 2-stage, 16 iters, 1 bar/iter, LDSM frags.
// launch_bounds(256,3): regs<=85, smem 61KB -> 3 blocks/SM (24 warps).
// grid (8 heads, 480): bm<224 K, <448 V, else Q.
// ===========================================================================
#define GLD 20
#define PJ_A_U32 (128 * GLD)                       // 2560 per plane
#define PJ_B_U32 (64 * GLD)                        // 1280 per plane
#define PJ_STAGE_U32 (2 * PJ_A_U32 + 2 * PJ_B_U32) // 7680
#define PJ_SMEM (2 * PJ_STAGE_U32 * 4)             // 61440

__global__ __launch_bounds__(256, 3)
void qkv_kernel()
{
    extern __shared__ uint32_t dsm[];
    const uint32_t sb = (uint32_t)__cvta_generic_to_shared(dsm);

    const int tid  = threadIdx.x;
    const int lane = tid & 31;
    const int warp = tid >> 5;
    const int wm   = warp >> 1;
    const int wn   = warp & 1;
    const int bn   = blockIdx.x;     // head
    const int bm   = blockIdx.y;     // 0..479
    const int r0 = lane >> 2;
    const int j2 = 2 * (lane & 3);
    const int mi = lane >> 3, ri = lane & 7;

    // mode: 0=K, 1=V, 2=Q
    int mode, bidx, t0, rowoff, wsel;
    if (bm < 224)      { mode = 0; int m2 = bm;       bidx = m2 / 28; t0 = (m2 % 28) * 128; rowoff = QDIM; wsel = 1; }
    else if (bm < 448) { mode = 1; int m2 = bm - 224; bidx = m2 / 28; t0 = (m2 % 28) * 128; rowoff = QDIM; wsel = 2; }
    else               { mode = 2; int m2 = bm - 448; bidx = m2 >> 2; t0 = (m2 & 3) * 128;  rowoff = 0;    wsel = 0; }

    const uint32_t* Xhp = g_Xh + ((size_t)bidx * TT + rowoff + t0) * (DIM / 2);
    const uint32_t* Xlp = g_Xl + ((size_t)bidx * TT + rowoff + t0) * (DIM / 2);
    const size_t wb = ((size_t)(wsel * NH + bn)) * HD * (DIM / 2);
    const uint32_t* Whp = g_Wth + wb;
    const uint32_t* Wlp = g_Wtl + wb;

    auto prefetch = [&](int st, int c) {
        uint32_t base = sb + st * (PJ_STAGE_U32 * 4);
        #pragma unroll
        for (int j = 0; j < 4; j++) {      // A: 2 planes x 128 rows x 4 segs = 1024
            int idx = tid + j * 256;
            int p = idx >> 9, rem = idx & 511;
            int row = rem >> 2, seg = rem & 3;
            cpa16(base + p * (PJ_A_U32 * 4) + row * (GLD * 4) + seg * 16,
                  (p ? Xlp : Xhp) + (size_t)row * (DIM / 2) + c * 16 + seg * 4);
        }
        #pragma unroll
        for (int j = 0; j < 2; j++) {      // B: 2 planes x 64 rows x 4 segs = 512
            int idx = tid + j * 256;
            int p = idx >> 8, rem = idx & 255;
            int row = rem >> 2, seg = rem & 3;
            cpa16(base + (2 * PJ_A_U32 + p * PJ_B_U32) * 4 + row * (GLD * 4) + seg * 16,
                  (p ? Wlp : Whp) + (size_t)row * (DIM / 2) + c * 16 + seg * 4);
        }
    };

    float acc[2][4][4];
    #pragma unroll
    for (int a = 0; a < 2; a++)
        #pragma unroll
        for (int b = 0; b < 4; b++)
            #pragma unroll
            for (int c = 0; c < 4; c++) acc[a][b][c] = 0.f;

    prefetch(0, 0);
    asm volatile("cp.async.commit_group;");

    for (int it = 0; it < 16; it++) {
        const int cur = it & 1;
        asm volatile("cp.async.wait_group 0;");
        __syncthreads();
        if (it + 1 < 16) prefetch(cur ^ 1, it + 1);
        asm volatile("cp.async.commit_group;");

        const uint32_t stg = sb + cur * (PJ_STAGE_U32 * 4);
        const uint32_t Ahb = stg;
        const uint32_t Alb = stg + PJ_A_U32 * 4;
        const uint32_t Bhb = stg + 2 * PJ_A_U32 * 4;
        const uint32_t Blb = Bhb + PJ_B_U32 * 4;

        #pragma unroll
        for (int kk = 0; kk < 2; kk++) {
            uint32_t ah[2][4], al[2][4];
            const uint32_t aoff = (kk * 8 + ((mi >> 1) << 2)) * 4;
            #pragma unroll
            for (int mt = 0; mt < 2; mt++) {
                uint32_t arow = wm * 32 + mt * 16 + ((mi & 1) << 3) + ri;
                ldsm4(ah[mt], Ahb + arow * (GLD * 4) + aoff);
                ldsm4(al[mt], Alb + arow * (GLD * 4) + aoff);
            }
            uint32_t bh[4][2], bl[4][2];
            const uint32_t boffc = (kk * 8 + ((mi & 1) << 2)) * 4;
            #pragma unroll
            for (int pp = 0; pp < 2; pp++) {
                uint32_t brow = wn * 32 + pp * 16 + ((mi >> 1) << 3) + ri;
                uint32_t r[4];
                ldsm4(r, Bhb + brow * (GLD * 4) + boffc);
                bh[pp * 2][0] = r[0]; bh[pp * 2][1] = r[1];
                bh[pp * 2 + 1][0] = r[2]; bh[pp * 2 + 1][1] = r[3];
                ldsm4(r, Blb + brow * (GLD * 4) + boffc);
                bl[pp * 2][0] = r[0]; bl[pp * 2][1] = r[1];
                bl[pp * 2 + 1][0] = r[2]; bl[pp * 2 + 1][1] = r[3];
            }
            #pragma unroll
            for (int nt = 0; nt < 4; nt++)
                #pragma unroll
                for (int mt = 0; mt < 2; mt++)
                    mma16(acc[mt][nt], ah[mt], bl[nt]);
            #pragma unroll
            for (int nt = 0; nt < 4; nt++)
                #pragma unroll
                for (int mt = 0; mt < 2; mt++)
                    mma16(acc[mt][nt], al[mt], bh[nt]);
            #pragma unroll
            for (int nt = 0; nt < 4; nt++)
                #pragma unroll
                for (int mt = 0; mt < 2; mt++)
                    mma16(acc[mt][nt], ah[mt], bh[nt]);
        }
    }

    // Epilogues
    const size_t pb = (size_t)(bn * BATCH + bidx);
    if (mode == 2) {
        #pragma unroll
        for (int mt = 0; mt < 2; mt++)
            #pragma unroll
            for (int nt = 0; nt < 4; nt++)
                #pragma unroll
                for (int i = 0; i < 4; i++) {
                    int mloc = wm * 32 + mt * 16 + r0 + ((i & 2) ? 8 : 0);
                    int nloc = wn * 32 + nt * 8 + j2 + (i & 1);
                    g_Q[(pb * QDIM + t0 + mloc) * HD + nloc] = packsplit(acc[mt][nt][i]);
                }
    } else if (mode == 0) {
        #pragma unroll
        for (int mt = 0; mt < 2; mt++)
            #pragma unroll
            for (int nt = 0; nt < 4; nt++) {
                int grow = t0 + wm * 32 + mt * 16 + r0;
                int dp = wn * 16 + nt * 4 + (lane & 3);
                uint32_t h0, l0, h1, l1;
                psplit2(acc[mt][nt][0], acc[mt][nt][1], h0, l0);
                psplit2(acc[mt][nt][2], acc[mt][nt][3], h1, l1);
                size_t kb = (pb * GG + grow) * (HD / 2) + dp;
                g_Kh[kb] = h0; g_Kl[kb] = l0;
                g_Kh[kb + 8 * (HD / 2)] = h1; g_Kl[kb + 8 * (HD / 2)] = l1;
            }
    } else {
        #pragma unroll
        for (int mt = 0; mt < 2; mt++)
            #pragma unroll
            for (int nt = 0; nt < 4; nt++) {
                int grow = t0 + wm * 32 + mt * 16 + r0;
                uint32_t p0 = packsplit(acc[mt][nt][0]);
                uint32_t p1 = packsplit(acc[mt][nt][1]);
                uint32_t p2 = packsplit(acc[mt][nt][2]);
                uint32_t p3 = packsplit(acc[mt][nt][3]);
                uint32_t q0 = __shfl_down_sync(0xffffffffu, p0, 4);
                uint32_t q1 = __shfl_down_sync(0xffffffffu, p1, 4);
                uint32_t q2 = __shfl_down_sync(0xffffffffu, p2, 4);
                uint32_t q3 = __shfl_down_sync(0xffffffffu, p3, 4);
                if ((r0 & 1) == 0) {
                    int d0 = wn * 32 + nt * 8 + j2;
                    size_t vb = ((size_t)pb * HD + d0) * (GG / 2) + (grow >> 1);
                    g_V2th[vb] = HI_PAIR(p0, q0);
                    g_V2tl[vb] = LO_PAIR(p0, q0);
                    g_V2th[vb + (GG / 2)] = HI_PAIR(p1, q1);
                    g_V2tl[vb + (GG / 2)] = LO_PAIR(p1, q1);
                    g_V2th[vb + 4] = HI_PAIR(p2, q2);
                    g_V2tl[vb + 4] = LO_PAIR(p2, q2);
                    g_V2th[vb + (GG / 2) + 4] = HI_PAIR(p3, q3);
                    g_V2tl[vb + (GG / 2) + 4] = LO_PAIR(p3, q3);
                }
            }
    }
}

// ===========================================================================
// Out projection: same structure, launch_bounds(256,3).
// ===========================================================================
__global__ __launch_bounds__(256, 3)
void oproj_kernel(float* __restrict__ Outp)
{
    extern __shared__ uint32_t dsm[];
    const uint32_t sb = (uint32_t)__cvta_generic_to_shared(dsm);

    const int tid  = threadIdx.x;
    const int lane = tid & 31;
    const int warp = tid >> 5;
    const int wm   = warp >> 1;
    const int wn   = warp & 1;
    const int bm   = blockIdx.y;
    const int bn   = blockIdx.x;
    const int r0 = lane >> 2;
    const int j2 = 2 * (lane & 3);
    const int mi = lane >> 3, ri = lane & 7;

    const size_t arow_g = (size_t)bm * 128;
    const size_t brow_g = (size_t)bn * 64;

    auto prefetch = [&](int st, int c) {
        uint32_t base = sb + st * (PJ_STAGE_U32 * 4);
        #pragma unroll
        for (int j = 0; j < 4; j++) {
            int idx = tid + j * 256;
            int p = idx >> 9, rem = idx & 511;
            int row = rem >> 2, seg = rem & 3;
            cpa16(base + p * (PJ_A_U32 * 4) + row * (GLD * 4) + seg * 16,
                  (p ? g_Hdl : g_Hdh) + (arow_g + row) * (DIM / 2) + c * 16 + seg * 4);
        }
        #pragma unroll
        for (int j = 0; j < 2; j++) {
            int idx = tid + j * 256;
            int p = idx >> 8, rem = idx & 255;
            int row = rem >> 2, seg = rem & 3;
            cpa16(base + (2 * PJ_A_U32 + p * PJ_B_U32) * 4 + row * (GLD * 4) + seg * 16,
                  (p ? g_Wotl : g_Woth) + (brow_g + row) * (DIM / 2) + c * 16 + seg * 4);
        }
    };

    float acc[2][4][4];
    #pragma unroll
    for (int a = 0; a < 2; a++)
        #pragma unroll
        for (int b = 0; b < 4; b++)
            #pragma unroll
            for (int c = 0; c < 4; c++) acc[a][b][c] = 0.f;

    prefetch(0, 0);
    asm volatile("cp.async.commit_group;");

    for (int it = 0; it < 16; it++) {
        const int cur = it & 1;
        asm volatile("cp.async.wait_group 0;");
        __syncthreads();
        if (it + 1 < 16) prefetch(cur ^ 1, it + 1);
        asm volatile("cp.async.commit_group;");

        const uint32_t stg = sb + cur * (PJ_STAGE_U32 * 4);
        const uint32_t Ahb = stg;
        const uint32_t Alb = stg + PJ_A_U32 * 4;
        const uint32_t Bhb = stg + 2 * PJ_A_U32 * 4;
        const uint32_t Blb = Bhb + PJ_B_U32 * 4;

        #pragma unroll
        for (int kk = 0; kk < 2; kk++) {
            uint32_t ah[2][4], al[2][4];
            const uint32_t aoff = (kk * 8 + ((mi >> 1) << 2)) * 4;
            #pragma unroll
            for (int mt = 0; mt < 2; mt++) {
                uint32_t arow = wm * 32 + mt * 16 + ((mi & 1) << 3) + ri;
                ldsm4(ah[mt], Ahb + arow * (GLD * 4) + aoff);
                ldsm4(al[mt], Alb + arow * (GLD * 4) + aoff);
            }
            uint32_t bh[4][2], bl[4][2];
            const uint32_t boffc = (kk * 8 + ((mi & 1) << 2)) * 4;
            #pragma unroll
            for (int pp = 0; pp < 2; pp++) {
                uint32_t brow = wn * 32 + pp * 16 + ((mi >> 1) << 3) + ri;
                uint32_t r[4];
                ldsm4(r, Bhb + brow * (GLD * 4) + boffc);
                bh[pp * 2][0] = r[0]; bh[pp * 2][1] = r[1];
                bh[pp * 2 + 1][0] = r[2]; bh[pp * 2 + 1][1] = r[3];
                ldsm4(r, Blb + brow * (GLD * 4) + boffc);
                bl[pp * 2][0] = r[0]; bl[pp * 2][1] = r[1];
                bl[pp * 2 + 1][0] = r[2]; bl[pp * 2 + 1][1] = r[3];
            }
            #pragma unroll
            for (int nt = 0; nt < 4; nt++)
                #pragma unroll
                for (int mt = 0; mt < 2; mt++)
                    mma16(acc[mt][nt], ah[mt], bl[nt]);
            #pragma unroll
            for (int nt = 0; nt < 4; nt++)
                #pragma unroll
                for (int mt = 0; mt < 2; mt++)
                    mma16(acc[mt][nt], al[mt], bh[nt]);
            #pragma unroll
            for (int nt = 0; nt < 4; nt++)
                #pragma unroll
                for (int mt = 0; mt < 2; mt++)
                    mma16(acc[mt][nt], ah[mt], bh[nt]);
        }
    }

    #pragma unroll
    for (int mt = 0; mt < 2; mt++)
        #pragma unroll
        for (int nt = 0; nt < 4; nt++)
            #pragma unroll
            for (int i = 0; i < 4; i++) {
                int mloc = wm * 32 + mt * 16 + r0 + ((i & 2) ? 8 : 0);
                int nloc = wn * 32 + nt * 8 + j2 + (i & 1);
                Outp[(size_t)(bm * 128 + mloc) * DIM + bn * 64 + nloc] = acc[mt][nt][i];
            }
}

// ===========================================================================
// Flash attention: UNCHANGED from round 15.
// ===========================================================================
#define AK_LD 36
#define VT_LD 36
#define AK_U32 (64 * AK_LD)
#define VT_U32 (64 * VT_LD)
#define ATTN_STAGE_U32 (2 * AK_U32 + 2 * VT_U32)
#define ATTN_SMEM (3 * ATTN_STAGE_U32 * 4)

__global__ __launch_bounds__(256, 2)
void attn_kernel()
{
    extern __shared__ uint32_t dsm[];
    const uint32_t sb = (uint32_t)__cvta_generic_to_shared(dsm);

    const int tid  = threadIdx.x;
    const int lane = tid & 31;
    const int warp = tid >> 5;
    const int qt   = blockIdx.x;
    const int pair = blockIdx.y;
    const int r0 = lane >> 2;
    const int j2 = 2 * (lane & 3);
    const int mi = lane >> 3, ri = lane & 7;

    const uint32_t* Qp  = g_Q + ((size_t)pair * QDIM + qt * 128 + warp * 16) * HD;
    const size_t kbase = (size_t)pair * GG * (HD / 2);
    const size_t vtbase = (size_t)pair * HD * (GG / 2);

    auto prefetch = [&](int st, int c) {
        uint32_t base = sb + st * (ATTN_STAGE_U32 * 4);
        #pragma unroll
        for (int j = 0; j < 2; j++) {
            int idx = tid + j * 256;
            int row = idx >> 3, seg = idx & 7;
            cpa16(base + row * (AK_LD * 4) + seg * 16,
                  g_Kh + kbase + (size_t)(c * 64 + row) * (HD / 2) + seg * 4);
            cpa16(base + AK_U32 * 4 + row * (AK_LD * 4) + seg * 16,
                  g_Kl + kbase + (size_t)(c * 64 + row) * (HD / 2) + seg * 4);
        }
        #pragma unroll
        for (int j = 0; j < 2; j++) {
            int idx = tid + j * 256;
            int row = idx >> 3, seg = idx & 7;
            cpa16(base + 2 * AK_U32 * 4 + row * (VT_LD * 4) + seg * 16,
                  g_V2th + vtbase + (size_t)row * (GG / 2) + c * 32 + seg * 4);
            cpa16(base + (2 * AK_U32 + VT_U32) * 4 + row * (VT_LD * 4) + seg * 16,
                  g_V2tl + vtbase + (size_t)row * (GG / 2) + c * 32 + seg * 4);
        }
    };

    uint32_t qh[4][4], ql[4][4];
    #pragma unroll
    for (int kk = 0; kk < 4; kk++) {
        int d0 = kk * 16 + j2;
        uint2 w01 = *reinterpret_cast<const uint2*>(Qp + (size_t)r0 * HD + d0);
        uint2 w23 = *reinterpret_cast<const uint2*>(Qp + (size_t)(r0 + 8) * HD + d0);
        uint2 w45 = *reinterpret_cast<const uint2*>(Qp + (size_t)r0 * HD + d0 + 8);
        uint2 w67 = *reinterpret_cast<const uint2*>(Qp + (size_t)(r0 + 8) * HD + d0 + 8);
        qh[kk][0] = h2scale8(HI_PAIR(w01.x, w01.y)); ql[kk][0] = h2scale8(LO_PAIR(w01.x, w01.y));
        qh[kk][1] = h2scale8(HI_PAIR(w23.x, w23.y)); ql[kk][1] = h2scale8(LO_PAIR(w23.x, w23.y));
        qh[kk][2] = h2scale8(HI_PAIR(w45.x, w45.y)); ql[kk][2] = h2scale8(LO_PAIR(w45.x, w45.y));
        qh[kk][3] = h2scale8(HI_PAIR(w67.x, w67.y)); ql[kk][3] = h2scale8(LO_PAIR(w67.x, w67.y));
    }

    float oacc[8][4];
    #pragma unroll
    for (int t = 0; t < 8; t++)
        #pragma unroll
        for (int i = 0; i < 4; i++) oacc[t][i] = 0.f;
    float m0 = -1e30f, m1 = -1e30f, l0 = 0.f, l1 = 0.f;

    prefetch(0, 0);
    asm volatile("cp.async.commit_group;");
    prefetch(1, 1);
    asm volatile("cp.async.commit_group;");

    for (int c = 0; c < NCHUNK; c++) {
        asm volatile("cp.async.wait_group 1;");
        __syncthreads();
        if (c + 2 < NCHUNK) prefetch((c + 2) % 3, c + 2);
        asm volatile("cp.async.commit_group;");

        const uint32_t stg = sb + (c % 3) * (ATTN_STAGE_U32 * 4);
        const uint32_t Khb = stg;
        const uint32_t Klb = stg + AK_U32 * 4;
        const uint32_t Vthb = stg + 2 * AK_U32 * 4;
        const uint32_t Vtlb = Vthb + VT_U32 * 4;

        float sacc[8][4];
        #pragma unroll
        for (int t = 0; t < 8; t++)
            #pragma unroll
            for (int i = 0; i < 4; i++) sacc[t][i] = 0.f;

        #pragma unroll
        for (int kk = 0; kk < 4; kk++) {
            const uint32_t goff = (kk * 8 + ((mi & 1) << 2)) * 4;
            #pragma unroll
            for (int g = 0; g < 2; g++) {
                uint32_t bh[4][2], bl[4][2];
                #pragma unroll
                for (int tp = 0; tp < 2; tp++) {
                    uint32_t grow = (g * 4 + tp * 2) * 8 + ((mi >> 1) << 3) + ri;
                    uint32_t r[4];
                    ldsm4(r, Khb + grow * (AK_LD * 4) + goff);
                    bh[tp * 2][0] = r[0]; bh[tp * 2][1] = r[1];
                    bh[tp * 2 + 1][0] = r[2]; bh[tp * 2 + 1][1] = r[3];
                    ldsm4(r, Klb + grow * (AK_LD * 4) + goff);
                    bl[tp * 2][0] = r[0]; bl[tp * 2][1] = r[1];
                    bl[tp * 2 + 1][0] = r[2]; bl[tp * 2 + 1][1] = r[3];
                }
                #pragma unroll
                for (int t = 0; t < 4; t++) mma16(sacc[g * 4 + t], qh[kk], bl[t]);
                #pragma unroll
                for (int t = 0; t < 4; t++) mma16(sacc[g * 4 + t], ql[kk], bh[t]);
                #pragma unroll
                for (int t = 0; t < 4; t++) mma16(sacc[g * 4 + t], qh[kk], bh[t]);
            }
        }

        float mx0 = -1e30f, mx1 = -1e30f;
        #pragma unroll
        for (int t = 0; t < 8; t++) {
            mx0 = fmaxf(mx0, fmaxf(sacc[t][0], sacc[t][1]));
            mx1 = fmaxf(mx1, fmaxf(sacc[t][2], sacc[t][3]));
        }
        mx0 = fmaxf(mx0, __shfl_xor_sync(0xffffffffu, mx0, 1));
        mx0 = fmaxf(mx0, __shfl_xor_sync(0xffffffffu, mx0, 2));
        mx1 = fmaxf(mx1, __shfl_xor_sync(0xffffffffu, mx1, 1));
        mx1 = fmaxf(mx1, __shfl_xor_sync(0xffffffffu, mx1, 2));

        float mn0 = fmaxf(m0, mx0), mn1 = fmaxf(m1, mx1);
        float al0 = __expf(m0 - mn0), al1 = __expf(m1 - mn1);
        float s0 = 0.f, s1 = 0.f;
        #pragma unroll
        for (int t = 0; t < 8; t++) {
            sacc[t][0] = __expf(sacc[t][0] - mn0);
            sacc[t][1] = __expf(sacc[t][1] - mn0);
            sacc[t][2] = __expf(sacc[t][2] - mn1);
            sacc[t][3] = __expf(sacc[t][3] - mn1);
            s0 += sacc[t][0] + sacc[t][1];
            s1 += sacc[t][2] + sacc[t][3];
        }
        s0 += __shfl_xor_sync(0xffffffffu, s0, 1);
        s0 += __shfl_xor_sync(0xffffffffu, s0, 2);
        s1 += __shfl_xor_sync(0xffffffffu, s1, 1);
        s1 += __shfl_xor_sync(0xffffffffu, s1, 2);
        l0 = l0 * al0 + s0;
        l1 = l1 * al1 + s1;
        m0 = mn0; m1 = mn1;
        #pragma unroll
        for (int nt = 0; nt < 8; nt++) {
            oacc[nt][0] *= al0; oacc[nt][1] *= al0;
            oacc[nt][2] *= al1; oacc[nt][3] *= al1;
        }

        #pragma unroll
        for (int kk = 0; kk < 4; kk++) {
            uint32_t pah[4], pal[4];
            psplit2(sacc[2 * kk][0],     sacc[2 * kk][1],     pah[0], pal[0]);
            psplit2(sacc[2 * kk][2],     sacc[2 * kk][3],     pah[1], pal[1]);
            psplit2(sacc[2 * kk + 1][0], sacc[2 * kk + 1][1], pah[2], pal[2]);
            psplit2(sacc[2 * kk + 1][2], sacc[2 * kk + 1][3], pah[3], pal[3]);
            const uint32_t goff = (kk * 8 + ((mi & 1) << 2)) * 4;
            #pragma unroll
            for (int g = 0; g < 2; g++) {
                uint32_t bh[4][2], bl[4][2];
                #pragma unroll
                for (int tp = 0; tp < 2; tp++) {
                    uint32_t drow = (g * 4 + tp * 2) * 8 + ((mi >> 1) << 3) + ri;
                    uint32_t r[4];
                    ldsm4(r, Vthb + drow * (VT_LD * 4) + goff);
                    bh[tp * 2][0] = r[0]; bh[tp * 2][1] = r[1];
                    bh[tp * 2 + 1][0] = r[2]; bh[tp * 2 + 1][1] = r[3];
                    ldsm4(r, Vtlb + drow * (VT_LD * 4) + goff);
                    bl[tp * 2][0] = r[0]; bl[tp * 2][1] = r[1];
                    bl[tp * 2 + 1][0] = r[2]; bl[tp * 2 + 1][1] = r[3];
                }
                #pragma unroll
                for (int t = 0; t < 4; t++) mma16(oacc[g * 4 + t], pah, bl[t]);
                #pragma unroll
                for (int t = 0; t < 4; t++) mma16(oacc[g * 4 + t], pal, bh[t]);
                #pragma unroll
                for (int t = 0; t < 4; t++) mma16(oacc[g * 4 + t], pah, bh[t]);
            }
        }
    }

    float inv0 = 1.f / l0, inv1 = 1.f / l1;
    int h = pair >> 3, b = pair & 7;
    #pragma unroll
    for (int nt = 0; nt < 8; nt++) {
        int q = qt * 128 + warp * 16 + r0;
        int dp = h * 32 + nt * 4 + (lane & 3);
        uint32_t h0, l0u, h1, l1u;
        psplit2(oacc[nt][0] * inv0, oacc[nt][1] * inv0, h0, l0u);
        psplit2(oacc[nt][2] * inv1, oacc[nt][3] * inv1, h1, l1u);
        size_t o = ((size_t)(b * QDIM + q)) * (DIM / 2) + dp;
        g_Hdh[o] = h0; g_Hdl[o] = l0u;
        g_Hdh[o + 8 * (DIM / 2)] = h1; g_Hdl[o + 8 * (DIM / 2)] = l1u;
    }
}

extern "C" void kernel_launch(void* const* d_in, const int* in_sizes, int n_in,
                              void* d_out, int out_size)
{
    (void)in_sizes; (void)n_in; (void)out_size;
    const float* q  = (const float*)d_in[0];
    const float* Wq = (const float*)d_in[1];
    const float* Wk = (const float*)d_in[2];
    const float* Wv = (const float*)d_in[3];
    const float* Wo = (const float*)d_in[4];
    float* out = (float*)d_out;

    static bool attrs_set = false;
    if (!attrs_set) {
        cudaFuncSetAttribute(qkv_kernel,   cudaFuncAttributeMaxDynamicSharedMemorySize, PJ_SMEM);
        cudaFuncSetAttribute(attn_kernel,  cudaFuncAttributeMaxDynamicSharedMemorySize, ATTN_SMEM);
        cudaFuncSetAttribute(oproj_kernel, cudaFuncAttributeMaxDynamicSharedMemorySize, PJ_SMEM);
        attrs_set = true;
    }

    splitx_kernel<<<16384, 256>>>(q);
    splitw_qkv_kernel<<<1536, 256>>>(Wq, Wk, Wv);
    splitw_o_kernel<<<512, 256>>>(Wo);
    qkv_kernel<<<dim3(8, 480), 256, PJ_SMEM>>>();
    attn_kernel<<<dim3(4, 64), 256, ATTN_SMEM>>>();
    oproj_kernel<<<dim3(8, 32), 256, PJ_SMEM>>>(out);
}

// round 17
// speedup vs baseline: 1.3582x; 1.0704x over previous
#include <cuda_runtime.h>
#include <cuda_fp16.h>
#include <cstdint>

#define BATCH 8
#define TT    4096
#define DIM   512
#define NH    8
#define HD    64
#define QDIM  512
#define GG    3584
#define NCHUNK 56

// ---- global scratch (u32 = half2 of adjacent elements of ONE plane) ----
__device__ __align__(256) uint32_t g_Q  [(size_t)NH*BATCH*QDIM*HD];
__device__ __align__(256) uint32_t g_Kh [(size_t)NH*BATCH*GG*(HD/2)];
__device__ __align__(256) uint32_t g_Kl [(size_t)NH*BATCH*GG*(HD/2)];
__device__ __align__(256) uint32_t g_V2th[(size_t)NH*BATCH*HD*(GG/2)];  // [pair][d][gpair]
__device__ __align__(256) uint32_t g_V2tl[(size_t)NH*BATCH*HD*(GG/2)];
__device__ __align__(256) uint32_t g_Hdh[(size_t)BATCH*QDIM*(DIM/2)];
__device__ __align__(256) uint32_t g_Hdl[(size_t)BATCH*QDIM*(DIM/2)];
__device__ __align__(256) uint32_t g_Xh [(size_t)BATCH*TT*(DIM/2)];
__device__ __align__(256) uint32_t g_Xl [(size_t)BATCH*TT*(DIM/2)];
__device__ __align__(256) uint32_t g_Wth[(size_t)3*NH*HD*(DIM/2)];
__device__ __align__(256) uint32_t g_Wtl[(size_t)3*NH*HD*(DIM/2)];
__device__ __align__(256) uint32_t g_Woth[(size_t)DIM*(DIM/2)];
__device__ __align__(256) uint32_t g_Wotl[(size_t)DIM*(DIM/2)];

__device__ __forceinline__ uint32_t packsplit(float v) {
    __half h = __float2half_rn(v);
    __half l = __float2half_rn(v - __half2float(h));
    return (uint32_t)__half_as_ushort(h) | ((uint32_t)__half_as_ushort(l) << 16);
}
__device__ __forceinline__ void psplit2(float p0, float p1, uint32_t& hi, uint32_t& lo) {
    __half2 h = __floats2half2_rn(p0, p1);
    float2 hf = __half22float2(h);
    __half2 l = __floats2half2_rn(p0 - hf.x, p1 - hf.y);
    hi = *reinterpret_cast<uint32_t*>(&h);
    lo = *reinterpret_cast<uint32_t*>(&l);
}
__device__ __forceinline__ uint32_t pack2h(float p0, float p1) {
    __half2 h = __floats2half2_rn(p0, p1);
    return *reinterpret_cast<uint32_t*>(&h);
}
__device__ __forceinline__ uint32_t h2scale8(uint32_t a) {   // *=0.125 exact
    __half2 s = __float2half2_rn(0.125f);
    __half2 r = __hmul2(*reinterpret_cast<__half2*>(&a), s);
    return *reinterpret_cast<uint32_t*>(&r);
}
#define HI_PAIR(v0, v1) __byte_perm((v0), (v1), 0x5410)
#define LO_PAIR(v0, v1) __byte_perm((v0), (v1), 0x7632)

__device__ __forceinline__ void mma16(float* c, const uint32_t* a, const uint32_t* b) {
    asm volatile(
        "mma.sync.aligned.m16n8k16.row.col.f32.f16.f16.f32 "
        "{%0,%1,%2,%3},{%4,%5,%6,%7},{%8,%9},{%0,%1,%2,%3};"
        : "+f"(c[0]), "+f"(c[1]), "+f"(c[2]), "+f"(c[3])
        : "r"(a[0]), "r"(a[1]), "r"(a[2]), "r"(a[3]), "r"(b[0]), "r"(b[1]));
}
__device__ __forceinline__ void cpa16(uint32_t dst, const void* src) {
    asm volatile("cp.async.cg.shared.global [%0], [%1], 16;" :: "r"(dst), "l"(src));
}
__device__ __forceinline__ void ldsm4(uint32_t* r, uint32_t saddr) {
    asm volatile("ldmatrix.sync.aligned.m8n8.x4.shared.b16 {%0,%1,%2,%3}, [%4];"
        : "=r"(r[0]), "=r"(r[1]), "=r"(r[2]), "=r"(r[3]) : "r"(saddr));
}

// ===========================================================================
// Prep kernels
// ===========================================================================
__global__ __launch_bounds__(256) void splitx_kernel(const float* __restrict__ X) {
    int i = blockIdx.x * 256 + threadIdx.x;
    float4 v = reinterpret_cast<const float4*>(X)[i];
    uint32_t h0, l0, h1, l1;
    psplit2(v.x, v.y, h0, l0);
    psplit2(v.z, v.w, h1, l1);
    g_Xh[2 * i] = h0; g_Xh[2 * i + 1] = h1;
    g_Xl[2 * i] = l0; g_Xl[2 * i + 1] = l1;
}
__global__ __launch_bounds__(256) void splitw_qkv_kernel(const float* __restrict__ Wq,
                                                         const float* __restrict__ Wk,
                                                         const float* __restrict__ Wv) {
    int idx = blockIdx.x * 256 + threadIdx.x;
    int kp = idx & 255, n = (idx >> 8) & 63, h = (idx >> 14) & 7, w = idx >> 17;
    const float* W = (w == 0) ? Wq : (w == 1) ? Wk : Wv;
    const float* b = W + ((size_t)h * DIM + 2 * kp) * HD + n;
    uint32_t hi, lo;
    psplit2(b[0], b[HD], hi, lo);
    g_Wth[idx] = hi; g_Wtl[idx] = lo;
}
__global__ __launch_bounds__(256) void splitw_o_kernel(const float* __restrict__ Wo) {
    int idx = blockIdx.x * 256 + threadIdx.x;
    int kp = idx & 255, n = idx >> 8;
    const float* b = Wo + (size_t)(2 * kp) * DIM + n;
    uint32_t hi, lo;
    psplit2(b[0], b[DIM], hi, lo);
    g_Woth[idx] = hi; g_Wotl[idx] = lo;
}

// ===========================================================================
// Projection: ONE weight per block (K/V/Q modes). 256 thr, 8 warps (4Mx2N),
// warp 32x32, K-chunk 32, 2-stage, 16 iters, 1 bar/iter, LDSM frags.
// launch_bounds(256,3): 3 blocks/SM. (UNCHANGED from round 16)
// ===========================================================================
#define GLD 20
#define PJ_A_U32 (128 * GLD)
#define PJ_B_U32 (64 * GLD)
#define PJ_STAGE_U32 (2 * PJ_A_U32 + 2 * PJ_B_U32)
#define PJ_SMEM (2 * PJ_STAGE_U32 * 4)

__global__ __launch_bounds__(256, 3)
void qkv_kernel()
{
    extern __shared__ uint32_t dsm[];
    const uint32_t sb = (uint32_t)__cvta_generic_to_shared(dsm);

    const int tid  = threadIdx.x;
    const int lane = tid & 31;
    const int warp = tid >> 5;
    const int wm   = warp >> 1;
    const int wn   = warp & 1;
    const int bn   = blockIdx.x;
    const int bm   = blockIdx.y;
    const int r0 = lane >> 2;
    const int j2 = 2 * (lane & 3);
    const int mi = lane >> 3, ri = lane & 7;

    int mode, bidx, t0, rowoff, wsel;
    if (bm < 224)      { mode = 0; int m2 = bm;       bidx = m2 / 28; t0 = (m2 % 28) * 128; rowoff = QDIM; wsel = 1; }
    else if (bm < 448) { mode = 1; int m2 = bm - 224; bidx = m2 / 28; t0 = (m2 % 28) * 128; rowoff = QDIM; wsel = 2; }
    else               { mode = 2; int m2 = bm - 448; bidx = m2 >> 2; t0 = (m2 & 3) * 128;  rowoff = 0;    wsel = 0; }

    const uint32_t* Xhp = g_Xh + ((size_t)bidx * TT + rowoff + t0) * (DIM / 2);
    const uint32_t* Xlp = g_Xl + ((size_t)bidx * TT + rowoff + t0) * (DIM / 2);
    const size_t wb = ((size_t)(wsel * NH + bn)) * HD * (DIM / 2);
    const uint32_t* Whp = g_Wth + wb;
    const uint32_t* Wlp = g_Wtl + wb;

    auto prefetch = [&](int st, int c) {
        uint32_t base = sb + st * (PJ_STAGE_U32 * 4);
        #pragma unroll
        for (int j = 0; j < 4; j++) {
            int idx = tid + j * 256;
            int p = idx >> 9, rem = idx & 511;
            int row = rem >> 2, seg = rem & 3;
            cpa16(base + p * (PJ_A_U32 * 4) + row * (GLD * 4) + seg * 16,
                  (p ? Xlp : Xhp) + (size_t)row * (DIM / 2) + c * 16 + seg * 4);
        }
        #pragma unroll
        for (int j = 0; j < 2; j++) {
            int idx = tid + j * 256;
            int p = idx >> 8, rem = idx & 255;
            int row = rem >> 2, seg = rem & 3;
            cpa16(base + (2 * PJ_A_U32 + p * PJ_B_U32) * 4 + row * (GLD * 4) + seg * 16,
                  (p ? Wlp : Whp) + (size_t)row * (DIM / 2) + c * 16 + seg * 4);
        }
    };

    float acc[2][4][4];
    #pragma unroll
    for (int a = 0; a < 2; a++)
        #pragma unroll
        for (int b = 0; b < 4; b++)
            #pragma unroll
            for (int c = 0; c < 4; c++) acc[a][b][c] = 0.f;

    prefetch(0, 0);
    asm volatile("cp.async.commit_group;");

    for (int it = 0; it < 16; it++) {
        const int cur = it & 1;
        asm volatile("cp.async.wait_group 0;");
        __syncthreads();
        if (it + 1 < 16) prefetch(cur ^ 1, it + 1);
        asm volatile("cp.async.commit_group;");

        const uint32_t stg = sb + cur * (PJ_STAGE_U32 * 4);
        const uint32_t Ahb = stg;
        const uint32_t Alb = stg + PJ_A_U32 * 4;
        const uint32_t Bhb = stg + 2 * PJ_A_U32 * 4;
        const uint32_t Blb = Bhb + PJ_B_U32 * 4;

        #pragma unroll
        for (int kk = 0; kk < 2; kk++) {
            uint32_t ah[2][4], al[2][4];
            const uint32_t aoff = (kk * 8 + ((mi >> 1) << 2)) * 4;
            #pragma unroll
            for (int mt = 0; mt < 2; mt++) {
                uint32_t arow = wm * 32 + mt * 16 + ((mi & 1) << 3) + ri;
                ldsm4(ah[mt], Ahb + arow * (GLD * 4) + aoff);
                ldsm4(al[mt], Alb + arow * (GLD * 4) + aoff);
            }
            uint32_t bh[4][2], bl[4][2];
            const uint32_t boffc = (kk * 8 + ((mi & 1) << 2)) * 4;
            #pragma unroll
            for (int pp = 0; pp < 2; pp++) {
                uint32_t brow = wn * 32 + pp * 16 + ((mi >> 1) << 3) + ri;
                uint32_t r[4];
                ldsm4(r, Bhb + brow * (GLD * 4) + boffc);
                bh[pp * 2][0] = r[0]; bh[pp * 2][1] = r[1];
                bh[pp * 2 + 1][0] = r[2]; bh[pp * 2 + 1][1] = r[3];
                ldsm4(r, Blb + brow * (GLD * 4) + boffc);
                bl[pp * 2][0] = r[0]; bl[pp * 2][1] = r[1];
                bl[pp * 2 + 1][0] = r[2]; bl[pp * 2 + 1][1] = r[3];
            }
            #pragma unroll
            for (int nt = 0; nt < 4; nt++)
                #pragma unroll
                for (int mt = 0; mt < 2; mt++)
                    mma16(acc[mt][nt], ah[mt], bl[nt]);
            #pragma unroll
            for (int nt = 0; nt < 4; nt++)
                #pragma unroll
                for (int mt = 0; mt < 2; mt++)
                    mma16(acc[mt][nt], al[mt], bh[nt]);
            #pragma unroll
            for (int nt = 0; nt < 4; nt++)
                #pragma unroll
                for (int mt = 0; mt < 2; mt++)
                    mma16(acc[mt][nt], ah[mt], bh[nt]);
        }
    }

    const size_t pb = (size_t)(bn * BATCH + bidx);
    if (mode == 2) {
        #pragma unroll
        for (int mt = 0; mt < 2; mt++)
            #pragma unroll
            for (int nt = 0; nt < 4; nt++)
                #pragma unroll
                for (int i = 0; i < 4; i++) {
                    int mloc = wm * 32 + mt * 16 + r0 + ((i & 2) ? 8 : 0);
                    int nloc = wn * 32 + nt * 8 + j2 + (i & 1);
                    g_Q[(pb * QDIM + t0 + mloc) * HD + nloc] = packsplit(acc[mt][nt][i]);
                }
    } else if (mode == 0) {
        #pragma unroll
        for (int mt = 0; mt < 2; mt++)
            #pragma unroll
            for (int nt = 0; nt < 4; nt++) {
                int grow = t0 + wm * 32 + mt * 16 + r0;
                int dp = wn * 16 + nt * 4 + (lane & 3);
                uint32_t h0, l0, h1, l1;
                psplit2(acc[mt][nt][0], acc[mt][nt][1], h0, l0);
                psplit2(acc[mt][nt][2], acc[mt][nt][3], h1, l1);
                size_t kb = (pb * GG + grow) * (HD / 2) + dp;
                g_Kh[kb] = h0; g_Kl[kb] = l0;
                g_Kh[kb + 8 * (HD / 2)] = h1; g_Kl[kb + 8 * (HD / 2)] = l1;
            }
    } else {
        #pragma unroll
        for (int mt = 0; mt < 2; mt++)
            #pragma unroll
            for (int nt = 0; nt < 4; nt++) {
                int grow = t0 + wm * 32 + mt * 16 + r0;
                uint32_t p0 = packsplit(acc[mt][nt][0]);
                uint32_t p1 = packsplit(acc[mt][nt][1]);
                uint32_t p2 = packsplit(acc[mt][nt][2]);
                uint32_t p3 = packsplit(acc[mt][nt][3]);
                uint32_t q0 = __shfl_down_sync(0xffffffffu, p0, 4);
                uint32_t q1 = __shfl_down_sync(0xffffffffu, p1, 4);
                uint32_t q2 = __shfl_down_sync(0xffffffffu, p2, 4);
                uint32_t q3 = __shfl_down_sync(0xffffffffu, p3, 4);
                if ((r0 & 1) == 0) {
                    int d0 = wn * 32 + nt * 8 + j2;
                    size_t vb = ((size_t)pb * HD + d0) * (GG / 2) + (grow >> 1);
                    g_V2th[vb] = HI_PAIR(p0, q0);
                    g_V2tl[vb] = LO_PAIR(p0, q0);
                    g_V2th[vb + (GG / 2)] = HI_PAIR(p1, q1);
                    g_V2tl[vb + (GG / 2)] = LO_PAIR(p1, q1);
                    g_V2th[vb + 4] = HI_PAIR(p2, q2);
                    g_V2tl[vb + 4] = LO_PAIR(p2, q2);
                    g_V2th[vb + (GG / 2) + 4] = HI_PAIR(p3, q3);
                    g_V2tl[vb + (GG / 2) + 4] = LO_PAIR(p3, q3);
                }
            }
    }
}

// ===========================================================================
// Out projection: (UNCHANGED from round 16)
// ===========================================================================
__global__ __launch_bounds__(256, 3)
void oproj_kernel(float* __restrict__ Outp)
{
    extern __shared__ uint32_t dsm[];
    const uint32_t sb = (uint32_t)__cvta_generic_to_shared(dsm);

    const int tid  = threadIdx.x;
    const int lane = tid & 31;
    const int warp = tid >> 5;
    const int wm   = warp >> 1;
    const int wn   = warp & 1;
    const int bm   = blockIdx.y;
    const int bn   = blockIdx.x;
    const int r0 = lane >> 2;
    const int j2 = 2 * (lane & 3);
    const int mi = lane >> 3, ri = lane & 7;

    const size_t arow_g = (size_t)bm * 128;
    const size_t brow_g = (size_t)bn * 64;

    auto prefetch = [&](int st, int c) {
        uint32_t base = sb + st * (PJ_STAGE_U32 * 4);
        #pragma unroll
        for (int j = 0; j < 4; j++) {
            int idx = tid + j * 256;
            int p = idx >> 9, rem = idx & 511;
            int row = rem >> 2, seg = rem & 3;
            cpa16(base + p * (PJ_A_U32 * 4) + row * (GLD * 4) + seg * 16,
                  (p ? g_Hdl : g_Hdh) + (arow_g + row) * (DIM / 2) + c * 16 + seg * 4);
        }
        #pragma unroll
        for (int j = 0; j < 2; j++) {
            int idx = tid + j * 256;
            int p = idx >> 8, rem = idx & 255;
            int row = rem >> 2, seg = rem & 3;
            cpa16(base + (2 * PJ_A_U32 + p * PJ_B_U32) * 4 + row * (GLD * 4) + seg * 16,
                  (p ? g_Wotl : g_Woth) + (brow_g + row) * (DIM / 2) + c * 16 + seg * 4);
        }
    };

    float acc[2][4][4];
    #pragma unroll
    for (int a = 0; a < 2; a++)
        #pragma unroll
        for (int b = 0; b < 4; b++)
            #pragma unroll
            for (int c = 0; c < 4; c++) acc[a][b][c] = 0.f;

    prefetch(0, 0);
    asm volatile("cp.async.commit_group;");

    for (int it = 0; it < 16; it++) {
        const int cur = it & 1;
        asm volatile("cp.async.wait_group 0;");
        __syncthreads();
        if (it + 1 < 16) prefetch(cur ^ 1, it + 1);
        asm volatile("cp.async.commit_group;");

        const uint32_t stg = sb + cur * (PJ_STAGE_U32 * 4);
        const uint32_t Ahb = stg;
        const uint32_t Alb = stg + PJ_A_U32 * 4;
        const uint32_t Bhb = stg + 2 * PJ_A_U32 * 4;
        const uint32_t Blb = Bhb + PJ_B_U32 * 4;

        #pragma unroll
        for (int kk = 0; kk < 2; kk++) {
            uint32_t ah[2][4], al[2][4];
            const uint32_t aoff = (kk * 8 + ((mi >> 1) << 2)) * 4;
            #pragma unroll
            for (int mt = 0; mt < 2; mt++) {
                uint32_t arow = wm * 32 + mt * 16 + ((mi & 1) << 3) + ri;
                ldsm4(ah[mt], Ahb + arow * (GLD * 4) + aoff);
                ldsm4(al[mt], Alb + arow * (GLD * 4) + aoff);
            }
            uint32_t bh[4][2], bl[4][2];
            const uint32_t boffc = (kk * 8 + ((mi & 1) << 2)) * 4;
            #pragma unroll
            for (int pp = 0; pp < 2; pp++) {
                uint32_t brow = wn * 32 + pp * 16 + ((mi >> 1) << 3) + ri;
                uint32_t r[4];
                ldsm4(r, Bhb + brow * (GLD * 4) + boffc);
                bh[pp * 2][0] = r[0]; bh[pp * 2][1] = r[1];
                bh[pp * 2 + 1][0] = r[2]; bh[pp * 2 + 1][1] = r[3];
                ldsm4(r, Blb + brow * (GLD * 4) + boffc);
                bl[pp * 2][0] = r[0]; bl[pp * 2][1] = r[1];
                bl[pp * 2 + 1][0] = r[2]; bl[pp * 2 + 1][1] = r[3];
            }
            #pragma unroll
            for (int nt = 0; nt < 4; nt++)
                #pragma unroll
                for (int mt = 0; mt < 2; mt++)
                    mma16(acc[mt][nt], ah[mt], bl[nt]);
            #pragma unroll
            for (int nt = 0; nt < 4; nt++)
                #pragma unroll
                for (int mt = 0; mt < 2; mt++)
                    mma16(acc[mt][nt], al[mt], bh[nt]);
            #pragma unroll
            for (int nt = 0; nt < 4; nt++)
                #pragma unroll
                for (int mt = 0; mt < 2; mt++)
                    mma16(acc[mt][nt], ah[mt], bh[nt]);
        }
    }

    #pragma unroll
    for (int mt = 0; mt < 2; mt++)
        #pragma unroll
        for (int nt = 0; nt < 4; nt++)
            #pragma unroll
            for (int i = 0; i < 4; i++) {
                int mloc = wm * 32 + mt * 16 + r0 + ((i & 2) ? 8 : 0);
                int nloc = wn * 32 + nt * 8 + j2 + (i & 1);
                Outp[(size_t)(bm * 128 + mloc) * DIM + bn * 64 + nloc] = acc[mt][nt][i];
            }
}

// ===========================================================================
// Flash attention: deferred sum reduction + PV lo-term dropped (P_hi only).
// ===========================================================================
#define AK_LD 36
#define VT_LD 36
#define AK_U32 (64 * AK_LD)
#define VT_U32 (64 * VT_LD)
#define ATTN_STAGE_U32 (2 * AK_U32 + 2 * VT_U32)
#define ATTN_SMEM (3 * ATTN_STAGE_U32 * 4)

__global__ __launch_bounds__(256, 2)
void attn_kernel()
{
    extern __shared__ uint32_t dsm[];
    const uint32_t sb = (uint32_t)__cvta_generic_to_shared(dsm);

    const int tid  = threadIdx.x;
    const int lane = tid & 31;
    const int warp = tid >> 5;
    const int qt   = blockIdx.x;
    const int pair = blockIdx.y;
    const int r0 = lane >> 2;
    const int j2 = 2 * (lane & 3);
    const int mi = lane >> 3, ri = lane & 7;

    const uint32_t* Qp  = g_Q + ((size_t)pair * QDIM + qt * 128 + warp * 16) * HD;
    const size_t kbase = (size_t)pair * GG * (HD / 2);
    const size_t vtbase = (size_t)pair * HD * (GG / 2);

    auto prefetch = [&](int st, int c) {
        uint32_t base = sb + st * (ATTN_STAGE_U32 * 4);
        #pragma unroll
        for (int j = 0; j < 2; j++) {
            int idx = tid + j * 256;
            int row = idx >> 3, seg = idx & 7;
            cpa16(base + row * (AK_LD * 4) + seg * 16,
                  g_Kh + kbase + (size_t)(c * 64 + row) * (HD / 2) + seg * 4);
            cpa16(base + AK_U32 * 4 + row * (AK_LD * 4) + seg * 16,
                  g_Kl + kbase + (size_t)(c * 64 + row) * (HD / 2) + seg * 4);
        }
        #pragma unroll
        for (int j = 0; j < 2; j++) {
            int idx = tid + j * 256;
            int row = idx >> 3, seg = idx & 7;
            cpa16(base + 2 * AK_U32 * 4 + row * (VT_LD * 4) + seg * 16,
                  g_V2th + vtbase + (size_t)row * (GG / 2) + c * 32 + seg * 4);
            cpa16(base + (2 * AK_U32 + VT_U32) * 4 + row * (VT_LD * 4) + seg * 16,
                  g_V2tl + vtbase + (size_t)row * (GG / 2) + c * 32 + seg * 4);
        }
    };

    uint32_t qh[4][4], ql[4][4];
    #pragma unroll
    for (int kk = 0; kk < 4; kk++) {
        int d0 = kk * 16 + j2;
        uint2 w01 = *reinterpret_cast<const uint2*>(Qp + (size_t)r0 * HD + d0);
        uint2 w23 = *reinterpret_cast<const uint2*>(Qp + (size_t)(r0 + 8) * HD + d0);
        uint2 w45 = *reinterpret_cast<const uint2*>(Qp + (size_t)r0 * HD + d0 + 8);
        uint2 w67 = *reinterpret_cast<const uint2*>(Qp + (size_t)(r0 + 8) * HD + d0 + 8);
        qh[kk][0] = h2scale8(HI_PAIR(w01.x, w01.y)); ql[kk][0] = h2scale8(LO_PAIR(w01.x, w01.y));
        qh[kk][1] = h2scale8(HI_PAIR(w23.x, w23.y)); ql[kk][1] = h2scale8(LO_PAIR(w23.x, w23.y));
        qh[kk][2] = h2scale8(HI_PAIR(w45.x, w45.y)); ql[kk][2] = h2scale8(LO_PAIR(w45.x, w45.y));
        qh[kk][3] = h2scale8(HI_PAIR(w67.x, w67.y)); ql[kk][3] = h2scale8(LO_PAIR(w67.x, w67.y));
    }

    float oacc[8][4];
    #pragma unroll
    for (int t = 0; t < 8; t++)
        #pragma unroll
        for (int i = 0; i < 4; i++) oacc[t][i] = 0.f;
    float m0 = -1e30f, m1 = -1e30f, l0 = 0.f, l1 = 0.f;

    prefetch(0, 0);
    asm volatile("cp.async.commit_group;");
    prefetch(1, 1);
    asm volatile("cp.async.commit_group;");

    for (int c = 0; c < NCHUNK; c++) {
        asm volatile("cp.async.wait_group 1;");
        __syncthreads();
        if (c + 2 < NCHUNK) prefetch((c + 2) % 3, c + 2);
        asm volatile("cp.async.commit_group;");

        const uint32_t stg = sb + (c % 3) * (ATTN_STAGE_U32 * 4);
        const uint32_t Khb = stg;
        const uint32_t Klb = stg + AK_U32 * 4;
        const uint32_t Vthb = stg + 2 * AK_U32 * 4;
        const uint32_t Vtlb = Vthb + VT_U32 * 4;

        float sacc[8][4];
        #pragma unroll
        for (int t = 0; t < 8; t++)
            #pragma unroll
            for (int i = 0; i < 4; i++) sacc[t][i] = 0.f;

        // S = Q @ K^T (full 3-term)
        #pragma unroll
        for (int kk = 0; kk < 4; kk++) {
            const uint32_t goff = (kk * 8 + ((mi & 1) << 2)) * 4;
            #pragma unroll
            for (int g = 0; g < 2; g++) {
                uint32_t bh[4][2], bl[4][2];
                #pragma unroll
                for (int tp = 0; tp < 2; tp++) {
                    uint32_t grow = (g * 4 + tp * 2) * 8 + ((mi >> 1) << 3) + ri;
                    uint32_t r[4];
                    ldsm4(r, Khb + grow * (AK_LD * 4) + goff);
                    bh[tp * 2][0] = r[0]; bh[tp * 2][1] = r[1];
                    bh[tp * 2 + 1][0] = r[2]; bh[tp * 2 + 1][1] = r[3];
                    ldsm4(r, Klb + grow * (AK_LD * 4) + goff);
                    bl[tp * 2][0] = r[0]; bl[tp * 2][1] = r[1];
                    bl[tp * 2 + 1][0] = r[2]; bl[tp * 2 + 1][1] = r[3];
                }
                #pragma unroll
                for (int t = 0; t < 4; t++) mma16(sacc[g * 4 + t], qh[kk], bl[t]);
                #pragma unroll
                for (int t = 0; t < 4; t++) mma16(sacc[g * 4 + t], ql[kk], bh[t]);
                #pragma unroll
                for (int t = 0; t < 4; t++) mma16(sacc[g * 4 + t], qh[kk], bh[t]);
            }
        }

        // Online softmax: max reduction per chunk; sum reduction DEFERRED
        float mx0 = -1e30f, mx1 = -1e30f;
        #pragma unroll
        for (int t = 0; t < 8; t++) {
            mx0 = fmaxf(mx0, fmaxf(sacc[t][0], sacc[t][1]));
            mx1 = fmaxf(mx1, fmaxf(sacc[t][2], sacc[t][3]));
        }
        mx0 = fmaxf(mx0, __shfl_xor_sync(0xffffffffu, mx0, 1));
        mx0 = fmaxf(mx0, __shfl_xor_sync(0xffffffffu, mx0, 2));
        mx1 = fmaxf(mx1, __shfl_xor_sync(0xffffffffu, mx1, 1));
        mx1 = fmaxf(mx1, __shfl_xor_sync(0xffffffffu, mx1, 2));

        float mn0 = fmaxf(m0, mx0), mn1 = fmaxf(m1, mx1);
        float al0 = __expf(m0 - mn0), al1 = __expf(m1 - mn1);
        float s0 = 0.f, s1 = 0.f;
        #pragma unroll
        for (int t = 0; t < 8; t++) {
            sacc[t][0] = __expf(sacc[t][0] - mn0);
            sacc[t][1] = __expf(sacc[t][1] - mn0);
            sacc[t][2] = __expf(sacc[t][2] - mn1);
            sacc[t][3] = __expf(sacc[t][3] - mn1);
            s0 += sacc[t][0] + sacc[t][1];
            s1 += sacc[t][2] + sacc[t][3];
        }
        l0 = l0 * al0 + s0;          // per-thread partial; reduce at end
        l1 = l1 * al1 + s1;
        m0 = mn0; m1 = mn1;
        #pragma unroll
        for (int nt = 0; nt < 8; nt++) {
            oacc[nt][0] *= al0; oacc[nt][1] *= al0;
            oacc[nt][2] *= al1; oacc[nt][3] *= al1;
        }

        // O += P_hi @ (V_hi + V_lo)  [P_lo term dropped: ~2^-12 rel error]
        #pragma unroll
        for (int kk = 0; kk < 4; kk++) {
            uint32_t pah[4];
            pah[0] = pack2h(sacc[2 * kk][0],     sacc[2 * kk][1]);
            pah[1] = pack2h(sacc[2 * kk][2],     sacc[2 * kk][3]);
            pah[2] = pack2h(sacc[2 * kk + 1][0], sacc[2 * kk + 1][1]);
            pah[3] = pack2h(sacc[2 * kk + 1][2], sacc[2 * kk + 1][3]);
            const uint32_t goff = (kk * 8 + ((mi & 1) << 2)) * 4;
            #pragma unroll
            for (int g = 0; g < 2; g++) {
                uint32_t bh[4][2], bl[4][2];
                #pragma unroll
                for (int tp = 0; tp < 2; tp++) {
                    uint32_t drow = (g * 4 + tp * 2) * 8 + ((mi >> 1) << 3) + ri;
                    uint32_t r[4];
                    ldsm4(r, Vthb + drow * (VT_LD * 4) + goff);
                    bh[tp * 2][0] = r[0]; bh[tp * 2][1] = r[1];
                    bh[tp * 2 + 1][0] = r[2]; bh[tp * 2 + 1][1] = r[3];
                    ldsm4(r, Vtlb + drow * (VT_LD * 4) + goff);
                    bl[tp * 2][0] = r[0]; bl[tp * 2][1] = r[1];
                    bl[tp * 2 + 1][0] = r[2]; bl[tp * 2 + 1][1] = r[3];
                }
                #pragma unroll
                for (int t = 0; t < 4; t++) mma16(oacc[g * 4 + t], pah, bl[t]);
                #pragma unroll
                for (int t = 0; t < 4; t++) mma16(oacc[g * 4 + t], pah, bh[t]);
            }
        }
    }

    // Final sum reductions (once)
    l0 += __shfl_xor_sync(0xffffffffu, l0, 1);
    l0 += __shfl_xor_sync(0xffffffffu, l0, 2);
    l1 += __shfl_xor_sync(0xffffffffu, l1, 1);
    l1 += __shfl_xor_sync(0xffffffffu, l1, 2);

    float inv0 = 1.f / l0, inv1 = 1.f / l1;
    int h = pair >> 3, b = pair & 7;
    #pragma unroll
    for (int nt = 0; nt < 8; nt++) {
        int q = qt * 128 + warp * 16 + r0;
        int dp = h * 32 + nt * 4 + (lane & 3);
        uint32_t h0, l0u, h1, l1u;
        psplit2(oacc[nt][0] * inv0, oacc[nt][1] * inv0, h0, l0u);
        psplit2(oacc[nt][2] * inv1, oacc[nt][3] * inv1, h1, l1u);
        size_t o = ((size_t)(b * QDIM + q)) * (DIM / 2) + dp;
        g_Hdh[o] = h0; g_Hdl[o] = l0u;
        g_Hdh[o + 8 * (DIM / 2)] = h1; g_Hdl[o + 8 * (DIM / 2)] = l1u;
    }
}

extern "C" void kernel_launch(void* const* d_in, const int* in_sizes, int n_in,
                              void* d_out, int out_size)
{
    (void)in_sizes; (void)n_in; (void)out_size;
    const float* q  = (const float*)d_in[0];
    const float* Wq = (const float*)d_in[1];
    const float* Wk = (const float*)d_in[2];
    const float* Wv = (const float*)d_in[3];
    const float* Wo = (const float*)d_in[4];
    float* out = (float*)d_out;

    static bool attrs_set = false;
    if (!attrs_set) {
        cudaFuncSetAttribute(qkv_kernel,   cudaFuncAttributeMaxDynamicSharedMemorySize, PJ_SMEM);
        cudaFuncSetAttribute(attn_kernel,  cudaFuncAttributeMaxDynamicSharedMemorySize, ATTN_SMEM);
        cudaFuncSetAttribute(oproj_kernel, cudaFuncAttributeMaxDynamicSharedMemorySize, PJ_SMEM);
        attrs_set = true;
    }

    splitx_kernel<<<16384, 256>>>(q);
    splitw_qkv_kernel<<<1536, 256>>>(Wq, Wk, Wv);
    splitw_o_kernel<<<512, 256>>>(Wo);
    qkv_kernel<<<dim3(8, 480), 256, PJ_SMEM>>>();
    attn_kernel<<<dim3(4, 64), 256, ATTN_SMEM>>>();
    oproj_kernel<<<dim3(8, 32), 256, PJ_SMEM>>>(out);
}